// round 5
// baseline (speedup 1.0000x reference)
#include <cuda_runtime.h>
#include <math.h>
#include <float.h>

#define Bn   2
#define Mn   25000
#define Nn   100000
#define Kn   16
#define NGn  8
#define CPGn 8
#define GN_EPS 1e-5f
#define MKn  (Mn * Kn)          // 400000 columns per batch

typedef unsigned long long u64;

// ---------------- constant-bank weights (upper halves used; full stored) ----------------
__constant__ __align__(16) float c_w2pe[4096];   // pe_w2 transposed [h][o]
__constant__ __align__(16) float c_w1at[4096];   // at_w1 transposed [c][o]
__constant__ __align__(16) float c_w2at[4096];   // at_w2 transposed [h][o]

// ---------------- device scratch ----------------
__device__ double g_s1[Bn][NGn][2];
__device__ double g_s2[Bn][NGn][2];
__device__ __align__(16) float g_w1pe_f[Bn][4][64];    // folded conv1_pe [c][o]
__device__ __align__(16) float g_b1pe_f[Bn][64];
__device__ __align__(16) float g_a2[Bn][64];           // at-GN scale per channel
__device__ __align__(16) float g_c2[Bn][64];           // at-GN shift per channel
__device__ __align__(16) float g_w2pe_t[4096];
__device__ __align__(16) float g_w1at_t[4096];
__device__ __align__(16) float g_w2at_t[4096];
// big activation scratch (pass2 -> pass3)
__device__ __align__(16) float g_pe_buf[(size_t)Bn * MKn * 64];
__device__ __align__(16) float g_h1_buf[(size_t)Bn * MKn * 64];

// ---------------- f32x2 helpers ----------------
__device__ __forceinline__ u64 fma2(u64 a, u64 b, u64 c) {
    u64 d;
    asm("fma.rn.f32x2 %0, %1, %2, %3;" : "=l"(d) : "l"(a), "l"(b), "l"(c));
    return d;
}
__device__ __forceinline__ u64 add2(u64 a, u64 b) {
    u64 d;
    asm("add.rn.f32x2 %0, %1, %2;" : "=l"(d) : "l"(a), "l"(b));
    return d;
}
__device__ __forceinline__ u64 pack2(float v) {
    u64 r;
    asm("mov.b64 %0, {%1, %1};" : "=l"(r) : "f"(v));
    return r;
}
__device__ __forceinline__ void unpack2(u64 v, float& lo, float& hi) {
    asm("mov.b64 {%0, %1}, %2;" : "=f"(lo), "=f"(hi) : "l"(v));
}

// Split-port GEMV: ACC (32 packed pairs) = bias + W^T x.
// Outputs 0..31  <- SW  (shared half-copy, [h][0..31], stride 32)  -> LDS port
// Outputs 32..63 <- CW  (constant full copy, [h][32..63])          -> LDC port
// ACC[0..15] pairs cover outputs 0..31; ACC[16..31] pairs cover outputs 32..63.
#define GEMV64_SPLIT(SW, CW, sbias, xarr, ACC) do {                              \
    const ulonglong2* _b2 = reinterpret_cast<const ulonglong2*>(sbias);          \
    _Pragma("unroll")                                                            \
    for (int _j = 0; _j < 16; _j++) {                                            \
        ulonglong2 _bb = _b2[_j]; (ACC)[2*_j] = _bb.x; (ACC)[2*_j+1] = _bb.y;    \
    }                                                                            \
    _Pragma("unroll")                                                            \
    for (int _h = 0; _h < 64; _h++) {                                            \
        u64 _xx = pack2((xarr)[_h]);                                             \
        _Pragma("unroll")                                                        \
        for (int _j = 0; _j < 4; _j++) {                                         \
            ulonglong2 _ws = *reinterpret_cast<const ulonglong2*>(               \
                &(SW)[(_h << 5) + 8 * _j]);                                      \
            ulonglong2 _wc = *reinterpret_cast<const ulonglong2*>(               \
                &CW[(_h << 6) + 32 + 8 * _j]);                                   \
            ulonglong2 _ws2 = *reinterpret_cast<const ulonglong2*>(              \
                &(SW)[(_h << 5) + 8 * _j + 4]);                                  \
            ulonglong2 _wc2 = *reinterpret_cast<const ulonglong2*>(              \
                &CW[(_h << 6) + 36 + 8 * _j]);                                   \
            (ACC)[4*_j]      = fma2(_ws.x,  _xx, (ACC)[4*_j]);                   \
            (ACC)[16+4*_j]   = fma2(_wc.x,  _xx, (ACC)[16+4*_j]);                \
            (ACC)[4*_j+1]    = fma2(_ws.y,  _xx, (ACC)[4*_j+1]);                 \
            (ACC)[16+4*_j+1] = fma2(_wc.y,  _xx, (ACC)[16+4*_j+1]);              \
            (ACC)[4*_j+2]    = fma2(_ws2.x, _xx, (ACC)[4*_j+2]);                 \
            (ACC)[16+4*_j+2] = fma2(_wc2.x, _xx, (ACC)[16+4*_j+2]);              \
            (ACC)[4*_j+3]    = fma2(_ws2.y, _xx, (ACC)[4*_j+3]);                 \
            (ACC)[16+4*_j+3] = fma2(_wc2.y, _xx, (ACC)[16+4*_j+3]);              \
        }                                                                        \
    }                                                                            \
} while (0)

// ---------------- helpers ----------------
__device__ __forceinline__ void compute_lp(const float* __restrict__ q,
                                           const float* __restrict__ kx,
                                           const int*   __restrict__ idx,
                                           int b, int c, float lp[4]) {
    int m  = c >> 4;
    int id = idx[b * MKn + c];
    float qx = q[(b * 3 + 0) * Mn + m];
    float qy = q[(b * 3 + 1) * Mn + m];
    float qz = q[(b * 3 + 2) * Mn + m];
    float px = kx[(b * 3 + 0) * Nn + id];
    float py = kx[(b * 3 + 1) * Nn + id];
    float pz = kx[(b * 3 + 2) * Nn + id];
    float ox = px - qx, oy = py - qy, oz = pz - qz;
    float d  = sqrtf(ox * ox + oy * oy + oz * oz);
    float r  = 1.0f / fmaxf(d, 1e-12f);
    lp[0] = ox * r; lp[1] = oy * r; lp[2] = oz * r; lp[3] = d;
}

// ---------------- kernels ----------------
__global__ void k_prep(const float* __restrict__ w2pe,
                       const float* __restrict__ w1at,
                       const float* __restrict__ w2at) {
    int i = blockIdx.x;   // 0..63 output channel
    int j = threadIdx.x;  // 0..63 input channel
    g_w2pe_t[j * 64 + i] = w2pe[i * 64 + j];
    g_w1at_t[j * 64 + i] = w1at[i * 64 + j];
    g_w2at_t[j * 64 + i] = w2at[i * 64 + j];
    if (i == 0 && j < Bn * NGn * 2) {
        ((double*)g_s1)[j] = 0.0;
        ((double*)g_s2)[j] = 0.0;
    }
}

__global__ __launch_bounds__(256) void k_pass1(const float* __restrict__ q,
                                               const float* __restrict__ kx,
                                               const int*   __restrict__ idx,
                                               const float* __restrict__ w1,
                                               const float* __restrict__ b1) {
    __shared__ float sw[4][64];
    __shared__ float sb[64];
    __shared__ float sred[16];
    int t = threadIdx.x, b = blockIdx.y;
    {
        int o = t >> 2, cc = t & 3;
        sw[cc][o] = w1[o * 4 + cc];
    }
    if (t < 64) sb[t] = b1[t];
    if (t < 16) sred[t] = 0.f;
    __syncthreads();

    int c = blockIdx.x * 256 + t;
    bool valid = c < MKn;
    int csafe = valid ? c : 0;
    float lp[4];
    compute_lp(q, kx, idx, b, csafe, lp);

    float gs[8], gq[8];
#pragma unroll
    for (int g = 0; g < 8; g++) { gs[g] = 0.f; gq[g] = 0.f; }
    if (valid) {
#pragma unroll
        for (int o = 0; o < 64; o++) {
            float h = sb[o];
            h = fmaf(sw[0][o], lp[0], h);
            h = fmaf(sw[1][o], lp[1], h);
            h = fmaf(sw[2][o], lp[2], h);
            h = fmaf(sw[3][o], lp[3], h);
            gs[o >> 3] += h;
            gq[o >> 3] = fmaf(h, h, gq[o >> 3]);
        }
    }
#pragma unroll
    for (int g = 0; g < 8; g++) {
        float v1 = gs[g], v2 = gq[g];
        for (int off = 16; off; off >>= 1) {
            v1 += __shfl_down_sync(0xffffffffu, v1, off);
            v2 += __shfl_down_sync(0xffffffffu, v2, off);
        }
        if ((t & 31) == 0) { atomicAdd(&sred[g], v1); atomicAdd(&sred[8 + g], v2); }
    }
    __syncthreads();
    if (t < 16) {
        int g = t & 7, j = t >> 3;
        atomicAdd(&g_s1[b][g][j], (double)sred[j * 8 + g]);
    }
}

__global__ void k_fin1(const float* __restrict__ w1, const float* __restrict__ b1,
                       const float* __restrict__ gam, const float* __restrict__ bet) {
    int o = threadIdx.x;  // 64 threads
    double n = (double)CPGn * (double)MKn;
    for (int b = 0; b < Bn; b++) {
        int g = o >> 3;
        double s = g_s1[b][g][0], sq = g_s1[b][g][1];
        double mean = s / n;
        double var  = sq / n - mean * mean;
        float rstd  = (float)(1.0 / sqrt(var + (double)GN_EPS));
        float a  = gam[o] * rstd;
        float cc = bet[o] - (float)mean * a;
        g_b1pe_f[b][o] = fmaf(a, b1[o], cc);
        for (int c = 0; c < 4; c++) g_w1pe_f[b][c][o] = a * w1[o * 4 + c];
    }
}

__global__ __launch_bounds__(256) void k_pass2(const float* __restrict__ q,
                                               const float* __restrict__ kx,
                                               const int*   __restrict__ idx,
                                               const float* __restrict__ b2pe,
                                               const float* __restrict__ b1at) {
    __shared__ __align__(16) float s_w2pe_h[2048];   // [h][0..31]
    __shared__ __align__(16) float s_w1at_h[2048];   // [h][0..31]
    __shared__ __align__(16) float s_w1pe[256];
    __shared__ __align__(16) float s_b1pe[64];
    __shared__ __align__(16) float s_b2pe[64];
    __shared__ __align__(16) float s_b1at[64];
    __shared__ float sred[16];
    int t = threadIdx.x, b = blockIdx.y;
    for (int i = t; i < 2048; i += 256) {
        int h = i >> 5, o = i & 31;
        s_w2pe_h[i] = g_w2pe_t[h * 64 + o];
        s_w1at_h[i] = g_w1at_t[h * 64 + o];
    }
    s_w1pe[t] = ((const float*)g_w1pe_f[b])[t];
    if (t < 64) {
        s_b1pe[t] = g_b1pe_f[b][t];
        s_b2pe[t] = b2pe[t];
        s_b1at[t] = b1at[t];
    }
    if (t < 16) sred[t] = 0.f;
    __syncthreads();

    int c = blockIdx.x * 256 + t;
    bool valid = c < MKn;
    int csafe = valid ? c : 0;
    float lp[4];
    compute_lp(q, kx, idx, b, csafe, lp);

    // u = relu(folded conv1_pe(lp))  (tiny, shared only)
    float u[64];
    {
        u64 acc[32];
        const ulonglong2* b2 = reinterpret_cast<const ulonglong2*>(s_b1pe);
#pragma unroll
        for (int j = 0; j < 16; j++) { ulonglong2 bb = b2[j]; acc[2*j] = bb.x; acc[2*j+1] = bb.y; }
#pragma unroll
        for (int h = 0; h < 4; h++) {
            u64 xx = pack2(lp[h]);
            const ulonglong2* w2 = reinterpret_cast<const ulonglong2*>(s_w1pe + (h << 6));
#pragma unroll
            for (int j = 0; j < 16; j++) {
                ulonglong2 w = w2[j];
                acc[2*j]   = fma2(w.x, xx, acc[2*j]);
                acc[2*j+1] = fma2(w.y, xx, acc[2*j+1]);
            }
        }
#pragma unroll
        for (int i = 0; i < 32; i++) {
            float lo, hi; unpack2(acc[i], lo, hi);
            u[2*i] = fmaxf(lo, 0.f); u[2*i+1] = fmaxf(hi, 0.f);
        }
    }

    // pe = conv2_pe(u)   split across LDS + LDC ports
    float pe[64];
    {
        u64 acc[32];
        GEMV64_SPLIT(s_w2pe_h, c_w2pe, s_b2pe, u, acc);
        if (valid) {
            ulonglong2* dst = reinterpret_cast<ulonglong2*>(g_pe_buf + ((size_t)(b * MKn + c) << 6));
#pragma unroll
            for (int j = 0; j < 16; j++) dst[j] = make_ulonglong2(acc[2*j], acc[2*j+1]);
        }
#pragma unroll
        for (int i = 0; i < 32; i++) unpack2(acc[i], pe[2*i], pe[2*i+1]);
    }

    // h1 = conv1_at(pe)  split across ports; store + stats
    {
        u64 acc[32];
        GEMV64_SPLIT(s_w1at_h, c_w1at, s_b1at, pe, acc);
        if (valid) {
            ulonglong2* dst = reinterpret_cast<ulonglong2*>(g_h1_buf + ((size_t)(b * MKn + c) << 6));
#pragma unroll
            for (int j = 0; j < 16; j++) dst[j] = make_ulonglong2(acc[2*j], acc[2*j+1]);
        }
        u64 gs2[8], gq2[8];
#pragma unroll
        for (int g = 0; g < 8; g++) { gs2[g] = 0ull; gq2[g] = 0ull; }
        if (valid) {
            // acc pair p covers outputs (2p,2p+1) for p<16, outputs (32+2(p-16),...) for p>=16.
            // Group g = o>>3: pairs 0..3 -> g0, 4..7 -> g1, ..., 12..15 -> g3;
            // pairs 16..19 -> g4, ..., 28..31 -> g7. So g = p>>2 works for both halves.
#pragma unroll
            for (int i = 0; i < 32; i++) {
                int g = i >> 2;
                gs2[g] = add2(gs2[g], acc[i]);
                gq2[g] = fma2(acc[i], acc[i], gq2[g]);
            }
        }
#pragma unroll
        for (int g = 0; g < 8; g++) {
            float l1, h1v, l2, h2v;
            unpack2(gs2[g], l1, h1v);
            unpack2(gq2[g], l2, h2v);
            float v1 = l1 + h1v, v2 = l2 + h2v;
            for (int off = 16; off; off >>= 1) {
                v1 += __shfl_down_sync(0xffffffffu, v1, off);
                v2 += __shfl_down_sync(0xffffffffu, v2, off);
            }
            if ((t & 31) == 0) { atomicAdd(&sred[g], v1); atomicAdd(&sred[8 + g], v2); }
        }
    }
    __syncthreads();
    if (t < 16) {
        int g = t & 7, j = t >> 3;
        atomicAdd(&g_s2[b][g][j], (double)sred[j * 8 + g]);
    }
}

__global__ void k_fin2(const float* __restrict__ gam, const float* __restrict__ bet) {
    int o = threadIdx.x;  // 64 threads
    double n = (double)CPGn * (double)MKn;
    for (int b = 0; b < Bn; b++) {
        int g = o >> 3;
        double s = g_s2[b][g][0], sq = g_s2[b][g][1];
        double mean = s / n;
        double var  = sq / n - mean * mean;
        float rstd  = (float)(1.0 / sqrt(var + (double)GN_EPS));
        float a  = gam[o] * rstd;
        float cc = bet[o] - (float)mean * a;
        g_a2[b][o] = a;
        g_c2[b][o] = cc;
    }
}

__global__ __launch_bounds__(256) void k_pass3(const int* __restrict__ mask,
                                               const float* __restrict__ b2at,
                                               float* __restrict__ out) {
    __shared__ __align__(16) float s_w2at_h[2048];   // [h][0..31]
    __shared__ __align__(16) float s_a[64];
    __shared__ __align__(16) float s_c[64];
    __shared__ __align__(16) float s_b2at[64];
    int t = threadIdx.x, b = blockIdx.y;
    for (int i = t; i < 2048; i += 256) {
        int h = i >> 5, o = i & 31;
        s_w2at_h[i] = g_w2at_t[h * 64 + o];
    }
    if (t < 64) {
        s_a[t] = g_a2[b][t];
        s_c[t] = g_c2[b][t];
        s_b2at[t] = b2at[t];
    }
    __syncthreads();

    int m = blockIdx.x * 16 + (t >> 4);
    int k = t & 15;
    if (m >= Mn) return;
    size_t c = (size_t)b * MKn + (size_t)m * 16 + k;
    unsigned smask = (t & 16) ? 0xffff0000u : 0x0000ffffu;

    // v = relu(a * h1 + c)
    float v[64];
    {
        const float4* h4 = reinterpret_cast<const float4*>(g_h1_buf + (c << 6));
        const float4* a4 = reinterpret_cast<const float4*>(s_a);
        const float4* c4 = reinterpret_cast<const float4*>(s_c);
#pragma unroll
        for (int j = 0; j < 16; j++) {
            float4 h = h4[j], aa = a4[j], cc = c4[j];
            v[4*j+0] = fmaxf(fmaf(aa.x, h.x, cc.x), 0.f);
            v[4*j+1] = fmaxf(fmaf(aa.y, h.y, cc.y), 0.f);
            v[4*j+2] = fmaxf(fmaf(aa.z, h.z, cc.z), 0.f);
            v[4*j+3] = fmaxf(fmaf(aa.w, h.w, cc.w), 0.f);
        }
    }
    bool mk = mask[c] != 0;
    const float* peptr = g_pe_buf + (c << 6);

    // attn = conv2_at(v): all 64 outputs at once, split LDS/LDC ports
    u64 atacc[32];
    GEMV64_SPLIT(s_w2at_h, c_w2at, s_b2at, v, atacc);

    // pe values
    float pec[64];
    {
        const float4* p4 = reinterpret_cast<const float4*>(peptr);
#pragma unroll
        for (int j = 0; j < 16; j++) {
            float4 p = p4[j];
            pec[4*j] = p.x; pec[4*j+1] = p.y; pec[4*j+2] = p.z; pec[4*j+3] = p.w;
        }
    }

#pragma unroll
    for (int i = 0; i < 32; i++) {
        float a0, a1; unpack2(atacc[i], a0, a1);
        // pair i covers outputs: i<16 -> (2i, 2i+1); i>=16 -> (32+2(i-16), +1) = (2i, 2i+1). Same formula.
#pragma unroll
        for (int half = 0; half < 2; half++) {
            float aval = half ? a1 : a0;
            int o = 2 * i + half;
            float a = mk ? aval : -FLT_MAX;
            float mx = a;
#pragma unroll
            for (int off = 8; off; off >>= 1)
                mx = fmaxf(mx, __shfl_xor_sync(smask, mx, off));
            float e = __expf(a - mx);
            float s = e;
#pragma unroll
            for (int off = 8; off; off >>= 1)
                s += __shfl_xor_sync(smask, s, off);
            float pc = pec[o] * e;
#pragma unroll
            for (int off = 8; off; off >>= 1)
                pc += __shfl_xor_sync(smask, pc, off);
            if (k == 0) out[((size_t)b * 64 + o) * Mn + m] = pc * __fdividef(1.f, s);
        }
    }
}

// ---------------- launch ----------------
extern "C" void kernel_launch(void* const* d_in, const int* in_sizes, int n_in,
                              void* d_out, int out_size) {
    const float* q_xyzs  = (const float*)d_in[0];
    const float* k_xyzs  = (const float*)d_in[1];
    const int*   knn_idx = (const int*)d_in[2];
    const int*   mask    = (const int*)d_in[3];
    const float* pe_w1   = (const float*)d_in[4];
    const float* pe_b1   = (const float*)d_in[5];
    const float* pe_g    = (const float*)d_in[6];
    const float* pe_be   = (const float*)d_in[7];
    const float* pe_w2   = (const float*)d_in[8];
    const float* pe_b2   = (const float*)d_in[9];
    const float* at_w1   = (const float*)d_in[10];
    const float* at_b1   = (const float*)d_in[11];
    const float* at_g    = (const float*)d_in[12];
    const float* at_be   = (const float*)d_in[13];
    const float* at_w2   = (const float*)d_in[14];
    const float* at_b2   = (const float*)d_in[15];
    float* out = (float*)d_out;

    k_prep<<<64, 64>>>(pe_w2, at_w1, at_w2);

    // Stage transposed weights into the constant bank (D2D memcpy nodes, capturable)
    void *p_w2pe = nullptr, *p_w1at = nullptr, *p_w2at = nullptr;
    cudaGetSymbolAddress(&p_w2pe, g_w2pe_t);
    cudaGetSymbolAddress(&p_w1at, g_w1at_t);
    cudaGetSymbolAddress(&p_w2at, g_w2at_t);
    cudaMemcpyToSymbolAsync(c_w2pe, p_w2pe, 4096 * sizeof(float), 0,
                            cudaMemcpyDeviceToDevice, 0);
    cudaMemcpyToSymbolAsync(c_w1at, p_w1at, 4096 * sizeof(float), 0,
                            cudaMemcpyDeviceToDevice, 0);
    cudaMemcpyToSymbolAsync(c_w2at, p_w2at, 4096 * sizeof(float), 0,
                            cudaMemcpyDeviceToDevice, 0);

    dim3 gcol((MKn + 255) / 256, Bn);
    k_pass1<<<gcol, 256>>>(q_xyzs, k_xyzs, knn_idx, pe_w1, pe_b1);
    k_fin1<<<1, 64>>>(pe_w1, pe_b1, pe_g, pe_be);
    k_pass2<<<gcol, 256>>>(q_xyzs, k_xyzs, knn_idx, pe_b2, at_b1);
    k_fin2<<<1, 64>>>(at_g, at_be);

    dim3 g3((Mn + 15) / 16, Bn);
    k_pass3<<<g3, 256>>>(mask, at_b2, out);
}

// round 6
// speedup vs baseline: 1.3339x; 1.3339x over previous
#include <cuda_runtime.h>
#include <math.h>
#include <float.h>

#define Bn   2
#define Mn   25000
#define Nn   100000
#define NGn  8
#define CPGn 8
#define GN_EPS 1e-5f
#define MKn  (Mn * 16)          // 400000 columns per batch

typedef unsigned long long u64;

// ---------------- constant-bank weights ----------------
__constant__ __align__(16) float c_w2pe[4096];      // pe_w2 transposed [k][o]
__constant__ __align__(16) float c_w1at[4096];      // at_w1 transposed [k][o]
__constant__ __align__(16) float c_w2at[4096];      // at_w2 transposed [k][o]
__constant__ __align__(16) float c_w1raw[256];      // pe_w1 transposed [c][o]
__constant__ __align__(16) float c_w1pe_f[Bn][256]; // folded conv1_pe [b][c][o]
__constant__ __align__(16) float c_b1pe_f[Bn][64];
__constant__ __align__(16) float c_gn2[Bn][128];    // a2[64] | c2[64]

// ---------------- device scratch ----------------
__device__ double g_s1[Bn][NGn][2];
__device__ double g_s2[Bn][NGn][2];
__device__ __align__(16) float g_w1pe_f[Bn][256];
__device__ __align__(16) float g_b1pe_f[Bn][64];
__device__ __align__(16) float g_gn2d[Bn][128];
__device__ __align__(16) float g_w2pe_t[4096];
__device__ __align__(16) float g_w1at_t[4096];
__device__ __align__(16) float g_w2at_t[4096];
__device__ __align__(16) float g_w1raw_t[256];
// transposed activation scratch [b][o][MKn]
__device__ __align__(16) float g_pe_buf[(size_t)Bn * 64 * MKn];
__device__ __align__(16) float g_h1_buf[(size_t)Bn * 64 * MKn];

// ---------------- f32x2 helpers ----------------
__device__ __forceinline__ u64 fma2(u64 a, u64 b, u64 c) {
    u64 d;
    asm("fma.rn.f32x2 %0, %1, %2, %3;" : "=l"(d) : "l"(a), "l"(b), "l"(c));
    return d;
}
__device__ __forceinline__ u64 add2(u64 a, u64 b) {
    u64 d;
    asm("add.rn.f32x2 %0, %1, %2;" : "=l"(d) : "l"(a), "l"(b));
    return d;
}
__device__ __forceinline__ u64 pack2(float v) {
    u64 r;
    asm("mov.b64 %0, {%1, %1};" : "=l"(r) : "f"(v));
    return r;
}
__device__ __forceinline__ void unpack2(u64 v, float& lo, float& hi) {
    asm("mov.b64 {%0, %1}, %2;" : "=f"(lo), "=f"(hi) : "l"(v));
}

// ---------------- tiled GEMM: ACC[4 cols][8 out-pairs] = bias + CW^T x ----------------
// x from shared SA[k][128] (4 cols per thread at 4*CG), weights from constant CW [k][o].
#define TGEMM(CW, SBIAS, ACC, CG, OB, SA) do {                                    \
    _Pragma("unroll")                                                             \
    for (int _p = 0; _p < 8; _p++) {                                              \
        u64 _bv = *reinterpret_cast<const u64*>(&(SBIAS)[(OB) + 2 * _p]);         \
        (ACC)[0][_p] = _bv; (ACC)[1][_p] = _bv;                                   \
        (ACC)[2][_p] = _bv; (ACC)[3][_p] = _bv;                                   \
    }                                                                             \
    _Pragma("unroll 8")                                                           \
    for (int _k = 0; _k < 64; _k++) {                                             \
        float4 _xv = *reinterpret_cast<const float4*>(&SA[_k][4 * (CG)]);         \
        u64 _xb0 = pack2(_xv.x), _xb1 = pack2(_xv.y);                             \
        u64 _xb2 = pack2(_xv.z), _xb3 = pack2(_xv.w);                             \
        const ulonglong2* _wp =                                                   \
            reinterpret_cast<const ulonglong2*>(&CW[(_k << 6) + (OB)]);           \
        ulonglong2 _wq0 = _wp[0], _wq1 = _wp[1], _wq2 = _wp[2], _wq3 = _wp[3];    \
        u64 _w[8] = {_wq0.x, _wq0.y, _wq1.x, _wq1.y,                              \
                     _wq2.x, _wq2.y, _wq3.x, _wq3.y};                             \
        _Pragma("unroll")                                                         \
        for (int _p = 0; _p < 8; _p++) {                                          \
            (ACC)[0][_p] = fma2(_w[_p], _xb0, (ACC)[0][_p]);                      \
            (ACC)[1][_p] = fma2(_w[_p], _xb1, (ACC)[1][_p]);                      \
            (ACC)[2][_p] = fma2(_w[_p], _xb2, (ACC)[2][_p]);                      \
            (ACC)[3][_p] = fma2(_w[_p], _xb3, (ACC)[3][_p]);                      \
        }                                                                         \
    }                                                                             \
} while (0)

// Repack 4cols x 16outs tile into per-output float4s; store smem and/or global.
#define REPACK(ACC, OB, CG, SA, GPTR, DO_S, DO_G) do {                            \
    _Pragma("unroll")                                                             \
    for (int _p = 0; _p < 8; _p++) {                                              \
        float _f0[4], _f1[4];                                                     \
        _Pragma("unroll")                                                         \
        for (int _c = 0; _c < 4; _c++) unpack2((ACC)[_c][_p], _f0[_c], _f1[_c]);  \
        float4 _v0 = make_float4(_f0[0], _f0[1], _f0[2], _f0[3]);                 \
        float4 _v1 = make_float4(_f1[0], _f1[1], _f1[2], _f1[3]);                 \
        int _o0 = (OB) + 2 * _p;                                                  \
        if (DO_S) {                                                               \
            *reinterpret_cast<float4*>(&SA[_o0][4 * (CG)]) = _v0;                 \
            *reinterpret_cast<float4*>(&SA[_o0 + 1][4 * (CG)]) = _v1;             \
        }                                                                         \
        if (DO_G) {                                                               \
            *reinterpret_cast<float4*>((GPTR) + (size_t)_o0 * MKn) = _v0;         \
            *reinterpret_cast<float4*>((GPTR) + (size_t)(_o0 + 1) * MKn) = _v1;   \
        }                                                                         \
    }                                                                             \
} while (0)

// ---------------- helpers ----------------
__device__ __forceinline__ void compute_lp(const float* __restrict__ q,
                                           const float* __restrict__ kx,
                                           const int*   __restrict__ idx,
                                           int b, int c, float lp[4]) {
    int m  = c >> 4;
    int id = idx[b * MKn + c];
    float qx = q[(b * 3 + 0) * Mn + m];
    float qy = q[(b * 3 + 1) * Mn + m];
    float qz = q[(b * 3 + 2) * Mn + m];
    float px = kx[(b * 3 + 0) * Nn + id];
    float py = kx[(b * 3 + 1) * Nn + id];
    float pz = kx[(b * 3 + 2) * Nn + id];
    float ox = px - qx, oy = py - qy, oz = pz - qz;
    float d  = sqrtf(ox * ox + oy * oy + oz * oz);
    float r  = 1.0f / fmaxf(d, 1e-12f);
    lp[0] = ox * r; lp[1] = oy * r; lp[2] = oz * r; lp[3] = d;
}

// ---------------- kernels ----------------
__global__ void k_prep(const float* __restrict__ w2pe,
                       const float* __restrict__ w1at,
                       const float* __restrict__ w2at,
                       const float* __restrict__ w1pe) {
    int i = blockIdx.x;   // output channel
    int j = threadIdx.x;  // input channel
    g_w2pe_t[j * 64 + i] = w2pe[i * 64 + j];
    g_w1at_t[j * 64 + i] = w1at[i * 64 + j];
    g_w2at_t[j * 64 + i] = w2at[i * 64 + j];
    if (j < 4) g_w1raw_t[j * 64 + i] = w1pe[i * 4 + j];
    if (i == 0 && j < Bn * NGn * 2) {
        ((double*)g_s1)[j] = 0.0;
        ((double*)g_s2)[j] = 0.0;
    }
}

__global__ __launch_bounds__(128) void k_pass1(const float* __restrict__ q,
                                               const float* __restrict__ kx,
                                               const int*   __restrict__ idx,
                                               const float* __restrict__ b1) {
    __shared__ float s_red[16];
    int t = threadIdx.x, b = blockIdx.y;
    if (t < 16) s_red[t] = 0.f;
    __syncthreads();
    int col = blockIdx.x * 128 + t;
    float lp[4];
    compute_lp(q, kx, idx, b, col, lp);

    u64 a1[32];
    const u64* bp = reinterpret_cast<const u64*>(b1);
#pragma unroll
    for (int p = 0; p < 32; p++) a1[p] = bp[p];
#pragma unroll
    for (int c = 0; c < 4; c++) {
        u64 xb = pack2(lp[c]);
#pragma unroll
        for (int p = 0; p < 32; p++) {
            u64 w = *reinterpret_cast<const u64*>(&c_w1raw[c * 64 + 2 * p]);
            a1[p] = fma2(w, xb, a1[p]);
        }
    }
    // group stats (group of out o = o>>3; pair p covers outs 2p,2p+1 -> group p>>2)
    float r[16];
#pragma unroll
    for (int g = 0; g < 8; g++) {
        u64 s2 = 0ull, q2 = 0ull;
#pragma unroll
        for (int p = 4 * g; p < 4 * g + 4; p++) {
            s2 = add2(s2, a1[p]);
            q2 = fma2(a1[p], a1[p], q2);
        }
        float x0, x1;
        unpack2(s2, x0, x1); r[2 * g]     = x0 + x1;
        unpack2(q2, x0, x1); r[2 * g + 1] = x0 + x1;
    }
#pragma unroll
    for (int i = 0; i < 16; i++)
        for (int off = 16; off; off >>= 1)
            r[i] += __shfl_down_sync(0xffffffffu, r[i], off);
    if ((t & 31) == 0) {
#pragma unroll
        for (int i = 0; i < 16; i++) atomicAdd(&s_red[i], r[i]);
    }
    __syncthreads();
    if (t < 16) atomicAdd(&g_s1[b][t >> 1][t & 1], (double)s_red[t]);
}

__global__ void k_fin1(const float* __restrict__ w1, const float* __restrict__ b1,
                       const float* __restrict__ gam, const float* __restrict__ bet) {
    int o = threadIdx.x;  // 64 threads
    double n = (double)CPGn * (double)MKn;
    for (int b = 0; b < Bn; b++) {
        int g = o >> 3;
        double s = g_s1[b][g][0], sq = g_s1[b][g][1];
        double mean = s / n;
        double var  = sq / n - mean * mean;
        float rstd  = (float)(1.0 / sqrt(var + (double)GN_EPS));
        float a  = gam[o] * rstd;
        float cc = bet[o] - (float)mean * a;
        g_b1pe_f[b][o] = fmaf(a, b1[o], cc);
        for (int c = 0; c < 4; c++) g_w1pe_f[b][c * 64 + o] = a * w1[o * 4 + c];
    }
}

__global__ __launch_bounds__(128) void k_pass2(const float* __restrict__ q,
                                               const float* __restrict__ kx,
                                               const int*   __restrict__ idx,
                                               const float* __restrict__ b2pe,
                                               const float* __restrict__ b1at) {
    __shared__ __align__(16) float act[64][128];
    __shared__ __align__(16) float s_b2pe[64];
    __shared__ __align__(16) float s_b1at[64];
    __shared__ float s_red[16];
    int t = threadIdx.x, b = blockIdx.y;
    int colbase = blockIdx.x * 128;
    if (t < 64) { s_b2pe[t] = b2pe[t]; s_b1at[t] = b1at[t]; }

    // ---- phase A: u = relu(folded conv1_pe(lp)), own column ----
    int col = colbase + t;
    float lp[4];
    compute_lp(q, kx, idx, b, col, lp);
    {
        u64 a1[32];
#pragma unroll
        for (int p = 0; p < 32; p++)
            a1[p] = *reinterpret_cast<const u64*>(&c_b1pe_f[b][2 * p]);
#pragma unroll
        for (int c = 0; c < 4; c++) {
            u64 xb = pack2(lp[c]);
#pragma unroll
            for (int p = 0; p < 32; p++) {
                u64 w = *reinterpret_cast<const u64*>(&c_w1pe_f[b][c * 64 + 2 * p]);
                a1[p] = fma2(w, xb, a1[p]);
            }
        }
#pragma unroll
        for (int p = 0; p < 32; p++) {
            float lo, hi;
            unpack2(a1[p], lo, hi);
            act[2 * p][t]     = fmaxf(lo, 0.f);
            act[2 * p + 1][t] = fmaxf(hi, 0.f);
        }
    }
    __syncthreads();

    int cg = t & 31, og = t >> 5, obase = og * 16;

    // ---- GEMM1: pe = w2pe^T u + b2pe ----
    u64 acc[4][8];
    TGEMM(c_w2pe, s_b2pe, acc, cg, obase, act);
    __syncthreads();   // all reads of u done before overwriting act with pe
    {
        float* gpe = g_pe_buf + (size_t)b * 64 * MKn + colbase + 4 * cg;
        REPACK(acc, obase, cg, act, gpe, 1, 1);
    }
    __syncthreads();

    // ---- GEMM2: h1 = w1at^T pe + b1at ----
    u64 acc2[4][8];
    TGEMM(c_w1at, s_b1at, acc2, cg, obase, act);
    {
        float* gh1 = g_h1_buf + (size_t)b * 64 * MKn + colbase + 4 * cg;
        REPACK(acc2, obase, cg, act, gh1, 0, 1);
    }

    // ---- stats on h1: this thread's outs cover groups 2og, 2og+1 ----
    {
        u64 sa = 0ull, qa = 0ull, sb = 0ull, qb = 0ull;
#pragma unroll
        for (int c = 0; c < 4; c++) {
#pragma unroll
            for (int p = 0; p < 4; p++) {
                sa = add2(sa, acc2[c][p]);
                qa = fma2(acc2[c][p], acc2[c][p], qa);
            }
#pragma unroll
            for (int p = 4; p < 8; p++) {
                sb = add2(sb, acc2[c][p]);
                qb = fma2(acc2[c][p], acc2[c][p], qb);
            }
        }
        float r[4], x0, x1;
        unpack2(sa, x0, x1); r[0] = x0 + x1;
        unpack2(qa, x0, x1); r[1] = x0 + x1;
        unpack2(sb, x0, x1); r[2] = x0 + x1;
        unpack2(qb, x0, x1); r[3] = x0 + x1;
#pragma unroll
        for (int i = 0; i < 4; i++)
            for (int off = 16; off; off >>= 1)
                r[i] += __shfl_down_sync(0xffffffffu, r[i], off);
        if ((t & 31) == 0) {
            s_red[og * 4 + 0] = r[0];
            s_red[og * 4 + 1] = r[1];
            s_red[og * 4 + 2] = r[2];
            s_red[og * 4 + 3] = r[3];
        }
    }
    __syncthreads();
    if (t < 16) {
        int w = t >> 2, i = t & 3;
        atomicAdd(&g_s2[b][2 * w + (i >> 1)][i & 1], (double)s_red[t]);
    }
}

__global__ void k_fin2(const float* __restrict__ gam, const float* __restrict__ bet) {
    int o = threadIdx.x;  // 64 threads
    double n = (double)CPGn * (double)MKn;
    for (int b = 0; b < Bn; b++) {
        int g = o >> 3;
        double s = g_s2[b][g][0], sq = g_s2[b][g][1];
        double mean = s / n;
        double var  = sq / n - mean * mean;
        float rstd  = (float)(1.0 / sqrt(var + (double)GN_EPS));
        float a  = gam[o] * rstd;
        float cc = bet[o] - (float)mean * a;
        g_gn2d[b][o]      = a;
        g_gn2d[b][64 + o] = cc;
    }
}

__global__ __launch_bounds__(128) void k_pass3(const int* __restrict__ mask,
                                               const float* __restrict__ b2at,
                                               float* __restrict__ out) {
    __shared__ __align__(16) float act[64][128];
    __shared__ __align__(16) float s_b2at[64];
    int t = threadIdx.x, b = blockIdx.y;
    int colbase = blockIdx.x * 128;
    if (t < 64) s_b2at[t] = b2at[t];

    // ---- phase A: v = relu(a*h1 + c)  (coalesced transposed loads) ----
    {
        const float* gh1 = g_h1_buf + (size_t)b * 64 * MKn;
#pragma unroll
        for (int s = 0; s < 16; s++) {
            int id = t + 128 * s;        // 0..2047
            int o = id >> 5, cq = id & 31;
            float4 h = *reinterpret_cast<const float4*>(
                gh1 + (size_t)o * MKn + colbase + 4 * cq);
            float a  = c_gn2[b][o];
            float cc = c_gn2[b][64 + o];
            float4 v;
            v.x = fmaxf(fmaf(a, h.x, cc), 0.f);
            v.y = fmaxf(fmaf(a, h.y, cc), 0.f);
            v.z = fmaxf(fmaf(a, h.z, cc), 0.f);
            v.w = fmaxf(fmaf(a, h.w, cc), 0.f);
            *reinterpret_cast<float4*>(&act[o][4 * cq]) = v;
        }
    }
    __syncthreads();

    int cg = t & 31, og = t >> 5, obase = og * 16;

    // ---- GEMM: attn = w2at^T v + b2at ----
    u64 acc[4][8];
    TGEMM(c_w2at, s_b2at, acc, cg, obase, act);
    __syncthreads();
    REPACK(acc, obase, cg, act, (float*)0, 1, 0);   // attn -> act[o][col]
    __syncthreads();

    // ---- masked softmax over k (16 cols / m) + weighted pe sum ----
    int col = colbase + t;
    bool mk = mask[(size_t)b * MKn + col] != 0;
    const float* gpe = g_pe_buf + (size_t)b * 64 * MKn + col;
    unsigned smask = (t & 16) ? 0xffff0000u : 0x0000ffffu;
    int kk = t & 15;
    int m  = col >> 4;
#pragma unroll 4
    for (int o = 0; o < 64; o++) {
        float a = mk ? act[o][t] : -FLT_MAX;
        float mx = a;
#pragma unroll
        for (int off = 8; off; off >>= 1)
            mx = fmaxf(mx, __shfl_xor_sync(smask, mx, off));
        float e = __expf(a - mx);
        float s = e;
#pragma unroll
        for (int off = 8; off; off >>= 1)
            s += __shfl_xor_sync(smask, s, off);
        float pc = __ldg(gpe + (size_t)o * MKn) * e;
#pragma unroll
        for (int off = 8; off; off >>= 1)
            pc += __shfl_xor_sync(smask, pc, off);
        if (kk == 0) out[((size_t)b * 64 + o) * Mn + m] = pc * __fdividef(1.f, s);
    }
}

// ---------------- launch ----------------
extern "C" void kernel_launch(void* const* d_in, const int* in_sizes, int n_in,
                              void* d_out, int out_size) {
    const float* q_xyzs  = (const float*)d_in[0];
    const float* k_xyzs  = (const float*)d_in[1];
    const int*   knn_idx = (const int*)d_in[2];
    const int*   mask    = (const int*)d_in[3];
    const float* pe_w1   = (const float*)d_in[4];
    const float* pe_b1   = (const float*)d_in[5];
    const float* pe_g    = (const float*)d_in[6];
    const float* pe_be   = (const float*)d_in[7];
    const float* pe_w2   = (const float*)d_in[8];
    const float* pe_b2   = (const float*)d_in[9];
    const float* at_w1   = (const float*)d_in[10];
    const float* at_b1   = (const float*)d_in[11];
    const float* at_g    = (const float*)d_in[12];
    const float* at_be   = (const float*)d_in[13];
    const float* at_w2   = (const float*)d_in[14];
    const float* at_b2   = (const float*)d_in[15];
    float* out = (float*)d_out;

    k_prep<<<64, 64>>>(pe_w2, at_w1, at_w2, pe_w1);

    // static weights -> constant bank (D2D memcpy nodes, capturable)
    void *p1, *p2, *p3, *p4;
    cudaGetSymbolAddress(&p1, g_w2pe_t);
    cudaGetSymbolAddress(&p2, g_w1at_t);
    cudaGetSymbolAddress(&p3, g_w2at_t);
    cudaGetSymbolAddress(&p4, g_w1raw_t);
    cudaMemcpyToSymbolAsync(c_w2pe, p1, 4096 * 4, 0, cudaMemcpyDeviceToDevice, 0);
    cudaMemcpyToSymbolAsync(c_w1at, p2, 4096 * 4, 0, cudaMemcpyDeviceToDevice, 0);
    cudaMemcpyToSymbolAsync(c_w2at, p3, 4096 * 4, 0, cudaMemcpyDeviceToDevice, 0);
    cudaMemcpyToSymbolAsync(c_w1raw, p4, 256 * 4, 0, cudaMemcpyDeviceToDevice, 0);

    dim3 gcol(MKn / 128, Bn);
    k_pass1<<<gcol, 128>>>(q_xyzs, k_xyzs, knn_idx, pe_b1);
    k_fin1<<<1, 64>>>(pe_w1, pe_b1, pe_g, pe_be);

    // folded conv1_pe -> constant
    void *pf1, *pf2;
    cudaGetSymbolAddress(&pf1, g_w1pe_f);
    cudaGetSymbolAddress(&pf2, g_b1pe_f);
    cudaMemcpyToSymbolAsync(c_w1pe_f, pf1, Bn * 256 * 4, 0, cudaMemcpyDeviceToDevice, 0);
    cudaMemcpyToSymbolAsync(c_b1pe_f, pf2, Bn * 64 * 4, 0, cudaMemcpyDeviceToDevice, 0);

    k_pass2<<<gcol, 128>>>(q_xyzs, k_xyzs, knn_idx, pe_b2, at_b1);
    k_fin2<<<1, 64>>>(at_g, at_be);

    // at-GN fold -> constant
    void* pg;
    cudaGetSymbolAddress(&pg, g_gn2d);
    cudaMemcpyToSymbolAsync(c_gn2, pg, Bn * 128 * 4, 0, cudaMemcpyDeviceToDevice, 0);

    k_pass3<<<gcol, 128>>>(mask, at_b2, out);
}

// round 7
// speedup vs baseline: 1.6881x; 1.2655x over previous
#include <cuda_runtime.h>
#include <math.h>
#include <float.h>

#define Bn   2
#define Mn   25000
#define Nn   100000
#define NGn  8
#define CPGn 8
#define GN_EPS 1e-5f
#define MKn  (Mn * 16)          // 400000 columns per batch

typedef unsigned long long u64;

// ---------------- constant-bank (small, uniform) ----------------
__constant__ __align__(16) float c_w1raw[256];      // pe_w1 transposed [c][o]
__constant__ __align__(16) float c_gn2[Bn][128];    // a2[64] | c2[64]

// ---------------- device scratch ----------------
__device__ double g_s1[Bn][NGn][2];
__device__ double g_s2[Bn][NGn][2];
__device__ __align__(16) float g_w1pe_f[Bn][256];   // folded conv1_pe [b][c][o]
__device__ __align__(16) float g_b1pe_f[Bn][64];
__device__ __align__(16) float g_gn2d[Bn][128];
__device__ __align__(16) float g_w2pe_t[4096];      // [k][o]
__device__ __align__(16) float g_w1at_t[4096];
__device__ __align__(16) float g_w2at_t[4096];
__device__ __align__(16) float g_w1raw_t[256];
// transposed activation scratch [b][o][MKn]
__device__ __align__(16) float g_pe_buf[(size_t)Bn * 64 * MKn];
__device__ __align__(16) float g_h1_buf[(size_t)Bn * 64 * MKn];

// ---------------- f32x2 helpers ----------------
__device__ __forceinline__ u64 fma2(u64 a, u64 b, u64 c) {
    u64 d;
    asm("fma.rn.f32x2 %0, %1, %2, %3;" : "=l"(d) : "l"(a), "l"(b), "l"(c));
    return d;
}
__device__ __forceinline__ u64 add2(u64 a, u64 b) {
    u64 d;
    asm("add.rn.f32x2 %0, %1, %2;" : "=l"(d) : "l"(a), "l"(b));
    return d;
}
__device__ __forceinline__ u64 pack2(float v) {
    u64 r;
    asm("mov.b64 %0, {%1, %1};" : "=l"(r) : "f"(v));
    return r;
}
__device__ __forceinline__ void unpack2(u64 v, float& lo, float& hi) {
    asm("mov.b64 {%0, %1}, %2;" : "=f"(lo), "=f"(hi) : "l"(v));
}

// ---------------- tiled GEMM: ACC[4 cols][8 out-pairs] = bias + W^T x ----------------
// x from shared SA (stride 128), weights from shared W (stride 64), K = KK.
#define TGEMM_K(KK, W, SBIAS, ACC, CG, OB, SA) do {                               \
    _Pragma("unroll")                                                             \
    for (int _p = 0; _p < 8; _p++) {                                              \
        u64 _bv = *reinterpret_cast<const u64*>(&(SBIAS)[(OB) + 2 * _p]);         \
        (ACC)[0][_p] = _bv; (ACC)[1][_p] = _bv;                                   \
        (ACC)[2][_p] = _bv; (ACC)[3][_p] = _bv;                                   \
    }                                                                             \
    _Pragma("unroll 8")                                                           \
    for (int _k = 0; _k < (KK); _k++) {                                           \
        float4 _xv = *reinterpret_cast<const float4*>(&(SA)[_k * 128 + 4 * (CG)]);\
        u64 _xb0 = pack2(_xv.x), _xb1 = pack2(_xv.y);                             \
        u64 _xb2 = pack2(_xv.z), _xb3 = pack2(_xv.w);                             \
        const ulonglong2* _wp =                                                   \
            reinterpret_cast<const ulonglong2*>(&(W)[(_k << 6) + (OB)]);          \
        ulonglong2 _wq0 = _wp[0], _wq1 = _wp[1], _wq2 = _wp[2], _wq3 = _wp[3];    \
        u64 _w[8] = {_wq0.x, _wq0.y, _wq1.x, _wq1.y,                              \
                     _wq2.x, _wq2.y, _wq3.x, _wq3.y};                             \
        _Pragma("unroll")                                                         \
        for (int _p = 0; _p < 8; _p++) {                                          \
            (ACC)[0][_p] = fma2(_w[_p], _xb0, (ACC)[0][_p]);                      \
            (ACC)[1][_p] = fma2(_w[_p], _xb1, (ACC)[1][_p]);                      \
            (ACC)[2][_p] = fma2(_w[_p], _xb2, (ACC)[2][_p]);                      \
            (ACC)[3][_p] = fma2(_w[_p], _xb3, (ACC)[3][_p]);                      \
        }                                                                         \
    }                                                                             \
} while (0)

// Repack 4cols x 16outs into per-output float4; optional relu, smem, global.
#define REPACK(ACC, OB, CG, SA, GPTR, RELU, DO_S, DO_G) do {                      \
    _Pragma("unroll")                                                             \
    for (int _p = 0; _p < 8; _p++) {                                              \
        float _f0[4], _f1[4];                                                     \
        _Pragma("unroll")                                                         \
        for (int _c = 0; _c < 4; _c++) unpack2((ACC)[_c][_p], _f0[_c], _f1[_c]);  \
        if (RELU) {                                                               \
            _Pragma("unroll")                                                     \
            for (int _c = 0; _c < 4; _c++) {                                      \
                _f0[_c] = fmaxf(_f0[_c], 0.f); _f1[_c] = fmaxf(_f1[_c], 0.f);     \
            }                                                                     \
        }                                                                         \
        float4 _v0 = make_float4(_f0[0], _f0[1], _f0[2], _f0[3]);                 \
        float4 _v1 = make_float4(_f1[0], _f1[1], _f1[2], _f1[3]);                 \
        int _o0 = (OB) + 2 * _p;                                                  \
        if (DO_S) {                                                               \
            *reinterpret_cast<float4*>(&(SA)[_o0 * 128 + 4 * (CG)]) = _v0;        \
            *reinterpret_cast<float4*>(&(SA)[(_o0 + 1) * 128 + 4 * (CG)]) = _v1;  \
        }                                                                         \
        if (DO_G) {                                                               \
            *reinterpret_cast<float4*>((GPTR) + (size_t)_o0 * MKn) = _v0;         \
            *reinterpret_cast<float4*>((GPTR) + (size_t)(_o0 + 1) * MKn) = _v1;   \
        }                                                                         \
    }                                                                             \
} while (0)

// ---------------- shared layouts (float offsets) ----------------
#define P2_ACT   0        // [64][128]
#define P2_W     8192     // [64][64]
#define P2_W1PE  12288    // [4][64]
#define P2_LPS   12544    // [4][128]
#define P2_BPA   13056    // b1pe_f (64)
#define P2_BG1   13120    // b2pe (64)
#define P2_BG2   13184    // b1at (64)
#define P2_RED   13248    // 16
#define P2_TOT   13264
#define P3_ACT   0        // [64][128]
#define P3_W     8192     // [64][64]
#define P3_B     12288    // b2at (64)
#define P3_TOT   12352

// ---------------- helpers ----------------
__device__ __forceinline__ void compute_lp(const float* __restrict__ q,
                                           const float* __restrict__ kx,
                                           const int*   __restrict__ idx,
                                           int b, int c, float lp[4]) {
    int m  = c >> 4;
    int id = idx[b * MKn + c];
    float qx = q[(b * 3 + 0) * Mn + m];
    float qy = q[(b * 3 + 1) * Mn + m];
    float qz = q[(b * 3 + 2) * Mn + m];
    float px = kx[(b * 3 + 0) * Nn + id];
    float py = kx[(b * 3 + 1) * Nn + id];
    float pz = kx[(b * 3 + 2) * Nn + id];
    float ox = px - qx, oy = py - qy, oz = pz - qz;
    float d  = sqrtf(ox * ox + oy * oy + oz * oz);
    float r  = 1.0f / fmaxf(d, 1e-12f);
    lp[0] = ox * r; lp[1] = oy * r; lp[2] = oz * r; lp[3] = d;
}

// ---------------- kernels ----------------
__global__ void k_prep(const float* __restrict__ w2pe,
                       const float* __restrict__ w1at,
                       const float* __restrict__ w2at,
                       const float* __restrict__ w1pe) {
    int i = blockIdx.x;   // output channel
    int j = threadIdx.x;  // input channel
    g_w2pe_t[j * 64 + i] = w2pe[i * 64 + j];
    g_w1at_t[j * 64 + i] = w1at[i * 64 + j];
    g_w2at_t[j * 64 + i] = w2at[i * 64 + j];
    if (j < 4) g_w1raw_t[j * 64 + i] = w1pe[i * 4 + j];
    if (i == 0 && j < Bn * NGn * 2) {
        ((double*)g_s1)[j] = 0.0;
        ((double*)g_s2)[j] = 0.0;
    }
}

__global__ __launch_bounds__(128) void k_pass1(const float* __restrict__ q,
                                               const float* __restrict__ kx,
                                               const int*   __restrict__ idx,
                                               const float* __restrict__ b1) {
    __shared__ float s_red[16];
    int t = threadIdx.x, b = blockIdx.y;
    if (t < 16) s_red[t] = 0.f;
    __syncthreads();
    int col = blockIdx.x * 128 + t;
    float lp[4];
    compute_lp(q, kx, idx, b, col, lp);

    u64 a1[32];
    const u64* bp = reinterpret_cast<const u64*>(b1);
#pragma unroll
    for (int p = 0; p < 32; p++) a1[p] = bp[p];
#pragma unroll
    for (int c = 0; c < 4; c++) {
        u64 xb = pack2(lp[c]);
#pragma unroll
        for (int p = 0; p < 32; p++) {
            u64 w = *reinterpret_cast<const u64*>(&c_w1raw[c * 64 + 2 * p]);
            a1[p] = fma2(w, xb, a1[p]);
        }
    }
    float r[16];
#pragma unroll
    for (int g = 0; g < 8; g++) {
        u64 s2 = 0ull, q2 = 0ull;
#pragma unroll
        for (int p = 4 * g; p < 4 * g + 4; p++) {
            s2 = add2(s2, a1[p]);
            q2 = fma2(a1[p], a1[p], q2);
        }
        float x0, x1;
        unpack2(s2, x0, x1); r[2 * g]     = x0 + x1;
        unpack2(q2, x0, x1); r[2 * g + 1] = x0 + x1;
    }
#pragma unroll
    for (int i = 0; i < 16; i++)
        for (int off = 16; off; off >>= 1)
            r[i] += __shfl_down_sync(0xffffffffu, r[i], off);
    if ((t & 31) == 0) {
#pragma unroll
        for (int i = 0; i < 16; i++) atomicAdd(&s_red[i], r[i]);
    }
    __syncthreads();
    if (t < 16) atomicAdd(&g_s1[b][t >> 1][t & 1], (double)s_red[t]);
}

__global__ void k_fin1(const float* __restrict__ w1, const float* __restrict__ b1,
                       const float* __restrict__ gam, const float* __restrict__ bet) {
    int o = threadIdx.x;  // 64 threads
    double n = (double)CPGn * (double)MKn;
    for (int b = 0; b < Bn; b++) {
        int g = o >> 3;
        double s = g_s1[b][g][0], sq = g_s1[b][g][1];
        double mean = s / n;
        double var  = sq / n - mean * mean;
        float rstd  = (float)(1.0 / sqrt(var + (double)GN_EPS));
        float a  = gam[o] * rstd;
        float cc = bet[o] - (float)mean * a;
        g_b1pe_f[b][o] = fmaf(a, b1[o], cc);
        for (int c = 0; c < 4; c++) g_w1pe_f[b][c * 64 + o] = a * w1[o * 4 + c];
    }
}

__global__ __launch_bounds__(128, 4) void k_pass2(const float* __restrict__ q,
                                                  const float* __restrict__ kx,
                                                  const int*   __restrict__ idx,
                                                  const float* __restrict__ b2pe,
                                                  const float* __restrict__ b1at) {
    extern __shared__ __align__(16) float sm[];
    int t = threadIdx.x, b = blockIdx.y;
    int colbase = blockIdx.x * 128;
    int cg = t & 31, og = t >> 5, obase = og * 16;

    // ---- stage: lp, w1pe_f, w2pe, biases ----
    {
        int col = colbase + t;
        float lp[4];
        compute_lp(q, kx, idx, b, col, lp);
#pragma unroll
        for (int c = 0; c < 4; c++) sm[P2_LPS + c * 128 + t] = lp[c];
        const float4* src = reinterpret_cast<const float4*>(g_w2pe_t);
        float4* dstw = reinterpret_cast<float4*>(sm + P2_W);
#pragma unroll
        for (int i = 0; i < 8; i++) dstw[t + 128 * i] = src[t + 128 * i];
        if (t < 64) {
            *reinterpret_cast<float4*>(sm + P2_W1PE + 4 * t) =
                *reinterpret_cast<const float4*>(&g_w1pe_f[b][4 * t]);
        } else {
            int u = t - 64;
            sm[P2_BPA + u] = g_b1pe_f[b][u];
            sm[P2_BG1 + u] = b2pe[u];
            sm[P2_BG2 + u] = b1at[u];
        }
        if (t < 16) sm[P2_RED + t] = 0.f;
    }
    __syncthreads();

    // ---- phase A: u = relu(conv1_pe'(lp)) as K=4 GEMM ----
    {
        u64 acc[4][8];
        TGEMM_K(4, (sm + P2_W1PE), (sm + P2_BPA), acc, cg, obase, (sm + P2_LPS));
        REPACK(acc, obase, cg, (sm + P2_ACT), (float*)0, 1, 1, 0);
    }
    __syncthreads();

    // ---- GEMM1: pe = w2pe^T u + b2pe ----
    u64 acc1[4][8];
    TGEMM_K(64, (sm + P2_W), (sm + P2_BG1), acc1, cg, obase, (sm + P2_ACT));
    __syncthreads();   // all reads of u / w2pe done
    {
        // write pe -> act + global; stage w1at -> wbuf
        float* gpe = g_pe_buf + (size_t)b * 64 * MKn + colbase + 4 * cg;
        REPACK(acc1, obase, cg, (sm + P2_ACT), gpe, 0, 1, 1);
        const float4* src = reinterpret_cast<const float4*>(g_w1at_t);
        float4* dstw = reinterpret_cast<float4*>(sm + P2_W);
#pragma unroll
        for (int i = 0; i < 8; i++) dstw[t + 128 * i] = src[t + 128 * i];
    }
    __syncthreads();

    // ---- GEMM2: h1 = w1at^T pe + b1at ----
    u64 acc2[4][8];
    TGEMM_K(64, (sm + P2_W), (sm + P2_BG2), acc2, cg, obase, (sm + P2_ACT));
    {
        float* gh1 = g_h1_buf + (size_t)b * 64 * MKn + colbase + 4 * cg;
        REPACK(acc2, obase, cg, (sm + P2_ACT), gh1, 0, 0, 1);
    }

    // ---- stats on h1: this thread's outs cover groups 2og, 2og+1 ----
    {
        u64 sa = 0ull, qa = 0ull, sb = 0ull, qb = 0ull;
#pragma unroll
        for (int c = 0; c < 4; c++) {
#pragma unroll
            for (int p = 0; p < 4; p++) {
                sa = add2(sa, acc2[c][p]);
                qa = fma2(acc2[c][p], acc2[c][p], qa);
            }
#pragma unroll
            for (int p = 4; p < 8; p++) {
                sb = add2(sb, acc2[c][p]);
                qb = fma2(acc2[c][p], acc2[c][p], qb);
            }
        }
        float r[4], x0, x1;
        unpack2(sa, x0, x1); r[0] = x0 + x1;
        unpack2(qa, x0, x1); r[1] = x0 + x1;
        unpack2(sb, x0, x1); r[2] = x0 + x1;
        unpack2(qb, x0, x1); r[3] = x0 + x1;
#pragma unroll
        for (int i = 0; i < 4; i++)
            for (int off = 16; off; off >>= 1)
                r[i] += __shfl_down_sync(0xffffffffu, r[i], off);
        if ((t & 31) == 0) {
            sm[P2_RED + og * 4 + 0] = r[0];
            sm[P2_RED + og * 4 + 1] = r[1];
            sm[P2_RED + og * 4 + 2] = r[2];
            sm[P2_RED + og * 4 + 3] = r[3];
        }
    }
    __syncthreads();
    if (t < 16) {
        int w = t >> 2, i = t & 3;
        atomicAdd(&g_s2[b][2 * w + (i >> 1)][i & 1], (double)sm[P2_RED + t]);
    }
}

__global__ void k_fin2(const float* __restrict__ gam, const float* __restrict__ bet) {
    int o = threadIdx.x;  // 64 threads
    double n = (double)CPGn * (double)MKn;
    for (int b = 0; b < Bn; b++) {
        int g = o >> 3;
        double s = g_s2[b][g][0], sq = g_s2[b][g][1];
        double mean = s / n;
        double var  = sq / n - mean * mean;
        float rstd  = (float)(1.0 / sqrt(var + (double)GN_EPS));
        float a  = gam[o] * rstd;
        float cc = bet[o] - (float)mean * a;
        g_gn2d[b][o]      = a;
        g_gn2d[b][64 + o] = cc;
    }
}

__global__ __launch_bounds__(128, 4) void k_pass3(const int* __restrict__ mask,
                                                  const float* __restrict__ b2at,
                                                  float* __restrict__ out) {
    extern __shared__ __align__(16) float sm[];
    int t = threadIdx.x, b = blockIdx.y;
    int colbase = blockIdx.x * 128;
    int cg = t & 31, og = t >> 5, obase = og * 16;

    // ---- stage: v = relu(a*h1 + c), w2at, bias ----
    {
        const float* gh1 = g_h1_buf + (size_t)b * 64 * MKn;
#pragma unroll
        for (int s = 0; s < 16; s++) {
            int id = t + 128 * s;        // 0..2047
            int o = id >> 5, cq = id & 31;
            float4 h = *reinterpret_cast<const float4*>(
                gh1 + (size_t)o * MKn + colbase + 4 * cq);
            float a  = c_gn2[b][o];
            float cc = c_gn2[b][64 + o];
            float4 v;
            v.x = fmaxf(fmaf(a, h.x, cc), 0.f);
            v.y = fmaxf(fmaf(a, h.y, cc), 0.f);
            v.z = fmaxf(fmaf(a, h.z, cc), 0.f);
            v.w = fmaxf(fmaf(a, h.w, cc), 0.f);
            *reinterpret_cast<float4*>(&sm[P3_ACT + o * 128 + 4 * cq]) = v;
        }
        const float4* src = reinterpret_cast<const float4*>(g_w2at_t);
        float4* dstw = reinterpret_cast<float4*>(sm + P3_W);
#pragma unroll
        for (int i = 0; i < 8; i++) dstw[t + 128 * i] = src[t + 128 * i];
        if (t < 64) sm[P3_B + t] = b2at[t];
    }
    __syncthreads();

    // ---- GEMM: attn = w2at^T v + b2at ----
    u64 acc[4][8];
    TGEMM_K(64, (sm + P3_W), (sm + P3_B), acc, cg, obase, (sm + P3_ACT));
    __syncthreads();
    REPACK(acc, obase, cg, (sm + P3_ACT), (float*)0, 0, 1, 0);
    __syncthreads();

    // ---- masked softmax over k (16 cols / m) + weighted pe sum ----
    int col = colbase + t;
    bool mk = mask[(size_t)b * MKn + col] != 0;
    const float* gpe = g_pe_buf + (size_t)b * 64 * MKn + col;
    unsigned smask = (t & 16) ? 0xffff0000u : 0x0000ffffu;
    int kk = t & 15;
    int m  = col >> 4;
#pragma unroll 4
    for (int o = 0; o < 64; o++) {
        float a = mk ? sm[P3_ACT + o * 128 + t] : -FLT_MAX;
        float mx = a;
#pragma unroll
        for (int off = 8; off; off >>= 1)
            mx = fmaxf(mx, __shfl_xor_sync(smask, mx, off));
        float e = __expf(a - mx);
        float s = e;
#pragma unroll
        for (int off = 8; off; off >>= 1)
            s += __shfl_xor_sync(smask, s, off);
        float pc = __ldg(gpe + (size_t)o * MKn) * e;
#pragma unroll
        for (int off = 8; off; off >>= 1)
            pc += __shfl_xor_sync(smask, pc, off);
        if (kk == 0) out[((size_t)b * 64 + o) * Mn + m] = pc * __fdividef(1.f, s);
    }
}

// ---------------- launch ----------------
extern "C" void kernel_launch(void* const* d_in, const int* in_sizes, int n_in,
                              void* d_out, int out_size) {
    const float* q_xyzs  = (const float*)d_in[0];
    const float* k_xyzs  = (const float*)d_in[1];
    const int*   knn_idx = (const int*)d_in[2];
    const int*   mask    = (const int*)d_in[3];
    const float* pe_w1   = (const float*)d_in[4];
    const float* pe_b1   = (const float*)d_in[5];
    const float* pe_g    = (const float*)d_in[6];
    const float* pe_be   = (const float*)d_in[7];
    const float* pe_w2   = (const float*)d_in[8];
    const float* pe_b2   = (const float*)d_in[9];
    const float* at_w1   = (const float*)d_in[10];
    const float* at_b1   = (const float*)d_in[11];
    const float* at_g    = (const float*)d_in[12];
    const float* at_be   = (const float*)d_in[13];
    const float* at_w2   = (const float*)d_in[14];
    const float* at_b2   = (const float*)d_in[15];
    float* out = (float*)d_out;

    static int smem_set = 0;
    if (!smem_set) {
        cudaFuncSetAttribute(k_pass2, cudaFuncAttributeMaxDynamicSharedMemorySize,
                             P2_TOT * 4);
        cudaFuncSetAttribute(k_pass3, cudaFuncAttributeMaxDynamicSharedMemorySize,
                             P3_TOT * 4);
        smem_set = 1;
    }

    k_prep<<<64, 64>>>(pe_w2, at_w1, at_w2, pe_w1);

    // small uniform weights -> constant bank
    void *p4;
    cudaGetSymbolAddress(&p4, g_w1raw_t);
    cudaMemcpyToSymbolAsync(c_w1raw, p4, 256 * 4, 0, cudaMemcpyDeviceToDevice, 0);

    dim3 gcol(MKn / 128, Bn);
    k_pass1<<<gcol, 128>>>(q_xyzs, k_xyzs, knn_idx, pe_b1);
    k_fin1<<<1, 64>>>(pe_w1, pe_b1, pe_g, pe_be);

    k_pass2<<<gcol, 128, P2_TOT * 4>>>(q_xyzs, k_xyzs, knn_idx, pe_b2, at_b1);
    k_fin2<<<1, 64>>>(at_g, at_be);

    // at-GN fold -> constant
    void* pg;
    cudaGetSymbolAddress(&pg, g_gn2d);
    cudaMemcpyToSymbolAsync(c_gn2, pg, Bn * 128 * 4, 0, cudaMemcpyDeviceToDevice, 0);

    k_pass3<<<gcol, 128, P3_TOT * 4>>>(mask, at_b2, out);
}

// round 8
// speedup vs baseline: 2.7026x; 1.6010x over previous
#include <cuda_runtime.h>
#include <math.h>
#include <float.h>

#define Bn   2
#define Mn   25000
#define Nn   100000
#define NGn  8
#define CPGn 8
#define GN_EPS 1e-5f
#define MKn  (Mn * 16)          // 400000 columns per batch

typedef unsigned long long u64;

// ---------------- constant-bank (small, uniform) ----------------
__constant__ __align__(16) float c_gn2[Bn][128];    // a2[64] | c2[64]

// ---------------- device scratch ----------------
__device__ double g_m1[Bn][14];                     // lp moments: S[4], M2 upper[10]
__device__ double g_s2[Bn][NGn][2];
__device__ __align__(16) float g_w1pe_f[Bn][256];   // folded conv1_pe [b][c][o]
__device__ __align__(16) float g_b1pe_f[Bn][64];
__device__ __align__(16) float g_gn2d[Bn][128];
__device__ __align__(16) float g_w2pe_t[4096];      // [k][o]
__device__ __align__(16) float g_w1at_t[4096];
__device__ __align__(16) float g_w2at_t[4096];
// transposed activation scratch [b][o][MKn]
__device__ __align__(16) float g_pe_buf[(size_t)Bn * 64 * MKn];
__device__ __align__(16) float g_h1_buf[(size_t)Bn * 64 * MKn];

// ---------------- f32x2 helpers ----------------
__device__ __forceinline__ u64 fma2(u64 a, u64 b, u64 c) {
    u64 d;
    asm("fma.rn.f32x2 %0, %1, %2, %3;" : "=l"(d) : "l"(a), "l"(b), "l"(c));
    return d;
}
__device__ __forceinline__ u64 add2(u64 a, u64 b) {
    u64 d;
    asm("add.rn.f32x2 %0, %1, %2;" : "=l"(d) : "l"(a), "l"(b));
    return d;
}
__device__ __forceinline__ u64 pack2(float v) {
    u64 r;
    asm("mov.b64 %0, {%1, %1};" : "=l"(r) : "f"(v));
    return r;
}
__device__ __forceinline__ void unpack2(u64 v, float& lo, float& hi) {
    asm("mov.b64 {%0, %1}, %2;" : "=f"(lo), "=f"(hi) : "l"(v));
}

// ---------------- tiled GEMM: ACC[4 cols][8 out-pairs] = bias + W^T x ----------------
#define TGEMM_K(KK, W, SBIAS, ACC, CG, OB, SA, STR) do {                          \
    _Pragma("unroll")                                                             \
    for (int _p = 0; _p < 8; _p++) {                                              \
        u64 _bv = *reinterpret_cast<const u64*>(&(SBIAS)[(OB) + 2 * _p]);         \
        (ACC)[0][_p] = _bv; (ACC)[1][_p] = _bv;                                   \
        (ACC)[2][_p] = _bv; (ACC)[3][_p] = _bv;                                   \
    }                                                                             \
    _Pragma("unroll 8")                                                           \
    for (int _k = 0; _k < (KK); _k++) {                                           \
        float4 _xv = *reinterpret_cast<const float4*>(                            \
            &(SA)[_k * (STR) + 4 * (CG)]);                                        \
        u64 _xb0 = pack2(_xv.x), _xb1 = pack2(_xv.y);                             \
        u64 _xb2 = pack2(_xv.z), _xb3 = pack2(_xv.w);                             \
        const ulonglong2* _wp =                                                   \
            reinterpret_cast<const ulonglong2*>(&(W)[(_k << 6) + (OB)]);          \
        ulonglong2 _wq0 = _wp[0], _wq1 = _wp[1], _wq2 = _wp[2], _wq3 = _wp[3];    \
        u64 _w[8] = {_wq0.x, _wq0.y, _wq1.x, _wq1.y,                              \
                     _wq2.x, _wq2.y, _wq3.x, _wq3.y};                             \
        _Pragma("unroll")                                                         \
        for (int _p = 0; _p < 8; _p++) {                                          \
            (ACC)[0][_p] = fma2(_w[_p], _xb0, (ACC)[0][_p]);                      \
            (ACC)[1][_p] = fma2(_w[_p], _xb1, (ACC)[1][_p]);                      \
            (ACC)[2][_p] = fma2(_w[_p], _xb2, (ACC)[2][_p]);                      \
            (ACC)[3][_p] = fma2(_w[_p], _xb3, (ACC)[3][_p]);                      \
        }                                                                         \
    }                                                                             \
} while (0)

#define REPACK(ACC, OB, CG, SA, GPTR, RELU, DO_S, DO_G, STR) do {                 \
    _Pragma("unroll")                                                             \
    for (int _p = 0; _p < 8; _p++) {                                              \
        float _f0[4], _f1[4];                                                     \
        _Pragma("unroll")                                                         \
        for (int _c = 0; _c < 4; _c++) unpack2((ACC)[_c][_p], _f0[_c], _f1[_c]);  \
        if (RELU) {                                                               \
            _Pragma("unroll")                                                     \
            for (int _c = 0; _c < 4; _c++) {                                      \
                _f0[_c] = fmaxf(_f0[_c], 0.f); _f1[_c] = fmaxf(_f1[_c], 0.f);     \
            }                                                                     \
        }                                                                         \
        float4 _v0 = make_float4(_f0[0], _f0[1], _f0[2], _f0[3]);                 \
        float4 _v1 = make_float4(_f1[0], _f1[1], _f1[2], _f1[3]);                 \
        int _o0 = (OB) + 2 * _p;                                                  \
        if (DO_S) {                                                               \
            *reinterpret_cast<float4*>(&(SA)[_o0 * (STR) + 4 * (CG)]) = _v0;      \
            *reinterpret_cast<float4*>(&(SA)[(_o0 + 1) * (STR) + 4 * (CG)]) = _v1;\
        }                                                                         \
        if (DO_G) {                                                               \
            *reinterpret_cast<float4*>((GPTR) + (size_t)_o0 * MKn) = _v0;         \
            *reinterpret_cast<float4*>((GPTR) + (size_t)(_o0 + 1) * MKn) = _v1;   \
        }                                                                         \
    }                                                                             \
} while (0)

// ---------------- shared layouts (float offsets) ----------------
#define P2_ACT   0        // [64][128]
#define P2_W     8192     // [64][64]
#define P2_W1PE  12288    // [4][64]
#define P2_LPS   12544    // [4][128]
#define P2_BPA   13056
#define P2_BG1   13120
#define P2_BG2   13184
#define P2_RED   13248
#define P2_TOT   13264
#define P3_STR   136
#define P3_ACT   0        // [64][136]
#define P3_W     8704     // [64][64]
#define P3_B     12800
#define P3_TOT   12864

// ---------------- helpers ----------------
__device__ __forceinline__ void compute_lp(const float* __restrict__ q,
                                           const float* __restrict__ kx,
                                           const int*   __restrict__ idx,
                                           int b, int c, float lp[4]) {
    int m  = c >> 4;
    int id = idx[b * MKn + c];
    float qx = q[(b * 3 + 0) * Mn + m];
    float qy = q[(b * 3 + 1) * Mn + m];
    float qz = q[(b * 3 + 2) * Mn + m];
    float px = kx[(b * 3 + 0) * Nn + id];
    float py = kx[(b * 3 + 1) * Nn + id];
    float pz = kx[(b * 3 + 2) * Nn + id];
    float ox = px - qx, oy = py - qy, oz = pz - qz;
    float d  = sqrtf(ox * ox + oy * oy + oz * oz);
    float r  = 1.0f / fmaxf(d, 1e-12f);
    lp[0] = ox * r; lp[1] = oy * r; lp[2] = oz * r; lp[3] = d;
}

// ---------------- kernels ----------------
__global__ void k_prep(const float* __restrict__ w2pe,
                       const float* __restrict__ w1at,
                       const float* __restrict__ w2at) {
    int i = blockIdx.x;   // output channel
    int j = threadIdx.x;  // input channel
    g_w2pe_t[j * 64 + i] = w2pe[i * 64 + j];
    g_w1at_t[j * 64 + i] = w1at[i * 64 + j];
    g_w2at_t[j * 64 + i] = w2at[i * 64 + j];
    if (i == 0) {
        if (j < Bn * NGn * 2) ((double*)g_s2)[j] = 0.0;
        if (j < Bn * 14)      ((double*)g_m1)[j] = 0.0;
    }
}

// pass1: only lp moments (S[4], M2 upper-tri[10]) — no conv needed for GN1 stats
__global__ __launch_bounds__(128) void k_pass1(const float* __restrict__ q,
                                               const float* __restrict__ kx,
                                               const int*   __restrict__ idx) {
    __shared__ float s_red[14];
    int t = threadIdx.x, b = blockIdx.y;
    if (t < 14) s_red[t] = 0.f;
    __syncthreads();
    int col = blockIdx.x * 128 + t;
    float lp[4];
    compute_lp(q, kx, idx, b, col, lp);

    float v[14];
    v[0] = lp[0]; v[1] = lp[1]; v[2] = lp[2]; v[3] = lp[3];
    {
        int n = 4;
#pragma unroll
        for (int c = 0; c < 4; c++)
#pragma unroll
            for (int d = c; d < 4; d++) v[n++] = lp[c] * lp[d];
    }
#pragma unroll
    for (int i = 0; i < 14; i++) {
        for (int off = 16; off; off >>= 1)
            v[i] += __shfl_down_sync(0xffffffffu, v[i], off);
        if ((t & 31) == 0) atomicAdd(&s_red[i], v[i]);
    }
    __syncthreads();
    if (t < 14) atomicAdd(&g_m1[b][t], (double)s_red[t]);
}

__global__ void k_fin1(const float* __restrict__ w1, const float* __restrict__ b1,
                       const float* __restrict__ gam, const float* __restrict__ bet) {
    __shared__ double gs[8], gq[8];
    int o = threadIdx.x;  // 64 threads
    double n = (double)CPGn * (double)MKn;
    for (int b = 0; b < Bn; b++) {
        if (o < 8) { gs[o] = 0.0; gq[o] = 0.0; }
        __syncthreads();
        double m[14];
#pragma unroll
        for (int i = 0; i < 14; i++) m[i] = g_m1[b][i];
        double M2[4][4];
        {
            int idx5 = 4;
            for (int c = 0; c < 4; c++)
                for (int d = c; d < 4; d++) {
                    M2[c][d] = m[idx5]; M2[d][c] = m[idx5]; idx5++;
                }
        }
        double w[4];
#pragma unroll
        for (int c = 0; c < 4; c++) w[c] = (double)w1[o * 4 + c];
        double bo = (double)b1[o];
        double dot = w[0] * m[0] + w[1] * m[1] + w[2] * m[2] + w[3] * m[3];
        double sum_o = dot + (double)MKn * bo;
        double sq_o = 0.0;
#pragma unroll
        for (int c = 0; c < 4; c++)
#pragma unroll
            for (int d = 0; d < 4; d++) sq_o += w[c] * w[d] * M2[c][d];
        sq_o += 2.0 * bo * dot + (double)MKn * bo * bo;
        atomicAdd(&gs[o >> 3], sum_o);
        atomicAdd(&gq[o >> 3], sq_o);
        __syncthreads();
        int g = o >> 3;
        double mean = gs[g] / n;
        double var  = gq[g] / n - mean * mean;
        float rstd  = (float)(1.0 / sqrt(var + (double)GN_EPS));
        float a  = gam[o] * rstd;
        float cc = bet[o] - (float)mean * a;
        g_b1pe_f[b][o] = fmaf(a, b1[o], cc);
        for (int c = 0; c < 4; c++) g_w1pe_f[b][c * 64 + o] = a * w1[o * 4 + c];
        __syncthreads();
    }
}

__global__ __launch_bounds__(128, 4) void k_pass2(const float* __restrict__ q,
                                                  const float* __restrict__ kx,
                                                  const int*   __restrict__ idx,
                                                  const float* __restrict__ b2pe,
                                                  const float* __restrict__ b1at) {
    extern __shared__ __align__(16) float sm[];
    int t = threadIdx.x, b = blockIdx.y;
    int colbase = blockIdx.x * 128;
    int cg = t & 31, og = t >> 5, obase = og * 16;

    {
        int col = colbase + t;
        float lp[4];
        compute_lp(q, kx, idx, b, col, lp);
#pragma unroll
        for (int c = 0; c < 4; c++) sm[P2_LPS + c * 128 + t] = lp[c];
        const float4* src = reinterpret_cast<const float4*>(g_w2pe_t);
        float4* dstw = reinterpret_cast<float4*>(sm + P2_W);
#pragma unroll
        for (int i = 0; i < 8; i++) dstw[t + 128 * i] = src[t + 128 * i];
        if (t < 64) {
            *reinterpret_cast<float4*>(sm + P2_W1PE + 4 * t) =
                *reinterpret_cast<const float4*>(&g_w1pe_f[b][4 * t]);
        } else {
            int u = t - 64;
            sm[P2_BPA + u] = g_b1pe_f[b][u];
            sm[P2_BG1 + u] = b2pe[u];
            sm[P2_BG2 + u] = b1at[u];
        }
        if (t < 16) sm[P2_RED + t] = 0.f;
    }
    __syncthreads();

    {
        u64 acc[4][8];
        TGEMM_K(4, (sm + P2_W1PE), (sm + P2_BPA), acc, cg, obase, (sm + P2_LPS), 128);
        REPACK(acc, obase, cg, (sm + P2_ACT), (float*)0, 1, 1, 0, 128);
    }
    __syncthreads();

    u64 acc1[4][8];
    TGEMM_K(64, (sm + P2_W), (sm + P2_BG1), acc1, cg, obase, (sm + P2_ACT), 128);
    __syncthreads();
    {
        float* gpe = g_pe_buf + (size_t)b * 64 * MKn + colbase + 4 * cg;
        REPACK(acc1, obase, cg, (sm + P2_ACT), gpe, 0, 1, 1, 128);
        const float4* src = reinterpret_cast<const float4*>(g_w1at_t);
        float4* dstw = reinterpret_cast<float4*>(sm + P2_W);
#pragma unroll
        for (int i = 0; i < 8; i++) dstw[t + 128 * i] = src[t + 128 * i];
    }
    __syncthreads();

    u64 acc2[4][8];
    TGEMM_K(64, (sm + P2_W), (sm + P2_BG2), acc2, cg, obase, (sm + P2_ACT), 128);
    {
        float* gh1 = g_h1_buf + (size_t)b * 64 * MKn + colbase + 4 * cg;
        REPACK(acc2, obase, cg, (sm + P2_ACT), gh1, 0, 0, 1, 128);
    }

    {
        u64 sa = 0ull, qa = 0ull, sb = 0ull, qb = 0ull;
#pragma unroll
        for (int c = 0; c < 4; c++) {
#pragma unroll
            for (int p = 0; p < 4; p++) {
                sa = add2(sa, acc2[c][p]);
                qa = fma2(acc2[c][p], acc2[c][p], qa);
            }
#pragma unroll
            for (int p = 4; p < 8; p++) {
                sb = add2(sb, acc2[c][p]);
                qb = fma2(acc2[c][p], acc2[c][p], qb);
            }
        }
        float r[4], x0, x1;
        unpack2(sa, x0, x1); r[0] = x0 + x1;
        unpack2(qa, x0, x1); r[1] = x0 + x1;
        unpack2(sb, x0, x1); r[2] = x0 + x1;
        unpack2(qb, x0, x1); r[3] = x0 + x1;
#pragma unroll
        for (int i = 0; i < 4; i++)
            for (int off = 16; off; off >>= 1)
                r[i] += __shfl_down_sync(0xffffffffu, r[i], off);
        if ((t & 31) == 0) {
            sm[P2_RED + og * 4 + 0] = r[0];
            sm[P2_RED + og * 4 + 1] = r[1];
            sm[P2_RED + og * 4 + 2] = r[2];
            sm[P2_RED + og * 4 + 3] = r[3];
        }
    }
    __syncthreads();
    if (t < 16) {
        int w = t >> 2, i = t & 3;
        atomicAdd(&g_s2[b][2 * w + (i >> 1)][i & 1], (double)sm[P2_RED + t]);
    }
}

__global__ void k_fin2(const float* __restrict__ gam, const float* __restrict__ bet) {
    int o = threadIdx.x;  // 64 threads
    double n = (double)CPGn * (double)MKn;
    for (int b = 0; b < Bn; b++) {
        int g = o >> 3;
        double s = g_s2[b][g][0], sq = g_s2[b][g][1];
        double mean = s / n;
        double var  = sq / n - mean * mean;
        float rstd  = (float)(1.0 / sqrt(var + (double)GN_EPS));
        float a  = gam[o] * rstd;
        float cc = bet[o] - (float)mean * a;
        g_gn2d[b][o]      = a;
        g_gn2d[b][64 + o] = cc;
    }
}

__global__ __launch_bounds__(128, 4) void k_pass3(const int* __restrict__ mask,
                                                  const float* __restrict__ b2at,
                                                  float* __restrict__ out) {
    extern __shared__ __align__(16) float sm[];
    int t = threadIdx.x, b = blockIdx.y;
    int colbase = blockIdx.x * 128;
    int cg = t & 31, og = t >> 5, obase = og * 16;

    // ---- stage: v = relu(a*h1 + c), w2at, bias ----
    {
        const float* gh1 = g_h1_buf + (size_t)b * 64 * MKn;
#pragma unroll
        for (int s = 0; s < 16; s++) {
            int id = t + 128 * s;
            int o = id >> 5, cq = id & 31;
            float4 h = *reinterpret_cast<const float4*>(
                gh1 + (size_t)o * MKn + colbase + 4 * cq);
            float a  = c_gn2[b][o];
            float cc = c_gn2[b][64 + o];
            float4 v;
            v.x = fmaxf(fmaf(a, h.x, cc), 0.f);
            v.y = fmaxf(fmaf(a, h.y, cc), 0.f);
            v.z = fmaxf(fmaf(a, h.z, cc), 0.f);
            v.w = fmaxf(fmaf(a, h.w, cc), 0.f);
            *reinterpret_cast<float4*>(&sm[P3_ACT + o * P3_STR + 4 * cq]) = v;
        }
        const float4* src = reinterpret_cast<const float4*>(g_w2at_t);
        float4* dstw = reinterpret_cast<float4*>(sm + P3_W);
#pragma unroll
        for (int i = 0; i < 8; i++) dstw[t + 128 * i] = src[t + 128 * i];
        if (t < 64) sm[P3_B + t] = b2at[t];
    }
    __syncthreads();

    // ---- GEMM: attn = w2at^T v + b2at ----
    u64 acc[4][8];
    TGEMM_K(64, (sm + P3_W), (sm + P3_B), acc, cg, obase, (sm + P3_ACT), P3_STR);
    __syncthreads();

    // ---- masked repack: attn (or -FLT_MAX) -> act ----
    {
        int4 mi = *reinterpret_cast<const int4*>(&mask[(size_t)b * MKn + colbase + 4 * cg]);
        bool mb[4] = {mi.x != 0, mi.y != 0, mi.z != 0, mi.w != 0};
#pragma unroll
        for (int p = 0; p < 8; p++) {
            float f0[4], f1[4];
#pragma unroll
            for (int c = 0; c < 4; c++) {
                unpack2(acc[c][p], f0[c], f1[c]);
                if (!mb[c]) { f0[c] = -FLT_MAX; f1[c] = -FLT_MAX; }
            }
            int o0 = obase + 2 * p;
            *reinterpret_cast<float4*>(&sm[P3_ACT + o0 * P3_STR + 4 * cg]) =
                make_float4(f0[0], f0[1], f0[2], f0[3]);
            *reinterpret_cast<float4*>(&sm[P3_ACT + (o0 + 1) * P3_STR + 4 * cg]) =
                make_float4(f1[0], f1[1], f1[2], f1[3]);
        }
    }
    __syncthreads();

    // ---- per-(m,o) softmax units: 16 contiguous values, no shuffles ----
    const float* gpe = g_pe_buf + (size_t)b * 64 * MKn;
    int mbase = colbase >> 4;      // 8 m per tile
#pragma unroll
    for (int r = 0; r < 4; r++) {
        int unit = r * 128 + t;    // 0..511
        int o = unit >> 3, ml = unit & 7;
        const float* ap = &sm[P3_ACT + o * P3_STR + 16 * ml];
        float av[16];
#pragma unroll
        for (int j = 0; j < 4; j++) {
            float4 x = *reinterpret_cast<const float4*>(ap + 4 * j);
            av[4 * j] = x.x; av[4 * j + 1] = x.y; av[4 * j + 2] = x.z; av[4 * j + 3] = x.w;
        }
        float mx = av[0];
#pragma unroll
        for (int j = 1; j < 16; j++) mx = fmaxf(mx, av[j]);
        float s = 0.f;
#pragma unroll
        for (int j = 0; j < 16; j++) { av[j] = __expf(av[j] - mx); s += av[j]; }
        const float* pp = gpe + (size_t)o * MKn + colbase + 16 * ml;
        float accum = 0.f;
#pragma unroll
        for (int j = 0; j < 4; j++) {
            float4 p = __ldg(reinterpret_cast<const float4*>(pp + 4 * j));
            accum = fmaf(p.x, av[4 * j], accum);
            accum = fmaf(p.y, av[4 * j + 1], accum);
            accum = fmaf(p.z, av[4 * j + 2], accum);
            accum = fmaf(p.w, av[4 * j + 3], accum);
        }
        out[((size_t)b * 64 + o) * Mn + mbase + ml] = accum * __fdividef(1.f, s);
    }
}

// ---------------- launch ----------------
extern "C" void kernel_launch(void* const* d_in, const int* in_sizes, int n_in,
                              void* d_out, int out_size) {
    const float* q_xyzs  = (const float*)d_in[0];
    const float* k_xyzs  = (const float*)d_in[1];
    const int*   knn_idx = (const int*)d_in[2];
    const int*   mask    = (const int*)d_in[3];
    const float* pe_w1   = (const float*)d_in[4];
    const float* pe_b1   = (const float*)d_in[5];
    const float* pe_g    = (const float*)d_in[6];
    const float* pe_be   = (const float*)d_in[7];
    const float* pe_w2   = (const float*)d_in[8];
    const float* pe_b2   = (const float*)d_in[9];
    const float* at_w1   = (const float*)d_in[10];
    const float* at_b1   = (const float*)d_in[11];
    const float* at_g    = (const float*)d_in[12];
    const float* at_be   = (const float*)d_in[13];
    const float* at_w2   = (const float*)d_in[14];
    const float* at_b2   = (const float*)d_in[15];
    float* out = (float*)d_out;

    static int smem_set = 0;
    if (!smem_set) {
        cudaFuncSetAttribute(k_pass2, cudaFuncAttributeMaxDynamicSharedMemorySize,
                             P2_TOT * 4);
        cudaFuncSetAttribute(k_pass3, cudaFuncAttributeMaxDynamicSharedMemorySize,
                             P3_TOT * 4);
        smem_set = 1;
    }

    k_prep<<<64, 64>>>(pe_w2, at_w1, at_w2);

    dim3 gcol(MKn / 128, Bn);
    k_pass1<<<gcol, 128>>>(q_xyzs, k_xyzs, knn_idx);
    k_fin1<<<1, 64>>>(pe_w1, pe_b1, pe_g, pe_be);

    k_pass2<<<gcol, 128, P2_TOT * 4>>>(q_xyzs, k_xyzs, knn_idx, pe_b2, at_b1);
    k_fin2<<<1, 64>>>(at_g, at_be);

    void* pg;
    cudaGetSymbolAddress(&pg, g_gn2d);
    cudaMemcpyToSymbolAsync(c_gn2, pg, Bn * 128 * 4, 0, cudaMemcpyDeviceToDevice, 0);

    k_pass3<<<gcol, 128, P3_TOT * 4>>>(mask, at_b2, out);
}

// round 9
// speedup vs baseline: 2.9479x; 1.0908x over previous
#include <cuda_runtime.h>
#include <cuda_fp16.h>
#include <math.h>
#include <float.h>

#define Bn   2
#define Mn   25000
#define Nn   100000
#define NGn  8
#define CPGn 8
#define GN_EPS 1e-5f
#define MKn  (Mn * 16)          // 400000 columns per batch

typedef unsigned long long u64;

// ---------------- constant-bank (small, uniform) ----------------
__constant__ __align__(16) float c_gn2[Bn][128];    // a2[64] | c2[64]

// ---------------- device scratch ----------------
__device__ double g_m1[Bn][14];                     // lp moments: S[4], M2 upper[10]
__device__ double g_s2[Bn][NGn][2];
__device__ __align__(16) float g_w1pe_f[Bn][256];   // folded conv1_pe [b][c][o]
__device__ __align__(16) float g_b1pe_f[Bn][64];
__device__ __align__(16) float g_gn2d[Bn][128];
__device__ __align__(16) float g_w2pe_t[4096];      // [k][o]
__device__ __align__(16) float g_w1at_t[4096];
__device__ __align__(16) float g_w2at_t[4096];
// transposed activation scratch [b][o][MKn], fp16
__device__ __align__(16) __half g_pe_buf[(size_t)Bn * 64 * MKn];
__device__ __align__(16) __half g_h1_buf[(size_t)Bn * 64 * MKn];

// ---------------- f32x2 / fp16 helpers ----------------
__device__ __forceinline__ u64 fma2(u64 a, u64 b, u64 c) {
    u64 d;
    asm("fma.rn.f32x2 %0, %1, %2, %3;" : "=l"(d) : "l"(a), "l"(b), "l"(c));
    return d;
}
__device__ __forceinline__ u64 add2(u64 a, u64 b) {
    u64 d;
    asm("add.rn.f32x2 %0, %1, %2;" : "=l"(d) : "l"(a), "l"(b));
    return d;
}
__device__ __forceinline__ u64 pack2(float v) {
    u64 r;
    asm("mov.b64 %0, {%1, %1};" : "=l"(r) : "f"(v));
    return r;
}
__device__ __forceinline__ void unpack2(u64 v, float& lo, float& hi) {
    asm("mov.b64 {%0, %1}, %2;" : "=f"(lo), "=f"(hi) : "l"(v));
}
__device__ __forceinline__ uint2 f4_to_h4(float4 v) {
    __half2 a = __floats2half2_rn(v.x, v.y);
    __half2 b = __floats2half2_rn(v.z, v.w);
    uint2 r;
    r.x = *reinterpret_cast<unsigned*>(&a);
    r.y = *reinterpret_cast<unsigned*>(&b);
    return r;
}
__device__ __forceinline__ float4 h4_to_f4(uint2 u) {
    __half2 a = *reinterpret_cast<__half2*>(&u.x);
    __half2 b = *reinterpret_cast<__half2*>(&u.y);
    float2 fa = __half22float2(a), fb = __half22float2(b);
    return make_float4(fa.x, fa.y, fb.x, fb.y);
}

// ---------------- tiled GEMM: ACC[4 cols][8 out-pairs] = bias + W^T x ----------------
#define TGEMM_K(KK, W, SBIAS, ACC, CG, OB, SA, STR) do {                          \
    _Pragma("unroll")                                                             \
    for (int _p = 0; _p < 8; _p++) {                                              \
        u64 _bv = *reinterpret_cast<const u64*>(&(SBIAS)[(OB) + 2 * _p]);         \
        (ACC)[0][_p] = _bv; (ACC)[1][_p] = _bv;                                   \
        (ACC)[2][_p] = _bv; (ACC)[3][_p] = _bv;                                   \
    }                                                                             \
    _Pragma("unroll 8")                                                           \
    for (int _k = 0; _k < (KK); _k++) {                                           \
        float4 _xv = *reinterpret_cast<const float4*>(                            \
            &(SA)[_k * (STR) + 4 * (CG)]);                                        \
        u64 _xb0 = pack2(_xv.x), _xb1 = pack2(_xv.y);                             \
        u64 _xb2 = pack2(_xv.z), _xb3 = pack2(_xv.w);                             \
        const ulonglong2* _wp =                                                   \
            reinterpret_cast<const ulonglong2*>(&(W)[(_k << 6) + (OB)]);          \
        ulonglong2 _wq0 = _wp[0], _wq1 = _wp[1], _wq2 = _wp[2], _wq3 = _wp[3];    \
        u64 _w[8] = {_wq0.x, _wq0.y, _wq1.x, _wq1.y,                              \
                     _wq2.x, _wq2.y, _wq3.x, _wq3.y};                             \
        _Pragma("unroll")                                                         \
        for (int _p = 0; _p < 8; _p++) {                                          \
            (ACC)[0][_p] = fma2(_w[_p], _xb0, (ACC)[0][_p]);                      \
            (ACC)[1][_p] = fma2(_w[_p], _xb1, (ACC)[1][_p]);                      \
            (ACC)[2][_p] = fma2(_w[_p], _xb2, (ACC)[2][_p]);                      \
            (ACC)[3][_p] = fma2(_w[_p], _xb3, (ACC)[3][_p]);                      \
        }                                                                         \
    }                                                                             \
} while (0)

// Repack 4cols x 16outs; optional relu; smem store fp32; global store fp16.
#define REPACK(ACC, OB, CG, SA, GPTR, RELU, DO_S, DO_G, STR) do {                 \
    _Pragma("unroll")                                                             \
    for (int _p = 0; _p < 8; _p++) {                                              \
        float _f0[4], _f1[4];                                                     \
        _Pragma("unroll")                                                         \
        for (int _c = 0; _c < 4; _c++) unpack2((ACC)[_c][_p], _f0[_c], _f1[_c]);  \
        if (RELU) {                                                               \
            _Pragma("unroll")                                                     \
            for (int _c = 0; _c < 4; _c++) {                                      \
                _f0[_c] = fmaxf(_f0[_c], 0.f); _f1[_c] = fmaxf(_f1[_c], 0.f);     \
            }                                                                     \
        }                                                                         \
        float4 _v0 = make_float4(_f0[0], _f0[1], _f0[2], _f0[3]);                 \
        float4 _v1 = make_float4(_f1[0], _f1[1], _f1[2], _f1[3]);                 \
        int _o0 = (OB) + 2 * _p;                                                  \
        if (DO_S) {                                                               \
            *reinterpret_cast<float4*>(&(SA)[_o0 * (STR) + 4 * (CG)]) = _v0;      \
            *reinterpret_cast<float4*>(&(SA)[(_o0 + 1) * (STR) + 4 * (CG)]) = _v1;\
        }                                                                         \
        if (DO_G) {                                                               \
            *reinterpret_cast<uint2*>((GPTR) + (size_t)_o0 * MKn) = f4_to_h4(_v0);\
            *reinterpret_cast<uint2*>((GPTR) + (size_t)(_o0 + 1) * MKn) =         \
                f4_to_h4(_v1);                                                    \
        }                                                                         \
    }                                                                             \
} while (0)

// ---------------- shared layouts (float offsets) ----------------
#define P2_ACT   0        // [64][128]
#define P2_W     8192     // [64][64]
#define P2_W1PE  12288    // [4][64]
#define P2_LPS   12544    // [4][128]
#define P2_BPA   13056
#define P2_BG1   13120
#define P2_BG2   13184
#define P2_RED   13248
#define P2_TOT   13264
#define P3_STR   136
#define P3_ACT   0        // [64][136]
#define P3_W     8704     // [64][64]
#define P3_B     12800
#define P3_TOT   12864

// ---------------- helpers ----------------
__device__ __forceinline__ void compute_lp(const float* __restrict__ q,
                                           const float* __restrict__ kx,
                                           const int*   __restrict__ idx,
                                           int b, int c, float lp[4]) {
    int m  = c >> 4;
    int id = idx[b * MKn + c];
    float qx = q[(b * 3 + 0) * Mn + m];
    float qy = q[(b * 3 + 1) * Mn + m];
    float qz = q[(b * 3 + 2) * Mn + m];
    float px = kx[(b * 3 + 0) * Nn + id];
    float py = kx[(b * 3 + 1) * Nn + id];
    float pz = kx[(b * 3 + 2) * Nn + id];
    float ox = px - qx, oy = py - qy, oz = pz - qz;
    float d  = sqrtf(ox * ox + oy * oy + oz * oz);
    float r  = 1.0f / fmaxf(d, 1e-12f);
    lp[0] = ox * r; lp[1] = oy * r; lp[2] = oz * r; lp[3] = d;
}

// ---------------- kernels ----------------
__global__ void k_prep(const float* __restrict__ w2pe,
                       const float* __restrict__ w1at,
                       const float* __restrict__ w2at) {
    int i = blockIdx.x;   // output channel
    int j = threadIdx.x;  // input channel
    g_w2pe_t[j * 64 + i] = w2pe[i * 64 + j];
    g_w1at_t[j * 64 + i] = w1at[i * 64 + j];
    g_w2at_t[j * 64 + i] = w2at[i * 64 + j];
    if (i == 0) {
        if (j < Bn * NGn * 2) ((double*)g_s2)[j] = 0.0;
        if (j < Bn * 14)      ((double*)g_m1)[j] = 0.0;
    }
}

// pass1: only lp moments (S[4], M2 upper-tri[10])
__global__ __launch_bounds__(128) void k_pass1(const float* __restrict__ q,
                                               const float* __restrict__ kx,
                                               const int*   __restrict__ idx) {
    __shared__ float s_red[14];
    int t = threadIdx.x, b = blockIdx.y;
    if (t < 14) s_red[t] = 0.f;
    __syncthreads();
    int col = blockIdx.x * 128 + t;
    float lp[4];
    compute_lp(q, kx, idx, b, col, lp);

    float v[14];
    v[0] = lp[0]; v[1] = lp[1]; v[2] = lp[2]; v[3] = lp[3];
    {
        int n = 4;
#pragma unroll
        for (int c = 0; c < 4; c++)
#pragma unroll
            for (int d = c; d < 4; d++) v[n++] = lp[c] * lp[d];
    }
#pragma unroll
    for (int i = 0; i < 14; i++) {
        for (int off = 16; off; off >>= 1)
            v[i] += __shfl_down_sync(0xffffffffu, v[i], off);
        if ((t & 31) == 0) atomicAdd(&s_red[i], v[i]);
    }
    __syncthreads();
    if (t < 14) atomicAdd(&g_m1[b][t], (double)s_red[t]);
}

__global__ void k_fin1(const float* __restrict__ w1, const float* __restrict__ b1,
                       const float* __restrict__ gam, const float* __restrict__ bet) {
    __shared__ double gs[8], gq[8];
    int o = threadIdx.x;  // 64 threads
    double n = (double)CPGn * (double)MKn;
    for (int b = 0; b < Bn; b++) {
        if (o < 8) { gs[o] = 0.0; gq[o] = 0.0; }
        __syncthreads();
        double m[14];
#pragma unroll
        for (int i = 0; i < 14; i++) m[i] = g_m1[b][i];
        double M2[4][4];
        {
            int idx5 = 4;
            for (int c = 0; c < 4; c++)
                for (int d = c; d < 4; d++) {
                    M2[c][d] = m[idx5]; M2[d][c] = m[idx5]; idx5++;
                }
        }
        double w[4];
#pragma unroll
        for (int c = 0; c < 4; c++) w[c] = (double)w1[o * 4 + c];
        double bo = (double)b1[o];
        double dot = w[0] * m[0] + w[1] * m[1] + w[2] * m[2] + w[3] * m[3];
        double sum_o = dot + (double)MKn * bo;
        double sq_o = 0.0;
#pragma unroll
        for (int c = 0; c < 4; c++)
#pragma unroll
            for (int d = 0; d < 4; d++) sq_o += w[c] * w[d] * M2[c][d];
        sq_o += 2.0 * bo * dot + (double)MKn * bo * bo;
        atomicAdd(&gs[o >> 3], sum_o);
        atomicAdd(&gq[o >> 3], sq_o);
        __syncthreads();
        int g = o >> 3;
        double mean = gs[g] / n;
        double var  = gq[g] / n - mean * mean;
        float rstd  = (float)(1.0 / sqrt(var + (double)GN_EPS));
        float a  = gam[o] * rstd;
        float cc = bet[o] - (float)mean * a;
        g_b1pe_f[b][o] = fmaf(a, b1[o], cc);
        for (int c = 0; c < 4; c++) g_w1pe_f[b][c * 64 + o] = a * w1[o * 4 + c];
        __syncthreads();
    }
}

__global__ __launch_bounds__(128, 4) void k_pass2(const float* __restrict__ q,
                                                  const float* __restrict__ kx,
                                                  const int*   __restrict__ idx,
                                                  const float* __restrict__ b2pe,
                                                  const float* __restrict__ b1at) {
    extern __shared__ __align__(16) float sm[];
    int t = threadIdx.x, b = blockIdx.y;
    int colbase = blockIdx.x * 128;
    int cg = t & 31, og = t >> 5, obase = og * 16;

    {
        int col = colbase + t;
        float lp[4];
        compute_lp(q, kx, idx, b, col, lp);
#pragma unroll
        for (int c = 0; c < 4; c++) sm[P2_LPS + c * 128 + t] = lp[c];
        const float4* src = reinterpret_cast<const float4*>(g_w2pe_t);
        float4* dstw = reinterpret_cast<float4*>(sm + P2_W);
#pragma unroll
        for (int i = 0; i < 8; i++) dstw[t + 128 * i] = src[t + 128 * i];
        if (t < 64) {
            *reinterpret_cast<float4*>(sm + P2_W1PE + 4 * t) =
                *reinterpret_cast<const float4*>(&g_w1pe_f[b][4 * t]);
        } else {
            int u = t - 64;
            sm[P2_BPA + u] = g_b1pe_f[b][u];
            sm[P2_BG1 + u] = b2pe[u];
            sm[P2_BG2 + u] = b1at[u];
        }
        if (t < 16) sm[P2_RED + t] = 0.f;
    }
    __syncthreads();

    {
        u64 acc[4][8];
        TGEMM_K(4, (sm + P2_W1PE), (sm + P2_BPA), acc, cg, obase, (sm + P2_LPS), 128);
        REPACK(acc, obase, cg, (sm + P2_ACT), (__half*)0, 1, 1, 0, 128);
    }
    __syncthreads();

    u64 acc1[4][8];
    TGEMM_K(64, (sm + P2_W), (sm + P2_BG1), acc1, cg, obase, (sm + P2_ACT), 128);
    __syncthreads();
    {
        __half* gpe = g_pe_buf + (size_t)b * 64 * MKn + colbase + 4 * cg;
        REPACK(acc1, obase, cg, (sm + P2_ACT), gpe, 0, 1, 1, 128);
        const float4* src = reinterpret_cast<const float4*>(g_w1at_t);
        float4* dstw = reinterpret_cast<float4*>(sm + P2_W);
#pragma unroll
        for (int i = 0; i < 8; i++) dstw[t + 128 * i] = src[t + 128 * i];
    }
    __syncthreads();

    u64 acc2[4][8];
    TGEMM_K(64, (sm + P2_W), (sm + P2_BG2), acc2, cg, obase, (sm + P2_ACT), 128);
    {
        __half* gh1 = g_h1_buf + (size_t)b * 64 * MKn + colbase + 4 * cg;
        REPACK(acc2, obase, cg, (sm + P2_ACT), gh1, 0, 0, 1, 128);
    }

    {
        u64 sa = 0ull, qa = 0ull, sb = 0ull, qb = 0ull;
#pragma unroll
        for (int c = 0; c < 4; c++) {
#pragma unroll
            for (int p = 0; p < 4; p++) {
                sa = add2(sa, acc2[c][p]);
                qa = fma2(acc2[c][p], acc2[c][p], qa);
            }
#pragma unroll
            for (int p = 4; p < 8; p++) {
                sb = add2(sb, acc2[c][p]);
                qb = fma2(acc2[c][p], acc2[c][p], qb);
            }
        }
        float r[4], x0, x1;
        unpack2(sa, x0, x1); r[0] = x0 + x1;
        unpack2(qa, x0, x1); r[1] = x0 + x1;
        unpack2(sb, x0, x1); r[2] = x0 + x1;
        unpack2(qb, x0, x1); r[3] = x0 + x1;
#pragma unroll
        for (int i = 0; i < 4; i++)
            for (int off = 16; off; off >>= 1)
                r[i] += __shfl_down_sync(0xffffffffu, r[i], off);
        if ((t & 31) == 0) {
            sm[P2_RED + og * 4 + 0] = r[0];
            sm[P2_RED + og * 4 + 1] = r[1];
            sm[P2_RED + og * 4 + 2] = r[2];
            sm[P2_RED + og * 4 + 3] = r[3];
        }
    }
    __syncthreads();
    if (t < 16) {
        int w = t >> 2, i = t & 3;
        atomicAdd(&g_s2[b][2 * w + (i >> 1)][i & 1], (double)sm[P2_RED + t]);
    }
}

__global__ void k_fin2(const float* __restrict__ gam, const float* __restrict__ bet) {
    int o = threadIdx.x;  // 64 threads
    double n = (double)CPGn * (double)MKn;
    for (int b = 0; b < Bn; b++) {
        int g = o >> 3;
        double s = g_s2[b][g][0], sq = g_s2[b][g][1];
        double mean = s / n;
        double var  = sq / n - mean * mean;
        float rstd  = (float)(1.0 / sqrt(var + (double)GN_EPS));
        float a  = gam[o] * rstd;
        float cc = bet[o] - (float)mean * a;
        g_gn2d[b][o]      = a;
        g_gn2d[b][64 + o] = cc;
    }
}

__global__ __launch_bounds__(128, 4) void k_pass3(const int* __restrict__ mask,
                                                  const float* __restrict__ b2at,
                                                  float* __restrict__ out) {
    extern __shared__ __align__(16) float sm[];
    int t = threadIdx.x, b = blockIdx.y;
    int colbase = blockIdx.x * 128;
    int cg = t & 31, og = t >> 5, obase = og * 16;

    // ---- stage: v = relu(a*h1 + c) from fp16 h1, w2at, bias ----
    {
        const __half* gh1 = g_h1_buf + (size_t)b * 64 * MKn;
#pragma unroll
        for (int s = 0; s < 16; s++) {
            int id = t + 128 * s;
            int o = id >> 5, cq = id & 31;
            uint2 hv = __ldg(reinterpret_cast<const uint2*>(
                gh1 + (size_t)o * MKn + colbase + 4 * cq));
            float4 h = h4_to_f4(hv);
            float a  = c_gn2[b][o];
            float cc = c_gn2[b][64 + o];
            float4 v;
            v.x = fmaxf(fmaf(a, h.x, cc), 0.f);
            v.y = fmaxf(fmaf(a, h.y, cc), 0.f);
            v.z = fmaxf(fmaf(a, h.z, cc), 0.f);
            v.w = fmaxf(fmaf(a, h.w, cc), 0.f);
            *reinterpret_cast<float4*>(&sm[P3_ACT + o * P3_STR + 4 * cq]) = v;
        }
        const float4* src = reinterpret_cast<const float4*>(g_w2at_t);
        float4* dstw = reinterpret_cast<float4*>(sm + P3_W);
#pragma unroll
        for (int i = 0; i < 8; i++) dstw[t + 128 * i] = src[t + 128 * i];
        if (t < 64) sm[P3_B + t] = b2at[t];
    }
    __syncthreads();

    // ---- GEMM: attn = w2at^T v + b2at ----
    u64 acc[4][8];
    TGEMM_K(64, (sm + P3_W), (sm + P3_B), acc, cg, obase, (sm + P3_ACT), P3_STR);
    __syncthreads();

    // ---- masked repack: attn (or -FLT_MAX) -> act ----
    {
        int4 mi = *reinterpret_cast<const int4*>(&mask[(size_t)b * MKn + colbase + 4 * cg]);
        bool mb[4] = {mi.x != 0, mi.y != 0, mi.z != 0, mi.w != 0};
#pragma unroll
        for (int p = 0; p < 8; p++) {
            float f0[4], f1[4];
#pragma unroll
            for (int c = 0; c < 4; c++) {
                unpack2(acc[c][p], f0[c], f1[c]);
                if (!mb[c]) { f0[c] = -FLT_MAX; f1[c] = -FLT_MAX; }
            }
            int o0 = obase + 2 * p;
            *reinterpret_cast<float4*>(&sm[P3_ACT + o0 * P3_STR + 4 * cg]) =
                make_float4(f0[0], f0[1], f0[2], f0[3]);
            *reinterpret_cast<float4*>(&sm[P3_ACT + (o0 + 1) * P3_STR + 4 * cg]) =
                make_float4(f1[0], f1[1], f1[2], f1[3]);
        }
    }
    __syncthreads();

    // ---- per-(m,o) softmax units: 16 contiguous values, no shuffles ----
    const __half* gpe = g_pe_buf + (size_t)b * 64 * MKn;
    int mbase = colbase >> 4;      // 8 m per tile
#pragma unroll
    for (int r = 0; r < 4; r++) {
        int unit = r * 128 + t;    // 0..511
        int o = unit >> 3, ml = unit & 7;
        const float* ap = &sm[P3_ACT + o * P3_STR + 16 * ml];
        float av[16];
#pragma unroll
        for (int j = 0; j < 4; j++) {
            float4 x = *reinterpret_cast<const float4*>(ap + 4 * j);
            av[4 * j] = x.x; av[4 * j + 1] = x.y; av[4 * j + 2] = x.z; av[4 * j + 3] = x.w;
        }
        float mx = av[0];
#pragma unroll
        for (int j = 1; j < 16; j++) mx = fmaxf(mx, av[j]);
        float s = 0.f;
#pragma unroll
        for (int j = 0; j < 16; j++) { av[j] = __expf(av[j] - mx); s += av[j]; }
        const __half* pp = gpe + (size_t)o * MKn + colbase + 16 * ml;
        float accum = 0.f;
#pragma unroll
        for (int j = 0; j < 4; j++) {
            float4 p = h4_to_f4(__ldg(reinterpret_cast<const uint2*>(pp + 4 * j)));
            accum = fmaf(p.x, av[4 * j], accum);
            accum = fmaf(p.y, av[4 * j + 1], accum);
            accum = fmaf(p.z, av[4 * j + 2], accum);
            accum = fmaf(p.w, av[4 * j + 3], accum);
        }
        out[((size_t)b * 64 + o) * Mn + mbase + ml] = accum * __fdividef(1.f, s);
    }
}

// ---------------- launch ----------------
extern "C" void kernel_launch(void* const* d_in, const int* in_sizes, int n_in,
                              void* d_out, int out_size) {
    const float* q_xyzs  = (const float*)d_in[0];
    const float* k_xyzs  = (const float*)d_in[1];
    const int*   knn_idx = (const int*)d_in[2];
    const int*   mask    = (const int*)d_in[3];
    const float* pe_w1   = (const float*)d_in[4];
    const float* pe_b1   = (const float*)d_in[5];
    const float* pe_g    = (const float*)d_in[6];
    const float* pe_be   = (const float*)d_in[7];
    const float* pe_w2   = (const float*)d_in[8];
    const float* pe_b2   = (const float*)d_in[9];
    const float* at_w1   = (const float*)d_in[10];
    const float* at_b1   = (const float*)d_in[11];
    const float* at_g    = (const float*)d_in[12];
    const float* at_be   = (const float*)d_in[13];
    const float* at_w2   = (const float*)d_in[14];
    const float* at_b2   = (const float*)d_in[15];
    float* out = (float*)d_out;

    static int smem_set = 0;
    if (!smem_set) {
        cudaFuncSetAttribute(k_pass2, cudaFuncAttributeMaxDynamicSharedMemorySize,
                             P2_TOT * 4);
        cudaFuncSetAttribute(k_pass3, cudaFuncAttributeMaxDynamicSharedMemorySize,
                             P3_TOT * 4);
        smem_set = 1;
    }

    k_prep<<<64, 64>>>(pe_w2, at_w1, at_w2);

    dim3 gcol(MKn / 128, Bn);
    k_pass1<<<gcol, 128>>>(q_xyzs, k_xyzs, knn_idx);
    k_fin1<<<1, 64>>>(pe_w1, pe_b1, pe_g, pe_be);

    k_pass2<<<gcol, 128, P2_TOT * 4>>>(q_xyzs, k_xyzs, knn_idx, pe_b2, at_b1);
    k_fin2<<<1, 64>>>(at_g, at_be);

    void* pg;
    cudaGetSymbolAddress(&pg, g_gn2d);
    cudaMemcpyToSymbolAsync(c_gn2, pg, Bn * 128 * 4, 0, cudaMemcpyDeviceToDevice, 0);

    k_pass3<<<gcol, 128, P3_TOT * 4>>>(mask, at_b2, out);
}

// round 10
// speedup vs baseline: 4.6119x; 1.5645x over previous
#include <cuda_runtime.h>
#include <cuda_fp16.h>
#include <math.h>
#include <float.h>

#define Bn   2
#define Mn   25000
#define Nn   100000
#define NGn  8
#define CPGn 8
#define GN_EPS 1e-5f
#define MKn  (Mn * 16)          // 400000 columns per batch

#define XSTR 70                 // fp16 elems per Xs row (col-major activations [col][k])
#define WSTR 70                 // fp16 elems per Ws row ([o][k])
#define ASTR 136                // fp32 act stride in pass3

typedef unsigned long long u64;

// ---------------- constant-bank ----------------
__constant__ __align__(16) float c_gn2[Bn][128];    // a2[64] | c2[64]

// ---------------- device scratch ----------------
__device__ double g_m1[Bn][14];
__device__ double g_s2[Bn][NGn][2];
__device__ __align__(16) float g_w1pe_f[Bn][256];   // folded conv1_pe [b][c][o]
__device__ __align__(16) float g_b1pe_f[Bn][64];
__device__ __align__(16) float g_gn2d[Bn][128];
__device__ __align__(16) __half g_w2pe_h[4096];     // [o][k] fp16
__device__ __align__(16) __half g_w1at_h[4096];     // [o][k] fp16
__device__ __align__(16) __half g_w2at_h[4096];     // [o][k] fp16
// transposed activation scratch [b][o][MKn], fp16
__device__ __align__(16) __half g_pe_buf[(size_t)Bn * 64 * MKn];
__device__ __align__(16) __half g_h1_buf[(size_t)Bn * 64 * MKn];

// ---------------- f32x2 helpers (phase-A conv) ----------------
__device__ __forceinline__ u64 fma2(u64 a, u64 b, u64 c) {
    u64 d;
    asm("fma.rn.f32x2 %0, %1, %2, %3;" : "=l"(d) : "l"(a), "l"(b), "l"(c));
    return d;
}
__device__ __forceinline__ u64 pack2(float v) {
    u64 r;
    asm("mov.b64 %0, {%1, %1};" : "=l"(r) : "f"(v));
    return r;
}
__device__ __forceinline__ void unpack2(u64 v, float& lo, float& hi) {
    asm("mov.b64 {%0, %1}, %2;" : "=f"(lo), "=f"(hi) : "l"(v));
}
__device__ __forceinline__ float4 h4_to_f4(uint2 u) {
    __half2 a = *reinterpret_cast<__half2*>(&u.x);
    __half2 b = *reinterpret_cast<__half2*>(&u.y);
    float2 fa = __half22float2(a), fb = __half22float2(b);
    return make_float4(fa.x, fa.y, fb.x, fb.y);
}

// ---------------- mma.sync m16n8k16 f16->f32 ----------------
__device__ __forceinline__ void mma16816(float* c, const unsigned* a, const unsigned* b) {
    asm volatile(
        "mma.sync.aligned.m16n8k16.row.col.f32.f16.f16.f32 "
        "{%0,%1,%2,%3}, {%4,%5,%6,%7}, {%8,%9}, {%0,%1,%2,%3};\n"
        : "+f"(c[0]), "+f"(c[1]), "+f"(c[2]), "+f"(c[3])
        : "r"(a[0]), "r"(a[1]), "r"(a[2]), "r"(a[3]), "r"(b[0]), "r"(b[1]));
}

// one warp computes 64(out) x 32(col): Ws fp16 [64][WSTR], Xs fp16 [128][XSTR],
// bias fp32[64]. acc c[mt][nt][4]: rows (16mt+grp, +8), cols (n0+8nt+tig*2, +1).
__device__ __forceinline__ void mma_gemm64(const __half* Ws, const __half* Xs,
                                           const float* bias, int n0,
                                           int grp, int tig, float c[4][4][4]) {
#pragma unroll
    for (int mt = 0; mt < 4; mt++) {
        float b0 = bias[16 * mt + grp];
        float b1 = bias[16 * mt + 8 + grp];
#pragma unroll
        for (int nt = 0; nt < 4; nt++) {
            c[mt][nt][0] = b0; c[mt][nt][1] = b0;
            c[mt][nt][2] = b1; c[mt][nt][3] = b1;
        }
    }
#pragma unroll
    for (int kt = 0; kt < 4; kt++) {
        int k0 = kt * 16;
        unsigned a[4][4], bf[4][2];
#pragma unroll
        for (int mt = 0; mt < 4; mt++) {
            const __half* base = Ws + (16 * mt + grp) * WSTR + k0 + tig * 2;
            a[mt][0] = *reinterpret_cast<const unsigned*>(base);
            a[mt][1] = *reinterpret_cast<const unsigned*>(base + 8 * WSTR);
            a[mt][2] = *reinterpret_cast<const unsigned*>(base + 8);
            a[mt][3] = *reinterpret_cast<const unsigned*>(base + 8 * WSTR + 8);
        }
#pragma unroll
        for (int nt = 0; nt < 4; nt++) {
            const __half* base = Xs + (n0 + 8 * nt + grp) * XSTR + k0 + tig * 2;
            bf[nt][0] = *reinterpret_cast<const unsigned*>(base);
            bf[nt][1] = *reinterpret_cast<const unsigned*>(base + 8);
        }
#pragma unroll
        for (int mt = 0; mt < 4; mt++)
#pragma unroll
            for (int nt = 0; nt < 4; nt++)
                mma16816(c[mt][nt], a[mt], bf[nt]);
    }
}

// ---------------- helpers ----------------
__device__ __forceinline__ void compute_lp(const float* __restrict__ q,
                                           const float* __restrict__ kx,
                                           const int*   __restrict__ idx,
                                           int b, int c, float lp[4]) {
    int m  = c >> 4;
    int id = idx[b * MKn + c];
    float qx = q[(b * 3 + 0) * Mn + m];
    float qy = q[(b * 3 + 1) * Mn + m];
    float qz = q[(b * 3 + 2) * Mn + m];
    float px = kx[(b * 3 + 0) * Nn + id];
    float py = kx[(b * 3 + 1) * Nn + id];
    float pz = kx[(b * 3 + 2) * Nn + id];
    float ox = px - qx, oy = py - qy, oz = pz - qz;
    float d  = sqrtf(ox * ox + oy * oy + oz * oz);
    float r  = 1.0f / fmaxf(d, 1e-12f);
    lp[0] = ox * r; lp[1] = oy * r; lp[2] = oz * r; lp[3] = d;
}

// stage a 64x64 fp16 weight matrix [o][k] into padded smem [o][WSTR]
__device__ __forceinline__ void stage_w(const __half* __restrict__ gsrc,
                                        __half* Ws, int t) {
    const unsigned* src = reinterpret_cast<const unsigned*>(gsrc);
#pragma unroll
    for (int i = t; i < 2048; i += 128) {
        int o = i >> 5, kq = i & 31;
        *reinterpret_cast<unsigned*>(Ws + o * WSTR + kq * 2) = src[i];
    }
}

// ---------------- kernels ----------------
__global__ void k_prep(const float* __restrict__ w2pe,
                       const float* __restrict__ w1at,
                       const float* __restrict__ w2at) {
    int i = blockIdx.x;   // output channel
    int j = threadIdx.x;  // input channel
    g_w2pe_h[i * 64 + j] = __float2half(w2pe[i * 64 + j]);
    g_w1at_h[i * 64 + j] = __float2half(w1at[i * 64 + j]);
    g_w2at_h[i * 64 + j] = __float2half(w2at[i * 64 + j]);
    if (i == 0) {
        if (j < Bn * NGn * 2) ((double*)g_s2)[j] = 0.0;
        if (j < Bn * 14)      ((double*)g_m1)[j] = 0.0;
    }
}

// pass1: lp moments only
__global__ __launch_bounds__(128) void k_pass1(const float* __restrict__ q,
                                               const float* __restrict__ kx,
                                               const int*   __restrict__ idx) {
    __shared__ float s_red[14];
    int t = threadIdx.x, b = blockIdx.y;
    if (t < 14) s_red[t] = 0.f;
    __syncthreads();
    int col = blockIdx.x * 128 + t;
    float lp[4];
    compute_lp(q, kx, idx, b, col, lp);

    float v[14];
    v[0] = lp[0]; v[1] = lp[1]; v[2] = lp[2]; v[3] = lp[3];
    {
        int n = 4;
#pragma unroll
        for (int c = 0; c < 4; c++)
#pragma unroll
            for (int d = c; d < 4; d++) v[n++] = lp[c] * lp[d];
    }
#pragma unroll
    for (int i = 0; i < 14; i++) {
        for (int off = 16; off; off >>= 1)
            v[i] += __shfl_down_sync(0xffffffffu, v[i], off);
        if ((t & 31) == 0) atomicAdd(&s_red[i], v[i]);
    }
    __syncthreads();
    if (t < 14) atomicAdd(&g_m1[b][t], (double)s_red[t]);
}

__global__ void k_fin1(const float* __restrict__ w1, const float* __restrict__ b1,
                       const float* __restrict__ gam, const float* __restrict__ bet) {
    __shared__ double gs[8], gq[8];
    int o = threadIdx.x;  // 64 threads
    double n = (double)CPGn * (double)MKn;
    for (int b = 0; b < Bn; b++) {
        if (o < 8) { gs[o] = 0.0; gq[o] = 0.0; }
        __syncthreads();
        double m[14];
#pragma unroll
        for (int i = 0; i < 14; i++) m[i] = g_m1[b][i];
        double M2[4][4];
        {
            int idx5 = 4;
            for (int c = 0; c < 4; c++)
                for (int d = c; d < 4; d++) {
                    M2[c][d] = m[idx5]; M2[d][c] = m[idx5]; idx5++;
                }
        }
        double w[4];
#pragma unroll
        for (int c = 0; c < 4; c++) w[c] = (double)w1[o * 4 + c];
        double bo = (double)b1[o];
        double dot = w[0] * m[0] + w[1] * m[1] + w[2] * m[2] + w[3] * m[3];
        double sum_o = dot + (double)MKn * bo;
        double sq_o = 0.0;
#pragma unroll
        for (int c = 0; c < 4; c++)
#pragma unroll
            for (int d = 0; d < 4; d++) sq_o += w[c] * w[d] * M2[c][d];
        sq_o += 2.0 * bo * dot + (double)MKn * bo * bo;
        atomicAdd(&gs[o >> 3], sum_o);
        atomicAdd(&gq[o >> 3], sq_o);
        __syncthreads();
        int g = o >> 3;
        double mean = gs[g] / n;
        double var  = gq[g] / n - mean * mean;
        float rstd  = (float)(1.0 / sqrt(var + (double)GN_EPS));
        float a  = gam[o] * rstd;
        float cc = bet[o] - (float)mean * a;
        g_b1pe_f[b][o] = fmaf(a, b1[o], cc);
        for (int c = 0; c < 4; c++) g_w1pe_f[b][c * 64 + o] = a * w1[o * 4 + c];
        __syncthreads();
    }
}

// ---- pass2 smem layout (bytes) ----
#define P2_XS    0                  // fp16 128*XSTR
#define P2_WS1   (P2_XS + 128 * XSTR * 2)
#define P2_WS2   (P2_WS1 + 64 * WSTR * 2)
#define P2_W1PE  (P2_WS2 + 64 * WSTR * 2)     // fp32 256
#define P2_B1PE  (P2_W1PE + 1024)
#define P2_B2PE  (P2_B1PE + 256)
#define P2_B1AT  (P2_B2PE + 256)
#define P2_RED   (P2_B1AT + 256)
#define P2_TOTB  (P2_RED + 64)

__global__ __launch_bounds__(128, 4) void k_pass2(const float* __restrict__ q,
                                                  const float* __restrict__ kx,
                                                  const int*   __restrict__ idx,
                                                  const float* __restrict__ b2pe,
                                                  const float* __restrict__ b1at) {
    extern __shared__ __align__(16) char smc[];
    __half* Xs  = reinterpret_cast<__half*>(smc + P2_XS);
    __half* Ws1 = reinterpret_cast<__half*>(smc + P2_WS1);
    __half* Ws2 = reinterpret_cast<__half*>(smc + P2_WS2);
    float* s_w1pe = reinterpret_cast<float*>(smc + P2_W1PE);
    float* s_b1pe = reinterpret_cast<float*>(smc + P2_B1PE);
    float* s_b2pe = reinterpret_cast<float*>(smc + P2_B2PE);
    float* s_b1at = reinterpret_cast<float*>(smc + P2_B1AT);
    float* s_red  = reinterpret_cast<float*>(smc + P2_RED);

    int t = threadIdx.x, b = blockIdx.y;
    int colbase = blockIdx.x * 128;
    int lane = t & 31, warp = t >> 5;
    int grp = lane >> 2, tig = lane & 3;
    int n0 = warp * 32;

    // ---- stage weights + params ----
    stage_w(g_w2pe_h, Ws1, t);
    stage_w(g_w1at_h, Ws2, t);
    s_w1pe[t] = g_w1pe_f[b][t];
    s_w1pe[t + 128] = g_w1pe_f[b][t + 128];
    if (t < 64) {
        s_b1pe[t] = g_b1pe_f[b][t];
        s_b2pe[t] = b2pe[t];
        s_b1at[t] = b1at[t];
    }
    if (t < 16) s_red[t] = 0.f;
    __syncthreads();

    // ---- phase A: u = relu(conv1_pe'(lp)) -> Xs[col=t][k] fp16 ----
    {
        int col = colbase + t;
        float lp[4];
        compute_lp(q, kx, idx, b, col, lp);
        u64 a1[32];
#pragma unroll
        for (int p = 0; p < 32; p++)
            a1[p] = *reinterpret_cast<const u64*>(&s_b1pe[2 * p]);
#pragma unroll
        for (int c = 0; c < 4; c++) {
            u64 xb = pack2(lp[c]);
#pragma unroll
            for (int p = 0; p < 32; p++) {
                u64 w = *reinterpret_cast<const u64*>(&s_w1pe[c * 64 + 2 * p]);
                a1[p] = fma2(w, xb, a1[p]);
            }
        }
#pragma unroll
        for (int p = 0; p < 32; p++) {
            float lo, hi;
            unpack2(a1[p], lo, hi);
            __half2 h = __floats2half2_rn(fmaxf(lo, 0.f), fmaxf(hi, 0.f));
            *reinterpret_cast<__half2*>(Xs + t * XSTR + 2 * p) = h;
        }
    }
    __syncwarp();

    // ---- GEMM1: pe = w2pe * u + b2pe (tensor) ----
    float c1[4][4][4];
    mma_gemm64(Ws1, Xs, s_b2pe, n0, grp, tig, c1);
    // repack: global fp16 [o][col] + in-place smem transpose Xs[col][o]
    {
        __half* gpe = g_pe_buf + (size_t)b * 64 * MKn + colbase;
#pragma unroll
        for (int mt = 0; mt < 4; mt++) {
            int r0 = 16 * mt + grp, r1 = r0 + 8;
#pragma unroll
            for (int nt = 0; nt < 4; nt++) {
                int colL = n0 + 8 * nt + tig * 2;
                __half2 h01 = __floats2half2_rn(c1[mt][nt][0], c1[mt][nt][1]);
                __half2 h23 = __floats2half2_rn(c1[mt][nt][2], c1[mt][nt][3]);
                *reinterpret_cast<__half2*>(gpe + (size_t)r0 * MKn + colL) = h01;
                *reinterpret_cast<__half2*>(gpe + (size_t)r1 * MKn + colL) = h23;
                Xs[colL * XSTR + r0]       = __low2half(h01);
                Xs[(colL + 1) * XSTR + r0] = __high2half(h01);
                Xs[colL * XSTR + r1]       = __low2half(h23);
                Xs[(colL + 1) * XSTR + r1] = __high2half(h23);
            }
        }
    }
    __syncwarp();

    // ---- GEMM2: h1 = w1at * pe + b1at (tensor) ----
    float c2[4][4][4];
    mma_gemm64(Ws2, Xs, s_b1at, n0, grp, tig, c2);
    // store h1 global fp16 + GN2 stats from fp32 fragments
    {
        __half* gh1 = g_h1_buf + (size_t)b * 64 * MKn + colbase;
        float gs[8], gq[8];
#pragma unroll
        for (int g = 0; g < 8; g++) { gs[g] = 0.f; gq[g] = 0.f; }
#pragma unroll
        for (int mt = 0; mt < 4; mt++) {
            int r0 = 16 * mt + grp, r1 = r0 + 8;
#pragma unroll
            for (int nt = 0; nt < 4; nt++) {
                int colL = n0 + 8 * nt + tig * 2;
                float v0 = c2[mt][nt][0], v1 = c2[mt][nt][1];
                float v2 = c2[mt][nt][2], v3 = c2[mt][nt][3];
                *reinterpret_cast<__half2*>(gh1 + (size_t)r0 * MKn + colL) =
                    __floats2half2_rn(v0, v1);
                *reinterpret_cast<__half2*>(gh1 + (size_t)r1 * MKn + colL) =
                    __floats2half2_rn(v2, v3);
                gs[2 * mt]     += v0 + v1;
                gq[2 * mt]     = fmaf(v0, v0, fmaf(v1, v1, gq[2 * mt]));
                gs[2 * mt + 1] += v2 + v3;
                gq[2 * mt + 1] = fmaf(v2, v2, fmaf(v3, v3, gq[2 * mt + 1]));
            }
        }
        float r[16];
#pragma unroll
        for (int g = 0; g < 8; g++) { r[g] = gs[g]; r[8 + g] = gq[g]; }
#pragma unroll
        for (int i = 0; i < 16; i++)
            for (int off = 16; off; off >>= 1)
                r[i] += __shfl_down_sync(0xffffffffu, r[i], off);
        if (lane == 0) {
#pragma unroll
            for (int i = 0; i < 16; i++) atomicAdd(&s_red[i], r[i]);
        }
    }
    __syncthreads();
    if (t < 16) atomicAdd(&g_s2[b][t & 7][t >> 3], (double)s_red[t]);
}

__global__ void k_fin2(const float* __restrict__ gam, const float* __restrict__ bet) {
    int o = threadIdx.x;  // 64 threads
    double n = (double)CPGn * (double)MKn;
    for (int b = 0; b < Bn; b++) {
        int g = o >> 3;
        double s = g_s2[b][g][0], sq = g_s2[b][g][1];
        double mean = s / n;
        double var  = sq / n - mean * mean;
        float rstd  = (float)(1.0 / sqrt(var + (double)GN_EPS));
        float a  = gam[o] * rstd;
        float cc = bet[o] - (float)mean * a;
        g_gn2d[b][o]      = a;
        g_gn2d[b][64 + o] = cc;
    }
}

// ---- pass3 smem layout: act fp32 overlaps Xs/Ws (sequenced by barriers) ----
#define P3_XS    0                                  // fp16 128*XSTR
#define P3_WS    (P3_XS + 128 * XSTR * 2)           // fp16 64*WSTR
#define P3_ACTB  0                                  // fp32 64*ASTR (overlaps)
#define P3_BAT   (64 * ASTR * 4)                    // fp32 64 (after act region)
#define P3_TOTB  (P3_BAT + 256)

__global__ __launch_bounds__(128, 4) void k_pass3(const int* __restrict__ mask,
                                                  const float* __restrict__ b2at,
                                                  float* __restrict__ out) {
    extern __shared__ __align__(16) char smc[];
    __half* Xs = reinterpret_cast<__half*>(smc + P3_XS);
    __half* Ws = reinterpret_cast<__half*>(smc + P3_WS);
    float* act = reinterpret_cast<float*>(smc + P3_ACTB);
    float* s_bat = reinterpret_cast<float*>(smc + P3_BAT);

    int t = threadIdx.x, b = blockIdx.y;
    int colbase = blockIdx.x * 128;
    int lane = t & 31, warp = t >> 5;
    int grp = lane >> 2, tig = lane & 3;
    int n0 = warp * 32;

    // ---- stage: v = relu(a*h1 + c) -> Xs[col][o] fp16; w2at; bias ----
    {
        const __half* gh1 = g_h1_buf + (size_t)b * 64 * MKn;
#pragma unroll
        for (int s = 0; s < 16; s++) {
            int id = t + 128 * s;
            int o = id >> 5, cq = id & 31;
            uint2 hv = __ldg(reinterpret_cast<const uint2*>(
                gh1 + (size_t)o * MKn + colbase + 4 * cq));
            float4 h = h4_to_f4(hv);
            float a  = c_gn2[b][o];
            float cc = c_gn2[b][64 + o];
            Xs[(4 * cq + 0) * XSTR + o] = __float2half(fmaxf(fmaf(a, h.x, cc), 0.f));
            Xs[(4 * cq + 1) * XSTR + o] = __float2half(fmaxf(fmaf(a, h.y, cc), 0.f));
            Xs[(4 * cq + 2) * XSTR + o] = __float2half(fmaxf(fmaf(a, h.z, cc), 0.f));
            Xs[(4 * cq + 3) * XSTR + o] = __float2half(fmaxf(fmaf(a, h.w, cc), 0.f));
        }
        stage_w(g_w2at_h, Ws, t);
        if (t < 64) s_bat[t] = b2at[t];
    }
    __syncthreads();

    // ---- GEMM: attn = w2at * v + b2at (tensor) ----
    float c3[4][4][4];
    mma_gemm64(Ws, Xs, s_bat, n0, grp, tig, c3);

    // mask loads (per col pair, reused across m-tiles)
    int2 m2[4];
    {
        const int* mrow = mask + (size_t)b * MKn + colbase;
#pragma unroll
        for (int nt = 0; nt < 4; nt++)
            m2[nt] = *reinterpret_cast<const int2*>(mrow + n0 + 8 * nt + tig * 2);
    }
    __syncthreads();   // all GEMM reads of Xs/Ws done before act overwrite

    // ---- masked repack -> act fp32 [o][col] ----
#pragma unroll
    for (int mt = 0; mt < 4; mt++) {
        int r0 = 16 * mt + grp, r1 = r0 + 8;
#pragma unroll
        for (int nt = 0; nt < 4; nt++) {
            int colL = n0 + 8 * nt + tig * 2;
            bool mb0 = m2[nt].x != 0, mb1 = m2[nt].y != 0;
            act[r0 * ASTR + colL]     = mb0 ? c3[mt][nt][0] : -FLT_MAX;
            act[r0 * ASTR + colL + 1] = mb1 ? c3[mt][nt][1] : -FLT_MAX;
            act[r1 * ASTR + colL]     = mb0 ? c3[mt][nt][2] : -FLT_MAX;
            act[r1 * ASTR + colL + 1] = mb1 ? c3[mt][nt][3] : -FLT_MAX;
        }
    }
    __syncthreads();

    // ---- per-(m,o) softmax units: 16 contiguous cols, no shuffles ----
    const __half* gpe = g_pe_buf + (size_t)b * 64 * MKn;
    int mbase = colbase >> 4;
#pragma unroll
    for (int r = 0; r < 4; r++) {
        int unit = r * 128 + t;    // 0..511
        int o = unit >> 3, ml = unit & 7;
        const float* ap = &act[o * ASTR + 16 * ml];
        float av[16];
#pragma unroll
        for (int j = 0; j < 4; j++) {
            float4 x = *reinterpret_cast<const float4*>(ap + 4 * j);
            av[4 * j] = x.x; av[4 * j + 1] = x.y; av[4 * j + 2] = x.z; av[4 * j + 3] = x.w;
        }
        float mx = av[0];
#pragma unroll
        for (int j = 1; j < 16; j++) mx = fmaxf(mx, av[j]);
        float s = 0.f;
#pragma unroll
        for (int j = 0; j < 16; j++) { av[j] = __expf(av[j] - mx); s += av[j]; }
        const __half* pp = gpe + (size_t)o * MKn + colbase + 16 * ml;
        float accum = 0.f;
#pragma unroll
        for (int j = 0; j < 4; j++) {
            float4 p = h4_to_f4(__ldg(reinterpret_cast<const uint2*>(pp + 4 * j)));
            accum = fmaf(p.x, av[4 * j], accum);
            accum = fmaf(p.y, av[4 * j + 1], accum);
            accum = fmaf(p.z, av[4 * j + 2], accum);
            accum = fmaf(p.w, av[4 * j + 3], accum);
        }
        out[((size_t)b * 64 + o) * Mn + mbase + ml] = accum * __fdividef(1.f, s);
    }
}

// ---------------- launch ----------------
extern "C" void kernel_launch(void* const* d_in, const int* in_sizes, int n_in,
                              void* d_out, int out_size) {
    const float* q_xyzs  = (const float*)d_in[0];
    const float* k_xyzs  = (const float*)d_in[1];
    const int*   knn_idx = (const int*)d_in[2];
    const int*   mask    = (const int*)d_in[3];
    const float* pe_w1   = (const float*)d_in[4];
    const float* pe_b1   = (const float*)d_in[5];
    const float* pe_g    = (const float*)d_in[6];
    const float* pe_be   = (const float*)d_in[7];
    const float* pe_w2   = (const float*)d_in[8];
    const float* pe_b2   = (const float*)d_in[9];
    const float* at_w1   = (const float*)d_in[10];
    const float* at_b1   = (const float*)d_in[11];
    const float* at_g    = (const float*)d_in[12];
    const float* at_be   = (const float*)d_in[13];
    const float* at_w2   = (const float*)d_in[14];
    const float* at_b2   = (const float*)d_in[15];
    float* out = (float*)d_out;

    static int smem_set = 0;
    if (!smem_set) {
        cudaFuncSetAttribute(k_pass2, cudaFuncAttributeMaxDynamicSharedMemorySize,
                             P2_TOTB);
        cudaFuncSetAttribute(k_pass3, cudaFuncAttributeMaxDynamicSharedMemorySize,
                             P3_TOTB);
        smem_set = 1;
    }

    k_prep<<<64, 64>>>(pe_w2, at_w1, at_w2);

    dim3 gcol(MKn / 128, Bn);
    k_pass1<<<gcol, 128>>>(q_xyzs, k_xyzs, knn_idx);
    k_fin1<<<1, 64>>>(pe_w1, pe_b1, pe_g, pe_be);

    k_pass2<<<gcol, 128, P2_TOTB>>>(q_xyzs, k_xyzs, knn_idx, pe_b2, at_b1);
    k_fin2<<<1, 64>>>(at_g, at_be);

    void* pg;
    cudaGetSymbolAddress(&pg, g_gn2d);
    cudaMemcpyToSymbolAsync(c_gn2, pg, Bn * 128 * 4, 0, cudaMemcpyDeviceToDevice, 0);

    k_pass3<<<gcol, 128, P3_TOTB>>>(mask, at_b2, out);
}

// round 12
// speedup vs baseline: 5.3801x; 1.1666x over previous
#include <cuda_runtime.h>
#include <cuda_fp16.h>
#include <math.h>
#include <float.h>

#define Bn   2
#define Mn   25000
#define Nn   100000
#define NGn  8
#define CPGn 8
#define GN_EPS 1e-5f
#define MKn  (Mn * 16)          // 400000 columns per batch

#define XSTR 72                 // fp16 act stride (halves), rows 16B-aligned
#define WSTR 72                 // fp16 weight stride
#define VSTR 136                // fp16 v stride in pass3 [o][col]
#define ASTR 136                // fp32 attn stride in pass3 [o][col]

typedef unsigned long long u64;

// ---------------- device scratch ----------------
__device__ double g_m1[Bn][14];
__device__ double g_s2[Bn][NGn][2];
__device__ __align__(16) float g_w1pe_f[Bn][256];   // folded conv1_pe [b][c][o]
__device__ __align__(16) float g_b1pe_f[Bn][64];
__device__ __align__(16) float g_gn2d[Bn][128];     // a2[64] | c2[64]
__device__ __align__(16) __half g_w2pe_h[4096];     // [o][k] fp16
__device__ __align__(16) __half g_w1at_h[4096];     // [o][k] fp16
__device__ __align__(16) __half g_w2at_h[4096];     // [o][k] fp16
// activation scratch [b][o][MKn] fp16 (round-10 layout)
__device__ __align__(16) __half g_pe_buf[(size_t)Bn * 64 * MKn];
__device__ __align__(16) __half g_h1_buf[(size_t)Bn * 64 * MKn];

// ---------------- scalar helpers ----------------
__device__ __forceinline__ u64 fma2(u64 a, u64 b, u64 c) {
    u64 d;
    asm("fma.rn.f32x2 %0, %1, %2, %3;" : "=l"(d) : "l"(a), "l"(b), "l"(c));
    return d;
}
__device__ __forceinline__ u64 pack2(float v) {
    u64 r;
    asm("mov.b64 %0, {%1, %1};" : "=l"(r) : "f"(v));
    return r;
}
__device__ __forceinline__ void unpack2(u64 v, float& lo, float& hi) {
    asm("mov.b64 {%0, %1}, %2;" : "=f"(lo), "=f"(hi) : "l"(v));
}
__device__ __forceinline__ float4 h4_to_f4(uint2 u) {
    __half2 a = *reinterpret_cast<__half2*>(&u.x);
    __half2 b = *reinterpret_cast<__half2*>(&u.y);
    float2 fa = __half22float2(a), fb = __half22float2(b);
    return make_float4(fa.x, fa.y, fb.x, fb.y);
}
__device__ __forceinline__ unsigned h2u(float a, float b) {
    __half2 h = __floats2half2_rn(a, b);
    return *reinterpret_cast<unsigned*>(&h);
}

// ---------------- tensor primitives ----------------
__device__ __forceinline__ void mma16816(float* c, const unsigned* a, const unsigned* b) {
    asm volatile(
        "mma.sync.aligned.m16n8k16.row.col.f32.f16.f16.f32 "
        "{%0,%1,%2,%3}, {%4,%5,%6,%7}, {%8,%9}, {%0,%1,%2,%3};\n"
        : "+f"(c[0]), "+f"(c[1]), "+f"(c[2]), "+f"(c[3])
        : "r"(a[0]), "r"(a[1]), "r"(a[2]), "r"(a[3]), "r"(b[0]), "r"(b[1]));
}
__device__ __forceinline__ void ldsm4(unsigned* r, unsigned addr) {
    asm volatile("ldmatrix.sync.aligned.m8n8.x4.shared.b16 {%0,%1,%2,%3}, [%4];"
        : "=r"(r[0]), "=r"(r[1]), "=r"(r[2]), "=r"(r[3]) : "r"(addr));
}
__device__ __forceinline__ void ldsm4t(unsigned* r, unsigned addr) {
    asm volatile("ldmatrix.sync.aligned.m8n8.x4.trans.shared.b16 {%0,%1,%2,%3}, [%4];"
        : "=r"(r[0]), "=r"(r[1]), "=r"(r[2]), "=r"(r[3]) : "r"(addr));
}
__device__ __forceinline__ unsigned movm(unsigned a) {
    unsigned d;
    asm volatile("movmatrix.sync.aligned.m8n8.trans.b16 %0, %1;" : "=r"(d) : "r"(a));
    return d;
}

// ---------------- misc helpers ----------------
__device__ __forceinline__ void compute_lp(const float* __restrict__ q,
                                           const float* __restrict__ kx,
                                           const int*   __restrict__ idx,
                                           int b, int c, float lp[4]) {
    int m  = c >> 4;
    int id = idx[b * MKn + c];
    float qx = q[(b * 3 + 0) * Mn + m];
    float qy = q[(b * 3 + 1) * Mn + m];
    float qz = q[(b * 3 + 2) * Mn + m];
    float px = kx[(b * 3 + 0) * Nn + id];
    float py = kx[(b * 3 + 1) * Nn + id];
    float pz = kx[(b * 3 + 2) * Nn + id];
    float ox = px - qx, oy = py - qy, oz = pz - qz;
    float d  = sqrtf(ox * ox + oy * oy + oz * oz);
    float r  = 1.0f / fmaxf(d, 1e-12f);
    lp[0] = ox * r; lp[1] = oy * r; lp[2] = oz * r; lp[3] = d;
}

// stage a 64x64 fp16 [o][k] weight into smem [o][WSTR]
__device__ __forceinline__ void stage_w(const __half* __restrict__ gsrc,
                                        __half* Ws, int t) {
#pragma unroll
    for (int id = t; id < 512; id += 128) {
        int row = id >> 3, c = id & 7;
        uint4 v = *reinterpret_cast<const uint4*>(gsrc + row * 64 + c * 8);
        *reinterpret_cast<uint4*>(Ws + row * WSTR + c * 8) = v;
    }
}

// ---------------- kernels ----------------
__global__ void k_prep(const float* __restrict__ w2pe,
                       const float* __restrict__ w1at,
                       const float* __restrict__ w2at) {
    int i = blockIdx.x;   // output channel
    int j = threadIdx.x;  // input channel
    g_w2pe_h[i * 64 + j] = __float2half(w2pe[i * 64 + j]);
    g_w1at_h[i * 64 + j] = __float2half(w1at[i * 64 + j]);
    g_w2at_h[i * 64 + j] = __float2half(w2at[i * 64 + j]);
    if (i == 0) {
        if (j < Bn * NGn * 2) ((double*)g_s2)[j] = 0.0;
        if (j < Bn * 14)      ((double*)g_m1)[j] = 0.0;
    }
}

__global__ __launch_bounds__(128) void k_pass1(const float* __restrict__ q,
                                               const float* __restrict__ kx,
                                               const int*   __restrict__ idx) {
    __shared__ float s_red[14];
    int t = threadIdx.x, b = blockIdx.y;
    if (t < 14) s_red[t] = 0.f;
    __syncthreads();
    int col = blockIdx.x * 128 + t;
    float lp[4];
    compute_lp(q, kx, idx, b, col, lp);

    float v[14];
    v[0] = lp[0]; v[1] = lp[1]; v[2] = lp[2]; v[3] = lp[3];
    {
        int n = 4;
#pragma unroll
        for (int c = 0; c < 4; c++)
#pragma unroll
            for (int d = c; d < 4; d++) v[n++] = lp[c] * lp[d];
    }
#pragma unroll
    for (int i = 0; i < 14; i++) {
        for (int off = 16; off; off >>= 1)
            v[i] += __shfl_down_sync(0xffffffffu, v[i], off);
        if ((t & 31) == 0) atomicAdd(&s_red[i], v[i]);
    }
    __syncthreads();
    if (t < 14) atomicAdd(&g_m1[b][t], (double)s_red[t]);
}

__global__ void k_fin1(const float* __restrict__ w1, const float* __restrict__ b1,
                       const float* __restrict__ gam, const float* __restrict__ bet) {
    __shared__ double gs[8], gq[8];
    int o = threadIdx.x;  // 64 threads
    double n = (double)CPGn * (double)MKn;
    for (int b = 0; b < Bn; b++) {
        if (o < 8) { gs[o] = 0.0; gq[o] = 0.0; }
        __syncthreads();
        double m[14];
#pragma unroll
        for (int i = 0; i < 14; i++) m[i] = g_m1[b][i];
        double M2[4][4];
        {
            int idx5 = 4;
            for (int c = 0; c < 4; c++)
                for (int d = c; d < 4; d++) {
                    M2[c][d] = m[idx5]; M2[d][c] = m[idx5]; idx5++;
                }
        }
        double w[4];
#pragma unroll
        for (int c = 0; c < 4; c++) w[c] = (double)w1[o * 4 + c];
        double bo = (double)b1[o];
        double dot = w[0] * m[0] + w[1] * m[1] + w[2] * m[2] + w[3] * m[3];
        double sum_o = dot + (double)MKn * bo;
        double sq_o = 0.0;
#pragma unroll
        for (int c = 0; c < 4; c++)
#pragma unroll
            for (int d = 0; d < 4; d++) sq_o += w[c] * w[d] * M2[c][d];
        sq_o += 2.0 * bo * dot + (double)MKn * bo * bo;
        atomicAdd(&gs[o >> 3], sum_o);
        atomicAdd(&gq[o >> 3], sq_o);
        __syncthreads();
        int g = o >> 3;
        double mean = gs[g] / n;
        double var  = gq[g] / n - mean * mean;
        float rstd  = (float)(1.0 / sqrt(var + (double)GN_EPS));
        float a  = gam[o] * rstd;
        float cc = bet[o] - (float)mean * a;
        g_b1pe_f[b][o] = fmaf(a, b1[o], cc);
        for (int c = 0; c < 4; c++) g_w1pe_f[b][c * 64 + o] = a * w1[o * 4 + c];
        __syncthreads();
    }
}

// ---- pass2 smem (bytes) ----
#define P2_XS    0                       // fp16 [128][XSTR]
#define P2_WS1   18432
#define P2_WS2   27648
#define P2_W1PE  36864                   // fp32 256
#define P2_B1PE  37888
#define P2_B2PE  38144
#define P2_B1AT  38400
#define P2_RED   38656
#define P2_TOTB  38720

__global__ __launch_bounds__(128, 4) void k_pass2(const float* __restrict__ q,
                                                  const float* __restrict__ kx,
                                                  const int*   __restrict__ idx,
                                                  const float* __restrict__ b2pe,
                                                  const float* __restrict__ b1at) {
    extern __shared__ __align__(16) char smc[];
    __half* Xs  = reinterpret_cast<__half*>(smc + P2_XS);
    __half* Ws1 = reinterpret_cast<__half*>(smc + P2_WS1);
    __half* Ws2 = reinterpret_cast<__half*>(smc + P2_WS2);
    float* s_w1pe = reinterpret_cast<float*>(smc + P2_W1PE);
    float* s_b1pe = reinterpret_cast<float*>(smc + P2_B1PE);
    float* s_b2pe = reinterpret_cast<float*>(smc + P2_B2PE);
    float* s_b1at = reinterpret_cast<float*>(smc + P2_B1AT);
    float* s_red  = reinterpret_cast<float*>(smc + P2_RED);

    int t = threadIdx.x, b = blockIdx.y;
    int colbase = blockIdx.x * 128;
    int lane = t & 31, warp = t >> 5;
    int grp = lane >> 2, tig = lane & 3;
    int n0 = warp * 32;

    stage_w(g_w2pe_h, Ws1, t);
    stage_w(g_w1at_h, Ws2, t);
    s_w1pe[t] = g_w1pe_f[b][t];
    s_w1pe[t + 128] = g_w1pe_f[b][t + 128];
    if (t < 64) {
        s_b1pe[t] = g_b1pe_f[b][t];
        s_b2pe[t] = b2pe[t];
        s_b1at[t] = b1at[t];
    }
    if (t < 16) s_red[t] = 0.f;
    __syncthreads();

    // ---- phase A: u = relu(conv1_pe'(lp)) -> Xs[col=t][k] ----
    {
        int col = colbase + t;
        float lp[4];
        compute_lp(q, kx, idx, b, col, lp);
        u64 a1[32];
#pragma unroll
        for (int p = 0; p < 32; p++)
            a1[p] = *reinterpret_cast<const u64*>(&s_b1pe[2 * p]);
#pragma unroll
        for (int c = 0; c < 4; c++) {
            u64 xb = pack2(lp[c]);
#pragma unroll
            for (int p = 0; p < 32; p++) {
                u64 w = *reinterpret_cast<const u64*>(&s_w1pe[c * 64 + 2 * p]);
                a1[p] = fma2(w, xb, a1[p]);
            }
        }
        unsigned hh[32];
#pragma unroll
        for (int p = 0; p < 32; p++) {
            float lo, hi;
            unpack2(a1[p], lo, hi);
            hh[p] = h2u(fmaxf(lo, 0.f), fmaxf(hi, 0.f));
        }
#pragma unroll
        for (int c = 0; c < 8; c++)
            *reinterpret_cast<uint4*>(Xs + t * XSTR + 8 * c) =
                make_uint4(hh[4*c], hh[4*c+1], hh[4*c+2], hh[4*c+3]);
    }
    __syncwarp();

    unsigned xsb  = (unsigned)__cvta_generic_to_shared(Xs + (size_t)n0 * XSTR);
    unsigned ws1b = (unsigned)__cvta_generic_to_shared(Ws1);
    unsigned ws2b = (unsigned)__cvta_generic_to_shared(Ws2);
    int arow = lane & 15, ahalf = lane >> 4;
    int brow = (lane & 7) + ((lane >> 4) & 1) * 8;
    int bk   = ((lane >> 3) & 1) * 8;

    // ---- GEMM1: C1[o_pe rows][col cols] = w2pe * u + b2pe ----
    float C1[4][4][4];
#pragma unroll
    for (int mt = 0; mt < 4; mt++) {
        float b0 = s_b2pe[16 * mt + grp], b1 = s_b2pe[16 * mt + 8 + grp];
#pragma unroll
        for (int nt = 0; nt < 4; nt++) {
            C1[mt][nt][0] = b0; C1[mt][nt][1] = b0;
            C1[mt][nt][2] = b1; C1[mt][nt][3] = b1;
        }
    }
#pragma unroll
    for (int kt = 0; kt < 4; kt++) {
        unsigned Af[4][4];
#pragma unroll
        for (int mt = 0; mt < 4; mt++)
            ldsm4(Af[mt], ws1b + 2 * ((16 * mt + arow) * WSTR + 16 * kt + 8 * ahalf));
#pragma unroll
        for (int ntp = 0; ntp < 2; ntp++) {
            unsigned Bf[4];
            ldsm4(Bf, xsb + 2 * ((16 * ntp + brow) * XSTR + 16 * kt + bk));
#pragma unroll
            for (int mt = 0; mt < 4; mt++) {
                mma16816(C1[mt][2 * ntp],     Af[mt], Bf);
                mma16816(C1[mt][2 * ntp + 1], Af[mt], Bf + 2);
            }
        }
    }

    // ---- pe store global [o][MKn] + movmatrix chain -> GEMM2 B-fragments ----
    unsigned Bc[4][4][2];
    {
        __half* gpe = g_pe_buf + (size_t)b * 64 * MKn + colbase;
#pragma unroll
        for (int mt = 0; mt < 4; mt++) {
            int r0 = 16 * mt + grp, r1 = r0 + 8;
#pragma unroll
            for (int nt = 0; nt < 4; nt++) {
                int colL = n0 + 8 * nt + 2 * tig;
                unsigned p01 = h2u(C1[mt][nt][0], C1[mt][nt][1]);
                unsigned p23 = h2u(C1[mt][nt][2], C1[mt][nt][3]);
                *reinterpret_cast<unsigned*>(gpe + (size_t)r0 * MKn + colL) = p01;
                *reinterpret_cast<unsigned*>(gpe + (size_t)r1 * MKn + colL) = p23;
                Bc[mt][nt][0] = movm(p01);   // b0: k = o_pe 16mt..+7
                Bc[mt][nt][1] = movm(p23);   // b1: k = o_pe 16mt+8..+15
            }
        }
    }

    // ---- GEMM2: C2[o_h1 rows][col cols] = w1at * pe + b1at ----
    float C2[4][4][4];
#pragma unroll
    for (int mt = 0; mt < 4; mt++) {
        float b0 = s_b1at[16 * mt + grp], b1 = s_b1at[16 * mt + 8 + grp];
#pragma unroll
        for (int nt = 0; nt < 4; nt++) {
            C2[mt][nt][0] = b0; C2[mt][nt][1] = b0;
            C2[mt][nt][2] = b1; C2[mt][nt][3] = b1;
        }
    }
#pragma unroll
    for (int kt = 0; kt < 4; kt++) {
        unsigned Af[4][4];
#pragma unroll
        for (int mt = 0; mt < 4; mt++)
            ldsm4(Af[mt], ws2b + 2 * ((16 * mt + arow) * WSTR + 16 * kt + 8 * ahalf));
#pragma unroll
        for (int mt = 0; mt < 4; mt++)
#pragma unroll
            for (int nt = 0; nt < 4; nt++)
                mma16816(C2[mt][nt], Af[mt], Bc[kt][nt]);
    }

    // ---- h1 store [o][MKn] + GN2 stats ----
    {
        __half* gh1 = g_h1_buf + (size_t)b * 64 * MKn + colbase;
        float gs[8], gq[8];
#pragma unroll
        for (int g = 0; g < 8; g++) { gs[g] = 0.f; gq[g] = 0.f; }
#pragma unroll
        for (int mt = 0; mt < 4; mt++) {
            int r0 = 16 * mt + grp, r1 = r0 + 8;
#pragma unroll
            for (int nt = 0; nt < 4; nt++) {
                int colL = n0 + 8 * nt + 2 * tig;
                float v0 = C2[mt][nt][0], v1 = C2[mt][nt][1];
                float v2 = C2[mt][nt][2], v3 = C2[mt][nt][3];
                *reinterpret_cast<unsigned*>(gh1 + (size_t)r0 * MKn + colL) = h2u(v0, v1);
                *reinterpret_cast<unsigned*>(gh1 + (size_t)r1 * MKn + colL) = h2u(v2, v3);
                gs[2 * mt]     += v0 + v1;
                gq[2 * mt]     = fmaf(v0, v0, fmaf(v1, v1, gq[2 * mt]));
                gs[2 * mt + 1] += v2 + v3;
                gq[2 * mt + 1] = fmaf(v2, v2, fmaf(v3, v3, gq[2 * mt + 1]));
            }
        }
        float r[16];
#pragma unroll
        for (int g = 0; g < 8; g++) { r[g] = gs[g]; r[8 + g] = gq[g]; }
#pragma unroll
        for (int i = 0; i < 16; i++)
            for (int off = 16; off; off >>= 1)
                r[i] += __shfl_down_sync(0xffffffffu, r[i], off);
        if (lane == 0) {
#pragma unroll
            for (int i = 0; i < 16; i++) atomicAdd(&s_red[i], r[i]);
        }
    }
    __syncthreads();
    if (t < 16) atomicAdd(&g_s2[b][t & 7][t >> 3], (double)s_red[t]);
}

__global__ void k_fin2(const float* __restrict__ gam, const float* __restrict__ bet) {
    int o = threadIdx.x;  // 64 threads
    double n = (double)CPGn * (double)MKn;
    for (int b = 0; b < Bn; b++) {
        int g = o >> 3;
        double s = g_s2[b][g][0], sq = g_s2[b][g][1];
        double mean = s / n;
        double var  = sq / n - mean * mean;
        float rstd  = (float)(1.0 / sqrt(var + (double)GN_EPS));
        float a  = gam[o] * rstd;
        float cc = bet[o] - (float)mean * a;
        g_gn2d[b][o]      = a;
        g_gn2d[b][64 + o] = cc;
    }
}

// ---- pass3 smem (bytes): act fp32 overlaps Vs+Ws (dead after GEMM) ----
#define P3_VS    0                       // fp16 [64][VSTR]   (17408 B)
#define P3_WS    17408                   // fp16 [64][WSTR]   (9216 B)
#define P3_ACT   0                       // fp32 [64][ASTR]   (34816 B, overlap)
#define P3_BAT   34816                   // fp32 64
#define P3_TOTB  35072

__global__ __launch_bounds__(128, 4) void k_pass3(const int* __restrict__ mask,
                                                  const float* __restrict__ b2at,
                                                  float* __restrict__ out) {
    extern __shared__ __align__(16) char smc[];
    __half* Vs   = reinterpret_cast<__half*>(smc + P3_VS);
    __half* Ws   = reinterpret_cast<__half*>(smc + P3_WS);
    float* act   = reinterpret_cast<float*>(smc + P3_ACT);
    float* s_bat = reinterpret_cast<float*>(smc + P3_BAT);

    int t = threadIdx.x, b = blockIdx.y;
    int colbase = blockIdx.x * 128;
    int lane = t & 31, warp = t >> 5;
    int grp = lane >> 2, tig = lane & 3;
    int n0 = warp * 32;

    stage_w(g_w2at_h, Ws, t);
    if (t < 64) s_bat[t] = b2at[t];
    // v = relu(a*h1 + c) -> Vs[o][col] (coalesced uint2 stores)
    {
        const __half* gh1 = g_h1_buf + (size_t)b * 64 * MKn;
#pragma unroll
        for (int s = 0; s < 16; s++) {
            int id = t + 128 * s;        // 0..2047 -> 64 o x 32 col-quads
            int o = id >> 5, cq = id & 31;
            float a  = g_gn2d[b][o];
            float cc = g_gn2d[b][64 + o];
            uint2 hv = __ldg(reinterpret_cast<const uint2*>(
                gh1 + (size_t)o * MKn + colbase + 4 * cq));
            float4 h = h4_to_f4(hv);
            uint2 vv;
            vv.x = h2u(fmaxf(fmaf(a, h.x, cc), 0.f), fmaxf(fmaf(a, h.y, cc), 0.f));
            vv.y = h2u(fmaxf(fmaf(a, h.z, cc), 0.f), fmaxf(fmaf(a, h.w, cc), 0.f));
            *reinterpret_cast<uint2*>(Vs + o * VSTR + 4 * cq) = vv;
        }
    }
    __syncthreads();

    unsigned vsb = (unsigned)__cvta_generic_to_shared(Vs);
    unsigned wsb = (unsigned)__cvta_generic_to_shared(Ws);
    int arow = lane & 15, ahalf = lane >> 4;
    int orow = (lane & 7) + ((lane >> 3) & 1) * 8;
    int ocol = ((lane >> 4) & 1) * 8;

    // ---- GEMM3: C3[o rows][col cols] = w2at * v + b2at ----
    float C3[4][4][4];
#pragma unroll
    for (int mt = 0; mt < 4; mt++) {
        float b0 = s_bat[16 * mt + grp], b1 = s_bat[16 * mt + 8 + grp];
#pragma unroll
        for (int nt = 0; nt < 4; nt++) {
            C3[mt][nt][0] = b0; C3[mt][nt][1] = b0;
            C3[mt][nt][2] = b1; C3[mt][nt][3] = b1;
        }
    }
#pragma unroll
    for (int kt = 0; kt < 4; kt++) {
        unsigned Af[4][4];
#pragma unroll
        for (int mt = 0; mt < 4; mt++)
            ldsm4(Af[mt], wsb + 2 * ((16 * mt + arow) * WSTR + 16 * kt + 8 * ahalf));
#pragma unroll
        for (int ntp = 0; ntp < 2; ntp++) {
            unsigned Bf[4];
            ldsm4t(Bf, vsb + 2 * ((16 * kt + orow) * VSTR + n0 + 16 * ntp + ocol));
#pragma unroll
            for (int mt = 0; mt < 4; mt++) {
                mma16816(C3[mt][2 * ntp],     Af[mt], Bf);
                mma16816(C3[mt][2 * ntp + 1], Af[mt], Bf + 2);
            }
        }
    }

    // mask per col-pair (reused across mt)
    int2 mv[4];
    {
        const int* mrow = mask + (size_t)b * MKn + colbase;
#pragma unroll
        for (int nt = 0; nt < 4; nt++)
            mv[nt] = *reinterpret_cast<const int2*>(mrow + n0 + 8 * nt + 2 * tig);
    }
    __syncthreads();   // Vs/Ws reads done before act overwrite

    // ---- masked repack -> act fp32 [o][col] ----
#pragma unroll
    for (int mt = 0; mt < 4; mt++) {
        int r0 = 16 * mt + grp, r1 = r0 + 8;
#pragma unroll
        for (int nt = 0; nt < 4; nt++) {
            int colL = n0 + 8 * nt + 2 * tig;
            bool m0 = mv[nt].x != 0, m1 = mv[nt].y != 0;
            act[r0 * ASTR + colL]     = m0 ? C3[mt][nt][0] : -FLT_MAX;
            act[r0 * ASTR + colL + 1] = m1 ? C3[mt][nt][1] : -FLT_MAX;
            act[r1 * ASTR + colL]     = m0 ? C3[mt][nt][2] : -FLT_MAX;
            act[r1 * ASTR + colL + 1] = m1 ? C3[mt][nt][3] : -FLT_MAX;
        }
    }
    __syncthreads();

    // ---- per-(m,o) softmax units: 16 contiguous cols, no shuffles ----
    const __half* gpe = g_pe_buf + (size_t)b * 64 * MKn;
    int mbase = colbase >> 4;      // 8 m per tile
#pragma unroll
    for (int r = 0; r < 4; r++) {
        int unit = r * 128 + t;    // 0..511
        int o = unit >> 3, ml = unit & 7;
        const float* ap = &act[o * ASTR + 16 * ml];
        float av[16];
#pragma unroll
        for (int j = 0; j < 4; j++) {
            float4 x = *reinterpret_cast<const float4*>(ap + 4 * j);
            av[4 * j] = x.x; av[4 * j + 1] = x.y; av[4 * j + 2] = x.z; av[4 * j + 3] = x.w;
        }
        float mx = av[0];
#pragma unroll
        for (int j = 1; j < 16; j++) mx = fmaxf(mx, av[j]);
        float s = 0.f;
#pragma unroll
        for (int j = 0; j < 16; j++) { av[j] = __expf(av[j] - mx); s += av[j]; }
        const __half* pp = gpe + (size_t)o * MKn + colbase + 16 * ml;
        float accum = 0.f;
#pragma unroll
        for (int j = 0; j < 4; j++) {
            float4 p = h4_to_f4(__ldg(reinterpret_cast<const uint2*>(pp + 4 * j)));
            accum = fmaf(p.x, av[4 * j], accum);
            accum = fmaf(p.y, av[4 * j + 1], accum);
            accum = fmaf(p.z, av[4 * j + 2], accum);
            accum = fmaf(p.w, av[4 * j + 3], accum);
        }
        out[((size_t)b * 64 + o) * Mn + mbase + ml] = accum * __fdividef(1.f, s);
    }
}

// ---------------- launch ----------------
extern "C" void kernel_launch(void* const* d_in, const int* in_sizes, int n_in,
                              void* d_out, int out_size) {
    const float* q_xyzs  = (const float*)d_in[0];
    const float* k_xyzs  = (const float*)d_in[1];
    const int*   knn_idx = (const int*)d_in[2];
    const int*   mask    = (const int*)d_in[3];
    const float* pe_w1   = (const float*)d_in[4];
    const float* pe_b1   = (const float*)d_in[5];
    const float* pe_g    = (const float*)d_in[6];
    const float* pe_be   = (const float*)d_in[7];
    const float* pe_w2   = (const float*)d_in[8];
    const float* pe_b2   = (const float*)d_in[9];
    const float* at_w1   = (const float*)d_in[10];
    const float* at_b1   = (const float*)d_in[11];
    const float* at_g    = (const float*)d_in[12];
    const float* at_be   = (const float*)d_in[13];
    const float* at_w2   = (const float*)d_in[14];
    const float* at_b2   = (const float*)d_in[15];
    float* out = (float*)d_out;

    static int smem_set = 0;
    if (!smem_set) {
        cudaFuncSetAttribute(k_pass2, cudaFuncAttributeMaxDynamicSharedMemorySize,
                             P2_TOTB);
        cudaFuncSetAttribute(k_pass3, cudaFuncAttributeMaxDynamicSharedMemorySize,
                             P3_TOTB);
        smem_set = 1;
    }

    k_prep<<<64, 64>>>(pe_w2, at_w1, at_w2);

    dim3 gcol(MKn / 128, Bn);
    k_pass1<<<gcol, 128>>>(q_xyzs, k_xyzs, knn_idx);
    k_fin1<<<1, 64>>>(pe_w1, pe_b1, pe_g, pe_be);

    k_pass2<<<gcol, 128, P2_TOTB>>>(q_xyzs, k_xyzs, knn_idx, pe_b2, at_b1);
    k_fin2<<<1, 64>>>(at_g, at_be);

    k_pass3<<<gcol, 128, P3_TOTB>>>(mask, at_b2, out);
}

// round 13
// speedup vs baseline: 6.0951x; 1.1329x over previous
#include <cuda_runtime.h>
#include <cuda_fp16.h>
#include <math.h>
#include <float.h>

#define Bn   2
#define Mn   25000
#define Nn   100000
#define NGn  8
#define CPGn 8
#define GN_EPS 1e-5f
#define MKn  (Mn * 16)          // 400000 columns per batch

#define XSTR 72                 // fp16 act stride (halves), rows 16B-aligned
#define WSTR 72                 // fp16 weight stride
#define VSTR 136                // fp16 pe stride in pass3 [o][col]
#define ASTRH 136               // fp16 attn stride in pass3 [o][col]

typedef unsigned long long u64;

// ---------------- device scratch ----------------
__device__ double g_m1[Bn][14];
__device__ double g_s2[Bn][NGn][2];
__device__ __align__(16) float g_w1pe_f[Bn][256];   // folded conv1_pe [b][c][o]
__device__ __align__(16) float g_b1pe_f[Bn][64];
__device__ __align__(16) float g_gn2d[Bn][128];     // a2[64] | c2[64]
__device__ __align__(16) __half g_w2pe_h[4096];     // [o][k] fp16
__device__ __align__(16) __half g_w1at_h[4096];     // [o][k] fp16
__device__ __align__(16) __half g_w2at_h[4096];     // [o][k] fp16
// activation scratch [b][o][MKn] fp16 (pe only; h1 recomputed in pass3)
__device__ __align__(16) __half g_pe_buf[(size_t)Bn * 64 * MKn];

// ---------------- scalar helpers ----------------
__device__ __forceinline__ u64 fma2(u64 a, u64 b, u64 c) {
    u64 d;
    asm("fma.rn.f32x2 %0, %1, %2, %3;" : "=l"(d) : "l"(a), "l"(b), "l"(c));
    return d;
}
__device__ __forceinline__ u64 pack2(float v) {
    u64 r;
    asm("mov.b64 %0, {%1, %1};" : "=l"(r) : "f"(v));
    return r;
}
__device__ __forceinline__ void unpack2(u64 v, float& lo, float& hi) {
    asm("mov.b64 {%0, %1}, %2;" : "=f"(lo), "=f"(hi) : "l"(v));
}
__device__ __forceinline__ float4 h4_to_f4(uint2 u) {
    __half2 a = *reinterpret_cast<__half2*>(&u.x);
    __half2 b = *reinterpret_cast<__half2*>(&u.y);
    float2 fa = __half22float2(a), fb = __half22float2(b);
    return make_float4(fa.x, fa.y, fb.x, fb.y);
}
__device__ __forceinline__ unsigned h2u(float a, float b) {
    __half2 h = __floats2half2_rn(a, b);
    return *reinterpret_cast<unsigned*>(&h);
}

// ---------------- tensor primitives ----------------
__device__ __forceinline__ void mma16816(float* c, const unsigned* a, const unsigned* b) {
    asm volatile(
        "mma.sync.aligned.m16n8k16.row.col.f32.f16.f16.f32 "
        "{%0,%1,%2,%3}, {%4,%5,%6,%7}, {%8,%9}, {%0,%1,%2,%3};\n"
        : "+f"(c[0]), "+f"(c[1]), "+f"(c[2]), "+f"(c[3])
        : "r"(a[0]), "r"(a[1]), "r"(a[2]), "r"(a[3]), "r"(b[0]), "r"(b[1]));
}
__device__ __forceinline__ void ldsm4(unsigned* r, unsigned addr) {
    asm volatile("ldmatrix.sync.aligned.m8n8.x4.shared.b16 {%0,%1,%2,%3}, [%4];"
        : "=r"(r[0]), "=r"(r[1]), "=r"(r[2]), "=r"(r[3]) : "r"(addr));
}
__device__ __forceinline__ void ldsm4t(unsigned* r, unsigned addr) {
    asm volatile("ldmatrix.sync.aligned.m8n8.x4.trans.shared.b16 {%0,%1,%2,%3}, [%4];"
        : "=r"(r[0]), "=r"(r[1]), "=r"(r[2]), "=r"(r[3]) : "r"(addr));
}
__device__ __forceinline__ unsigned movm(unsigned a) {
    unsigned d;
    asm volatile("movmatrix.sync.aligned.m8n8.trans.b16 %0, %1;" : "=r"(d) : "r"(a));
    return d;
}

// ---------------- misc helpers ----------------
__device__ __forceinline__ void compute_lp(const float* __restrict__ q,
                                           const float* __restrict__ kx,
                                           const int*   __restrict__ idx,
                                           int b, int c, float lp[4]) {
    int m  = c >> 4;
    int id = idx[b * MKn + c];
    float qx = q[(b * 3 + 0) * Mn + m];
    float qy = q[(b * 3 + 1) * Mn + m];
    float qz = q[(b * 3 + 2) * Mn + m];
    float px = kx[(b * 3 + 0) * Nn + id];
    float py = kx[(b * 3 + 1) * Nn + id];
    float pz = kx[(b * 3 + 2) * Nn + id];
    float ox = px - qx, oy = py - qy, oz = pz - qz;
    float d  = sqrtf(ox * ox + oy * oy + oz * oz);
    float r  = 1.0f / fmaxf(d, 1e-12f);
    lp[0] = ox * r; lp[1] = oy * r; lp[2] = oz * r; lp[3] = d;
}

// stage a 64x64 fp16 [o][k] weight into smem [o][WSTR]
__device__ __forceinline__ void stage_w(const __half* __restrict__ gsrc,
                                        __half* Ws, int t) {
#pragma unroll
    for (int id = t; id < 512; id += 128) {
        int row = id >> 3, c = id & 7;
        uint4 v = *reinterpret_cast<const uint4*>(gsrc + row * 64 + c * 8);
        *reinterpret_cast<uint4*>(Ws + row * WSTR + c * 8) = v;
    }
}

// ---------------- kernels ----------------
__global__ void k_prep(const float* __restrict__ w2pe,
                       const float* __restrict__ w1at,
                       const float* __restrict__ w2at) {
    int i = blockIdx.x;   // output channel
    int j = threadIdx.x;  // input channel
    g_w2pe_h[i * 64 + j] = __float2half(w2pe[i * 64 + j]);
    g_w1at_h[i * 64 + j] = __float2half(w1at[i * 64 + j]);
    g_w2at_h[i * 64 + j] = __float2half(w2at[i * 64 + j]);
    if (i == 0) {
        if (j < Bn * NGn * 2) ((double*)g_s2)[j] = 0.0;
        if (j < Bn * 14)      ((double*)g_m1)[j] = 0.0;
    }
}

__global__ __launch_bounds__(128) void k_pass1(const float* __restrict__ q,
                                               const float* __restrict__ kx,
                                               const int*   __restrict__ idx) {
    __shared__ float s_red[14];
    int t = threadIdx.x, b = blockIdx.y;
    if (t < 14) s_red[t] = 0.f;
    __syncthreads();
    int col = blockIdx.x * 128 + t;
    float lp[4];
    compute_lp(q, kx, idx, b, col, lp);

    float v[14];
    v[0] = lp[0]; v[1] = lp[1]; v[2] = lp[2]; v[3] = lp[3];
    {
        int n = 4;
#pragma unroll
        for (int c = 0; c < 4; c++)
#pragma unroll
            for (int d = c; d < 4; d++) v[n++] = lp[c] * lp[d];
    }
#pragma unroll
    for (int i = 0; i < 14; i++) {
        for (int off = 16; off; off >>= 1)
            v[i] += __shfl_down_sync(0xffffffffu, v[i], off);
        if ((t & 31) == 0) atomicAdd(&s_red[i], v[i]);
    }
    __syncthreads();
    if (t < 14) atomicAdd(&g_m1[b][t], (double)s_red[t]);
}

__global__ void k_fin1(const float* __restrict__ w1, const float* __restrict__ b1,
                       const float* __restrict__ gam, const float* __restrict__ bet) {
    __shared__ double gs[8], gq[8];
    int o = threadIdx.x;  // 64 threads
    double n = (double)CPGn * (double)MKn;
    for (int b = 0; b < Bn; b++) {
        if (o < 8) { gs[o] = 0.0; gq[o] = 0.0; }
        __syncthreads();
        double m[14];
#pragma unroll
        for (int i = 0; i < 14; i++) m[i] = g_m1[b][i];
        double M2[4][4];
        {
            int idx5 = 4;
            for (int c = 0; c < 4; c++)
                for (int d = c; d < 4; d++) {
                    M2[c][d] = m[idx5]; M2[d][c] = m[idx5]; idx5++;
                }
        }
        double w[4];
#pragma unroll
        for (int c = 0; c < 4; c++) w[c] = (double)w1[o * 4 + c];
        double bo = (double)b1[o];
        double dot = w[0] * m[0] + w[1] * m[1] + w[2] * m[2] + w[3] * m[3];
        double sum_o = dot + (double)MKn * bo;
        double sq_o = 0.0;
#pragma unroll
        for (int c = 0; c < 4; c++)
#pragma unroll
            for (int d = 0; d < 4; d++) sq_o += w[c] * w[d] * M2[c][d];
        sq_o += 2.0 * bo * dot + (double)MKn * bo * bo;
        atomicAdd(&gs[o >> 3], sum_o);
        atomicAdd(&gq[o >> 3], sq_o);
        __syncthreads();
        int g = o >> 3;
        double mean = gs[g] / n;
        double var  = gq[g] / n - mean * mean;
        float rstd  = (float)(1.0 / sqrt(var + (double)GN_EPS));
        float a  = gam[o] * rstd;
        float cc = bet[o] - (float)mean * a;
        g_b1pe_f[b][o] = fmaf(a, b1[o], cc);
        for (int c = 0; c < 4; c++) g_w1pe_f[b][c * 64 + o] = a * w1[o * 4 + c];
        __syncthreads();
    }
}

// ---- pass2 smem (bytes) ----
#define P2_XS    0                       // fp16 [128][XSTR]
#define P2_WS1   18432
#define P2_WS2   27648
#define P2_W1PE  36864                   // fp32 256
#define P2_B1PE  37888
#define P2_B2PE  38144
#define P2_B1AT  38400
#define P2_RED   38656
#define P2_TOTB  38720

__global__ __launch_bounds__(128, 4) void k_pass2(const float* __restrict__ q,
                                                  const float* __restrict__ kx,
                                                  const int*   __restrict__ idx,
                                                  const float* __restrict__ b2pe,
                                                  const float* __restrict__ b1at) {
    extern __shared__ __align__(16) char smc[];
    __half* Xs  = reinterpret_cast<__half*>(smc + P2_XS);
    __half* Ws1 = reinterpret_cast<__half*>(smc + P2_WS1);
    __half* Ws2 = reinterpret_cast<__half*>(smc + P2_WS2);
    float* s_w1pe = reinterpret_cast<float*>(smc + P2_W1PE);
    float* s_b1pe = reinterpret_cast<float*>(smc + P2_B1PE);
    float* s_b2pe = reinterpret_cast<float*>(smc + P2_B2PE);
    float* s_b1at = reinterpret_cast<float*>(smc + P2_B1AT);
    float* s_red  = reinterpret_cast<float*>(smc + P2_RED);

    int t = threadIdx.x, b = blockIdx.y;
    int colbase = blockIdx.x * 128;
    int lane = t & 31, warp = t >> 5;
    int grp = lane >> 2, tig = lane & 3;
    int n0 = warp * 32;

    stage_w(g_w2pe_h, Ws1, t);
    stage_w(g_w1at_h, Ws2, t);
    s_w1pe[t] = g_w1pe_f[b][t];
    s_w1pe[t + 128] = g_w1pe_f[b][t + 128];
    if (t < 64) {
        s_b1pe[t] = g_b1pe_f[b][t];
        s_b2pe[t] = b2pe[t];
        s_b1at[t] = b1at[t];
    }
    if (t < 16) s_red[t] = 0.f;
    __syncthreads();

    // ---- phase A: u = relu(conv1_pe'(lp)) -> Xs[col=t][k] ----
    {
        int col = colbase + t;
        float lp[4];
        compute_lp(q, kx, idx, b, col, lp);
        u64 a1[32];
#pragma unroll
        for (int p = 0; p < 32; p++)
            a1[p] = *reinterpret_cast<const u64*>(&s_b1pe[2 * p]);
#pragma unroll
        for (int c = 0; c < 4; c++) {
            u64 xb = pack2(lp[c]);
#pragma unroll
            for (int p = 0; p < 32; p++) {
                u64 w = *reinterpret_cast<const u64*>(&s_w1pe[c * 64 + 2 * p]);
                a1[p] = fma2(w, xb, a1[p]);
            }
        }
        unsigned hh[32];
#pragma unroll
        for (int p = 0; p < 32; p++) {
            float lo, hi;
            unpack2(a1[p], lo, hi);
            hh[p] = h2u(fmaxf(lo, 0.f), fmaxf(hi, 0.f));
        }
#pragma unroll
        for (int c = 0; c < 8; c++)
            *reinterpret_cast<uint4*>(Xs + t * XSTR + 8 * c) =
                make_uint4(hh[4*c], hh[4*c+1], hh[4*c+2], hh[4*c+3]);
    }
    __syncwarp();

    unsigned xsb  = (unsigned)__cvta_generic_to_shared(Xs + (size_t)n0 * XSTR);
    unsigned ws1b = (unsigned)__cvta_generic_to_shared(Ws1);
    unsigned ws2b = (unsigned)__cvta_generic_to_shared(Ws2);
    int arow = lane & 15, ahalf = lane >> 4;
    int brow = (lane & 7) + ((lane >> 4) & 1) * 8;
    int bk   = ((lane >> 3) & 1) * 8;

    // ---- GEMM1: C1[o_pe rows][col cols] = w2pe * u + b2pe ----
    float C1[4][4][4];
#pragma unroll
    for (int mt = 0; mt < 4; mt++) {
        float b0 = s_b2pe[16 * mt + grp], b1 = s_b2pe[16 * mt + 8 + grp];
#pragma unroll
        for (int nt = 0; nt < 4; nt++) {
            C1[mt][nt][0] = b0; C1[mt][nt][1] = b0;
            C1[mt][nt][2] = b1; C1[mt][nt][3] = b1;
        }
    }
#pragma unroll
    for (int kt = 0; kt < 4; kt++) {
        unsigned Af[4][4];
#pragma unroll
        for (int mt = 0; mt < 4; mt++)
            ldsm4(Af[mt], ws1b + 2 * ((16 * mt + arow) * WSTR + 16 * kt + 8 * ahalf));
#pragma unroll
        for (int ntp = 0; ntp < 2; ntp++) {
            unsigned Bf[4];
            ldsm4(Bf, xsb + 2 * ((16 * ntp + brow) * XSTR + 16 * kt + bk));
#pragma unroll
            for (int mt = 0; mt < 4; mt++) {
                mma16816(C1[mt][2 * ntp],     Af[mt], Bf);
                mma16816(C1[mt][2 * ntp + 1], Af[mt], Bf + 2);
            }
        }
    }

    // ---- pe store global [o][MKn] + movmatrix chain -> GEMM2 B-fragments ----
    unsigned Bc[4][4][2];
    {
        __half* gpe = g_pe_buf + (size_t)b * 64 * MKn + colbase;
#pragma unroll
        for (int mt = 0; mt < 4; mt++) {
            int r0 = 16 * mt + grp, r1 = r0 + 8;
#pragma unroll
            for (int nt = 0; nt < 4; nt++) {
                int colL = n0 + 8 * nt + 2 * tig;
                unsigned p01 = h2u(C1[mt][nt][0], C1[mt][nt][1]);
                unsigned p23 = h2u(C1[mt][nt][2], C1[mt][nt][3]);
                *reinterpret_cast<unsigned*>(gpe + (size_t)r0 * MKn + colL) = p01;
                *reinterpret_cast<unsigned*>(gpe + (size_t)r1 * MKn + colL) = p23;
                Bc[mt][nt][0] = movm(p01);
                Bc[mt][nt][1] = movm(p23);
            }
        }
    }

    // ---- GEMM2 (stats only): C2 = w1at * pe + b1at ----
    float C2[4][4][4];
#pragma unroll
    for (int mt = 0; mt < 4; mt++) {
        float b0 = s_b1at[16 * mt + grp], b1 = s_b1at[16 * mt + 8 + grp];
#pragma unroll
        for (int nt = 0; nt < 4; nt++) {
            C2[mt][nt][0] = b0; C2[mt][nt][1] = b0;
            C2[mt][nt][2] = b1; C2[mt][nt][3] = b1;
        }
    }
#pragma unroll
    for (int kt = 0; kt < 4; kt++) {
        unsigned Af[4][4];
#pragma unroll
        for (int mt = 0; mt < 4; mt++)
            ldsm4(Af[mt], ws2b + 2 * ((16 * mt + arow) * WSTR + 16 * kt + 8 * ahalf));
#pragma unroll
        for (int mt = 0; mt < 4; mt++)
#pragma unroll
            for (int nt = 0; nt < 4; nt++)
                mma16816(C2[mt][nt], Af[mt], Bc[kt][nt]);
    }

    // ---- GN2 stats from C2 fragments ----
    {
        float gs[8], gq[8];
#pragma unroll
        for (int g = 0; g < 8; g++) { gs[g] = 0.f; gq[g] = 0.f; }
#pragma unroll
        for (int mt = 0; mt < 4; mt++) {
#pragma unroll
            for (int nt = 0; nt < 4; nt++) {
                float v0 = C2[mt][nt][0], v1 = C2[mt][nt][1];
                float v2 = C2[mt][nt][2], v3 = C2[mt][nt][3];
                gs[2 * mt]     += v0 + v1;
                gq[2 * mt]     = fmaf(v0, v0, fmaf(v1, v1, gq[2 * mt]));
                gs[2 * mt + 1] += v2 + v3;
                gq[2 * mt + 1] = fmaf(v2, v2, fmaf(v3, v3, gq[2 * mt + 1]));
            }
        }
        float r[16];
#pragma unroll
        for (int g = 0; g < 8; g++) { r[g] = gs[g]; r[8 + g] = gq[g]; }
#pragma unroll
        for (int i = 0; i < 16; i++)
            for (int off = 16; off; off >>= 1)
                r[i] += __shfl_down_sync(0xffffffffu, r[i], off);
        if (lane == 0) {
#pragma unroll
            for (int i = 0; i < 16; i++) atomicAdd(&s_red[i], r[i]);
        }
    }
    __syncthreads();
    if (t < 16) atomicAdd(&g_s2[b][t & 7][t >> 3], (double)s_red[t]);
}

__global__ void k_fin2(const float* __restrict__ gam, const float* __restrict__ bet) {
    int o = threadIdx.x;  // 64 threads
    double n = (double)CPGn * (double)MKn;
    for (int b = 0; b < Bn; b++) {
        int g = o >> 3;
        double s = g_s2[b][g][0], sq = g_s2[b][g][1];
        double mean = s / n;
        double var  = sq / n - mean * mean;
        float rstd  = (float)(1.0 / sqrt(var + (double)GN_EPS));
        float a  = gam[o] * rstd;
        float cc = bet[o] - (float)mean * a;
        g_gn2d[b][o]      = a;
        g_gn2d[b][64 + o] = cc;
    }
}

// ---- pass3 smem (bytes) ----
#define P3_PE    0                       // fp16 [64][VSTR]   17408
#define P3_WS2   17408                   // fp16 [64][WSTR]   9216
#define P3_WS3   26624                   // fp16 [64][WSTR]   9216
#define P3_ACT   35840                   // fp16 [64][ASTRH]  17408
#define P3_GN    53248                   // fp32 128
#define P3_B1AT  53760                   // fp32 64
#define P3_BAT   54016                   // fp32 64
#define P3_TOTB  54272

__global__ __launch_bounds__(128, 4) void k_pass3(const int* __restrict__ mask,
                                                  const float* __restrict__ b1at,
                                                  const float* __restrict__ b2at,
                                                  float* __restrict__ out) {
    extern __shared__ __align__(16) char smc[];
    __half* Pe_s  = reinterpret_cast<__half*>(smc + P3_PE);
    __half* Ws2   = reinterpret_cast<__half*>(smc + P3_WS2);
    __half* Ws3   = reinterpret_cast<__half*>(smc + P3_WS3);
    __half* acth  = reinterpret_cast<__half*>(smc + P3_ACT);
    float* s_gn   = reinterpret_cast<float*>(smc + P3_GN);
    float* s_b1at = reinterpret_cast<float*>(smc + P3_B1AT);
    float* s_bat  = reinterpret_cast<float*>(smc + P3_BAT);

    int t = threadIdx.x, b = blockIdx.y;
    int colbase = blockIdx.x * 128;
    int lane = t & 31, warp = t >> 5;
    int grp = lane >> 2, tig = lane & 3;
    int n0 = warp * 32;

    stage_w(g_w1at_h, Ws2, t);
    stage_w(g_w2at_h, Ws3, t);
    s_gn[t] = g_gn2d[b][t];
    if (t < 64) { s_b1at[t] = b1at[t]; s_bat[t] = b2at[t]; }
    // stage pe -> Pe_s[o][col] (coalesced uint2)
    {
        const __half* gpe = g_pe_buf + (size_t)b * 64 * MKn;
#pragma unroll
        for (int s = 0; s < 16; s++) {
            int id = t + 128 * s;        // 64 o x 32 col-quads
            int o = id >> 5, cq = id & 31;
            uint2 hv = __ldg(reinterpret_cast<const uint2*>(
                gpe + (size_t)o * MKn + colbase + 4 * cq));
            *reinterpret_cast<uint2*>(Pe_s + o * VSTR + 4 * cq) = hv;
        }
    }
    __syncthreads();

    unsigned peb  = (unsigned)__cvta_generic_to_shared(Pe_s);
    unsigned ws2b = (unsigned)__cvta_generic_to_shared(Ws2);
    unsigned ws3b = (unsigned)__cvta_generic_to_shared(Ws3);
    int arow = lane & 15, ahalf = lane >> 4;
    int orow = (lane & 7) + ((lane >> 3) & 1) * 8;
    int ocol = ((lane >> 4) & 1) * 8;

    // ---- GEMM2: C2[o_h1][col] = w1at * pe + b1at (B via ldsm4t, proven path) ----
    float C2[4][4][4];
#pragma unroll
    for (int mt = 0; mt < 4; mt++) {
        float b0 = s_b1at[16 * mt + grp], b1 = s_b1at[16 * mt + 8 + grp];
#pragma unroll
        for (int nt = 0; nt < 4; nt++) {
            C2[mt][nt][0] = b0; C2[mt][nt][1] = b0;
            C2[mt][nt][2] = b1; C2[mt][nt][3] = b1;
        }
    }
#pragma unroll
    for (int kt = 0; kt < 4; kt++) {
        unsigned Af[4][4];
#pragma unroll
        for (int mt = 0; mt < 4; mt++)
            ldsm4(Af[mt], ws2b + 2 * ((16 * mt + arow) * WSTR + 16 * kt + 8 * ahalf));
#pragma unroll
        for (int ntp = 0; ntp < 2; ntp++) {
            unsigned Bf[4];
            ldsm4t(Bf, peb + 2 * ((16 * kt + orow) * VSTR + n0 + 16 * ntp + ocol));
#pragma unroll
            for (int mt = 0; mt < 4; mt++) {
                mma16816(C2[mt][2 * ntp],     Af[mt], Bf);
                mma16816(C2[mt][2 * ntp + 1], Af[mt], Bf + 2);
            }
        }
    }

    // ---- GN2 fold + relu on fragments -> movmatrix chain (proven path) ----
    unsigned Bv[4][4][2];
#pragma unroll
    for (int mt = 0; mt < 4; mt++) {
        int r0 = 16 * mt + grp, r1 = r0 + 8;
        float a0 = s_gn[r0], c0 = s_gn[64 + r0];
        float a1 = s_gn[r1], c1 = s_gn[64 + r1];
#pragma unroll
        for (int nt = 0; nt < 4; nt++) {
            float v0 = fmaxf(fmaf(a0, C2[mt][nt][0], c0), 0.f);
            float v1 = fmaxf(fmaf(a0, C2[mt][nt][1], c0), 0.f);
            float v2 = fmaxf(fmaf(a1, C2[mt][nt][2], c1), 0.f);
            float v3 = fmaxf(fmaf(a1, C2[mt][nt][3], c1), 0.f);
            Bv[mt][nt][0] = movm(h2u(v0, v1));
            Bv[mt][nt][1] = movm(h2u(v2, v3));
        }
    }

    // ---- GEMM3: C3[o][col] = w2at * v + b2at (chained B, proven path) ----
    float C3[4][4][4];
#pragma unroll
    for (int mt = 0; mt < 4; mt++) {
        float b0 = s_bat[16 * mt + grp], b1 = s_bat[16 * mt + 8 + grp];
#pragma unroll
        for (int nt = 0; nt < 4; nt++) {
            C3[mt][nt][0] = b0; C3[mt][nt][1] = b0;
            C3[mt][nt][2] = b1; C3[mt][nt][3] = b1;
        }
    }
#pragma unroll
    for (int kt = 0; kt < 4; kt++) {
        unsigned Af[4][4];
#pragma unroll
        for (int mt = 0; mt < 4; mt++)
            ldsm4(Af[mt], ws3b + 2 * ((16 * mt + arow) * WSTR + 16 * kt + 8 * ahalf));
#pragma unroll
        for (int mt = 0; mt < 4; mt++)
#pragma unroll
            for (int nt = 0; nt < 4; nt++)
                mma16816(C3[mt][nt], Af[mt], Bv[kt][nt]);
    }

    // ---- masked store -> acth fp16 [o][col] ----
    {
        const int* mrow = mask + (size_t)b * MKn + colbase;
        int2 mv[4];
#pragma unroll
        for (int nt = 0; nt < 4; nt++)
            mv[nt] = *reinterpret_cast<const int2*>(mrow + n0 + 8 * nt + 2 * tig);
#pragma unroll
        for (int mt = 0; mt < 4; mt++) {
            int r0 = 16 * mt + grp, r1 = r0 + 8;
#pragma unroll
            for (int nt = 0; nt < 4; nt++) {
                int colL = n0 + 8 * nt + 2 * tig;
                bool m0 = mv[nt].x != 0, m1 = mv[nt].y != 0;
                float f0 = m0 ? C3[mt][nt][0] : -65504.f;
                float f1 = m1 ? C3[mt][nt][1] : -65504.f;
                float f2 = m0 ? C3[mt][nt][2] : -65504.f;
                float f3 = m1 ? C3[mt][nt][3] : -65504.f;
                *reinterpret_cast<unsigned*>(acth + r0 * ASTRH + colL) = h2u(f0, f1);
                *reinterpret_cast<unsigned*>(acth + r1 * ASTRH + colL) = h2u(f2, f3);
            }
        }
    }
    __syncthreads();

    // ---- per-(m,o) softmax units: 16 contiguous cols; pe from smem ----
    int mbase = colbase >> 4;      // 8 m per tile
#pragma unroll
    for (int r = 0; r < 4; r++) {
        int unit = r * 128 + t;    // 0..511
        int o = unit >> 3, ml = unit & 7;
        uint4 aw0 = *reinterpret_cast<const uint4*>(acth + o * ASTRH + 16 * ml);
        uint4 aw1 = *reinterpret_cast<const uint4*>(acth + o * ASTRH + 16 * ml + 8);
        float av[16];
        {
            float4 x;
            x = h4_to_f4(make_uint2(aw0.x, aw0.y));
            av[0] = x.x; av[1] = x.y; av[2] = x.z; av[3] = x.w;
            x = h4_to_f4(make_uint2(aw0.z, aw0.w));
            av[4] = x.x; av[5] = x.y; av[6] = x.z; av[7] = x.w;
            x = h4_to_f4(make_uint2(aw1.x, aw1.y));
            av[8] = x.x; av[9] = x.y; av[10] = x.z; av[11] = x.w;
            x = h4_to_f4(make_uint2(aw1.z, aw1.w));
            av[12] = x.x; av[13] = x.y; av[14] = x.z; av[15] = x.w;
        }
        float mx = av[0];
#pragma unroll
        for (int j = 1; j < 16; j++) mx = fmaxf(mx, av[j]);
        float s = 0.f;
#pragma unroll
        for (int j = 0; j < 16; j++) { av[j] = __expf(av[j] - mx); s += av[j]; }
        uint4 pw0 = *reinterpret_cast<const uint4*>(Pe_s + o * VSTR + 16 * ml);
        uint4 pw1 = *reinterpret_cast<const uint4*>(Pe_s + o * VSTR + 16 * ml + 8);
        float accum = 0.f;
        {
            float4 p;
            p = h4_to_f4(make_uint2(pw0.x, pw0.y));
            accum = fmaf(p.x, av[0], fmaf(p.y, av[1], fmaf(p.z, av[2], fmaf(p.w, av[3], accum))));
            p = h4_to_f4(make_uint2(pw0.z, pw0.w));
            accum = fmaf(p.x, av[4], fmaf(p.y, av[5], fmaf(p.z, av[6], fmaf(p.w, av[7], accum))));
            p = h4_to_f4(make_uint2(pw1.x, pw1.y));
            accum = fmaf(p.x, av[8], fmaf(p.y, av[9], fmaf(p.z, av[10], fmaf(p.w, av[11], accum))));
            p = h4_to_f4(make_uint2(pw1.z, pw1.w));
            accum = fmaf(p.x, av[12], fmaf(p.y, av[13], fmaf(p.z, av[14], fmaf(p.w, av[15], accum))));
        }
        out[((size_t)b * 64 + o) * Mn + mbase + ml] = accum * __fdividef(1.f, s);
    }
}

// ---------------- launch ----------------
extern "C" void kernel_launch(void* const* d_in, const int* in_sizes, int n_in,
                              void* d_out, int out_size) {
    const float* q_xyzs  = (const float*)d_in[0];
    const float* k_xyzs  = (const float*)d_in[1];
    const int*   knn_idx = (const int*)d_in[2];
    const int*   mask    = (const int*)d_in[3];
    const float* pe_w1   = (const float*)d_in[4];
    const float* pe_b1   = (const float*)d_in[5];
    const float* pe_g    = (const float*)d_in[6];
    const float* pe_be   = (const float*)d_in[7];
    const float* pe_w2   = (const float*)d_in[8];
    const float* pe_b2   = (const float*)d_in[9];
    const float* at_w1   = (const float*)d_in[10];
    const float* at_b1   = (const float*)d_in[11];
    const float* at_g    = (const float*)d_in[12];
    const float* at_be   = (const float*)d_in[13];
    const float* at_w2   = (const float*)d_in[14];
    const float* at_b2   = (const float*)d_in[15];
    float* out = (float*)d_out;

    static int smem_set = 0;
    if (!smem_set) {
        cudaFuncSetAttribute(k_pass2, cudaFuncAttributeMaxDynamicSharedMemorySize,
                             P2_TOTB);
        cudaFuncSetAttribute(k_pass3, cudaFuncAttributeMaxDynamicSharedMemorySize,
                             P3_TOTB);
        smem_set = 1;
    }

    k_prep<<<64, 64>>>(pe_w2, at_w1, at_w2);

    dim3 gcol(MKn / 128, Bn);
    k_pass1<<<gcol, 128>>>(q_xyzs, k_xyzs, knn_idx);
    k_fin1<<<1, 64>>>(pe_w1, pe_b1, pe_g, pe_be);

    k_pass2<<<gcol, 128, P2_TOTB>>>(q_xyzs, k_xyzs, knn_idx, pe_b2, at_b1);
    k_fin2<<<1, 64>>>(at_g, at_be);

    k_pass3<<<gcol, 128, P3_TOTB>>>(mask, at_b1, at_b2, out);
}

// round 14
// speedup vs baseline: 6.5137x; 1.0687x over previous
#include <cuda_runtime.h>
#include <cuda_fp16.h>
#include <math.h>
#include <float.h>

#define Bn   2
#define Mn   25000
#define Nn   100000
#define NGn  8
#define CPGn 8
#define GN_EPS 1e-5f
#define MKn  (Mn * 16)          // 400000 columns per batch

#define XLSTR 24                // fp16 lp-tile stride (halves): 48B rows, ldsm conflict-free
#define WLSTR 24                // fp16 folded-w1 stride
#define WSTR 72                 // fp16 weight stride
#define VSTR 136                // fp16 pe stride in pass3 [o][col]
#define ASTRH 136               // fp16 attn stride in pass3 [o][col]

typedef unsigned long long u64;

// ---------------- device scratch ----------------
__device__ double g_m1[Bn][14];
__device__ double g_s2[Bn][NGn][2];
__device__ __align__(16) float g_b1pe_f[Bn][64];
__device__ __align__(16) __half g_w1pe_hf[Bn][1024]; // folded conv1_pe fp16 [o][16] (12 zero-pad)
__device__ __align__(16) float g_gn2d[Bn][128];      // a2[64] | c2[64]
__device__ __align__(16) __half g_w2pe_h[4096];      // [o][k] fp16
__device__ __align__(16) __half g_w1at_h[4096];      // [o][k] fp16
__device__ __align__(16) __half g_w2at_h[4096];      // [o][k] fp16
// activation scratch [b][o][MKn] fp16 (pe only; h1 recomputed in pass3)
__device__ __align__(16) __half g_pe_buf[(size_t)Bn * 64 * MKn];

// ---------------- scalar helpers ----------------
__device__ __forceinline__ float4 h4_to_f4(uint2 u) {
    __half2 a = *reinterpret_cast<__half2*>(&u.x);
    __half2 b = *reinterpret_cast<__half2*>(&u.y);
    float2 fa = __half22float2(a), fb = __half22float2(b);
    return make_float4(fa.x, fa.y, fb.x, fb.y);
}
__device__ __forceinline__ unsigned h2u(float a, float b) {
    __half2 h = __floats2half2_rn(a, b);
    return *reinterpret_cast<unsigned*>(&h);
}

// ---------------- tensor primitives ----------------
__device__ __forceinline__ void mma16816(float* c, const unsigned* a, const unsigned* b) {
    asm volatile(
        "mma.sync.aligned.m16n8k16.row.col.f32.f16.f16.f32 "
        "{%0,%1,%2,%3}, {%4,%5,%6,%7}, {%8,%9}, {%0,%1,%2,%3};\n"
        : "+f"(c[0]), "+f"(c[1]), "+f"(c[2]), "+f"(c[3])
        : "r"(a[0]), "r"(a[1]), "r"(a[2]), "r"(a[3]), "r"(b[0]), "r"(b[1]));
}
__device__ __forceinline__ void ldsm4(unsigned* r, unsigned addr) {
    asm volatile("ldmatrix.sync.aligned.m8n8.x4.shared.b16 {%0,%1,%2,%3}, [%4];"
        : "=r"(r[0]), "=r"(r[1]), "=r"(r[2]), "=r"(r[3]) : "r"(addr));
}
__device__ __forceinline__ void ldsm4t(unsigned* r, unsigned addr) {
    asm volatile("ldmatrix.sync.aligned.m8n8.x4.trans.shared.b16 {%0,%1,%2,%3}, [%4];"
        : "=r"(r[0]), "=r"(r[1]), "=r"(r[2]), "=r"(r[3]) : "r"(addr));
}
__device__ __forceinline__ unsigned movm(unsigned a) {
    unsigned d;
    asm volatile("movmatrix.sync.aligned.m8n8.trans.b16 %0, %1;" : "=r"(d) : "r"(a));
    return d;
}

// ---------------- misc helpers ----------------
__device__ __forceinline__ void compute_lp(const float* __restrict__ q,
                                           const float* __restrict__ kx,
                                           const int*   __restrict__ idx,
                                           int b, int c, float lp[4]) {
    int m  = c >> 4;
    int id = idx[b * MKn + c];
    float qx = q[(b * 3 + 0) * Mn + m];
    float qy = q[(b * 3 + 1) * Mn + m];
    float qz = q[(b * 3 + 2) * Mn + m];
    float px = kx[(b * 3 + 0) * Nn + id];
    float py = kx[(b * 3 + 1) * Nn + id];
    float pz = kx[(b * 3 + 2) * Nn + id];
    float ox = px - qx, oy = py - qy, oz = pz - qz;
    float d  = sqrtf(ox * ox + oy * oy + oz * oz);
    float r  = 1.0f / fmaxf(d, 1e-12f);
    lp[0] = ox * r; lp[1] = oy * r; lp[2] = oz * r; lp[3] = d;
}

// stage a 64x64 fp16 [o][k] weight into smem [o][WSTR]
__device__ __forceinline__ void stage_w(const __half* __restrict__ gsrc,
                                        __half* Ws, int t) {
#pragma unroll
    for (int id = t; id < 512; id += 128) {
        int row = id >> 3, c = id & 7;
        uint4 v = *reinterpret_cast<const uint4*>(gsrc + row * 64 + c * 8);
        *reinterpret_cast<uint4*>(Ws + row * WSTR + c * 8) = v;
    }
}

// ---------------- kernels ----------------
__global__ void k_prep(const float* __restrict__ w2pe,
                       const float* __restrict__ w1at,
                       const float* __restrict__ w2at) {
    int i = blockIdx.x;   // output channel
    int j = threadIdx.x;  // input channel
    g_w2pe_h[i * 64 + j] = __float2half(w2pe[i * 64 + j]);
    g_w1at_h[i * 64 + j] = __float2half(w1at[i * 64 + j]);
    g_w2at_h[i * 64 + j] = __float2half(w2at[i * 64 + j]);
    if (i == 0) {
        if (j < Bn * NGn * 2) ((double*)g_s2)[j] = 0.0;
        if (j < Bn * 14)      ((double*)g_m1)[j] = 0.0;
    }
}

__global__ __launch_bounds__(128) void k_pass1(const float* __restrict__ q,
                                               const float* __restrict__ kx,
                                               const int*   __restrict__ idx) {
    __shared__ float s_red[14];
    int t = threadIdx.x, b = blockIdx.y;
    if (t < 14) s_red[t] = 0.f;
    __syncthreads();
    int col = blockIdx.x * 128 + t;
    float lp[4];
    compute_lp(q, kx, idx, b, col, lp);

    float v[14];
    v[0] = lp[0]; v[1] = lp[1]; v[2] = lp[2]; v[3] = lp[3];
    {
        int n = 4;
#pragma unroll
        for (int c = 0; c < 4; c++)
#pragma unroll
            for (int d = c; d < 4; d++) v[n++] = lp[c] * lp[d];
    }
#pragma unroll
    for (int i = 0; i < 14; i++) {
        for (int off = 16; off; off >>= 1)
            v[i] += __shfl_down_sync(0xffffffffu, v[i], off);
        if ((t & 31) == 0) atomicAdd(&s_red[i], v[i]);
    }
    __syncthreads();
    if (t < 14) atomicAdd(&g_m1[b][t], (double)s_red[t]);
}

__global__ void k_fin1(const float* __restrict__ w1, const float* __restrict__ b1,
                       const float* __restrict__ gam, const float* __restrict__ bet) {
    __shared__ double gs[8], gq[8];
    int o = threadIdx.x;  // 64 threads
    double n = (double)CPGn * (double)MKn;
    for (int b = 0; b < Bn; b++) {
        if (o < 8) { gs[o] = 0.0; gq[o] = 0.0; }
        __syncthreads();
        double m[14];
#pragma unroll
        for (int i = 0; i < 14; i++) m[i] = g_m1[b][i];
        double M2[4][4];
        {
            int idx5 = 4;
            for (int c = 0; c < 4; c++)
                for (int d = c; d < 4; d++) {
                    M2[c][d] = m[idx5]; M2[d][c] = m[idx5]; idx5++;
                }
        }
        double w[4];
#pragma unroll
        for (int c = 0; c < 4; c++) w[c] = (double)w1[o * 4 + c];
        double bo = (double)b1[o];
        double dot = w[0] * m[0] + w[1] * m[1] + w[2] * m[2] + w[3] * m[3];
        double sum_o = dot + (double)MKn * bo;
        double sq_o = 0.0;
#pragma unroll
        for (int c = 0; c < 4; c++)
#pragma unroll
            for (int d = 0; d < 4; d++) sq_o += w[c] * w[d] * M2[c][d];
        sq_o += 2.0 * bo * dot + (double)MKn * bo * bo;
        atomicAdd(&gs[o >> 3], sum_o);
        atomicAdd(&gq[o >> 3], sq_o);
        __syncthreads();
        int g = o >> 3;
        double mean = gs[g] / n;
        double var  = gq[g] / n - mean * mean;
        float rstd  = (float)(1.0 / sqrt(var + (double)GN_EPS));
        float a  = gam[o] * rstd;
        float cc = bet[o] - (float)mean * a;
        g_b1pe_f[b][o] = fmaf(a, b1[o], cc);
        __half* wh = g_w1pe_hf[b] + o * 16;
        for (int c = 0; c < 4; c++) wh[c] = __float2half(a * w1[o * 4 + c]);
        for (int c = 4; c < 16; c++) wh[c] = __float2half(0.f);
        __syncthreads();
    }
}

// ---- pass2 smem (bytes) ----
#define P2_XLP   0                       // fp16 [128][XLSTR]  6144
#define P2_WLP   6144                    // fp16 [64][WLSTR]   3072
#define P2_WS1   9216                    // fp16 [64][WSTR]    9216
#define P2_WS2   18432                   // fp16 [64][WSTR]    9216
#define P2_B1PE  27648                   // fp32 64
#define P2_B2PE  27904
#define P2_B1AT  28160
#define P2_RED   28416
#define P2_TOTB  28480

__global__ __launch_bounds__(128, 4) void k_pass2(const float* __restrict__ q,
                                                  const float* __restrict__ kx,
                                                  const int*   __restrict__ idx,
                                                  const float* __restrict__ b2pe,
                                                  const float* __restrict__ b1at) {
    extern __shared__ __align__(16) char smc[];
    __half* Xlp = reinterpret_cast<__half*>(smc + P2_XLP);
    __half* Wlp = reinterpret_cast<__half*>(smc + P2_WLP);
    __half* Ws1 = reinterpret_cast<__half*>(smc + P2_WS1);
    __half* Ws2 = reinterpret_cast<__half*>(smc + P2_WS2);
    float* s_b1pe = reinterpret_cast<float*>(smc + P2_B1PE);
    float* s_b2pe = reinterpret_cast<float*>(smc + P2_B2PE);
    float* s_b1at = reinterpret_cast<float*>(smc + P2_B1AT);
    float* s_red  = reinterpret_cast<float*>(smc + P2_RED);

    int t = threadIdx.x, b = blockIdx.y;
    int colbase = blockIdx.x * 128;
    int lane = t & 31, warp = t >> 5;
    int grp = lane >> 2, tig = lane & 3;
    int n0 = warp * 32;

    stage_w(g_w2pe_h, Ws1, t);
    stage_w(g_w1at_h, Ws2, t);
    {   // folded conv1 fp16 weights [64][16] -> [64][WLSTR]
        int row = t >> 1, c = t & 1;
        uint4 v = *reinterpret_cast<const uint4*>(g_w1pe_hf[b] + row * 16 + c * 8);
        *reinterpret_cast<uint4*>(Wlp + row * WLSTR + c * 8) = v;
    }
    if (t < 64) {
        s_b1pe[t] = g_b1pe_f[b][t];
        s_b2pe[t] = b2pe[t];
        s_b1at[t] = b1at[t];
    }
    if (t < 16) s_red[t] = 0.f;

    // ---- stage lp -> Xlp[col=t][0..15] (4 real + 12 zero) ----
    {
        int col = colbase + t;
        float lp[4];
        compute_lp(q, kx, idx, b, col, lp);
        *reinterpret_cast<uint4*>(Xlp + t * XLSTR) =
            make_uint4(h2u(lp[0], lp[1]), h2u(lp[2], lp[3]), 0u, 0u);
        *reinterpret_cast<uint4*>(Xlp + t * XLSTR + 8) = make_uint4(0u, 0u, 0u, 0u);
    }
    __syncthreads();

    unsigned xlpb = (unsigned)__cvta_generic_to_shared(Xlp + (size_t)n0 * XLSTR);
    unsigned wlpb = (unsigned)__cvta_generic_to_shared(Wlp);
    unsigned ws1b = (unsigned)__cvta_generic_to_shared(Ws1);
    unsigned ws2b = (unsigned)__cvta_generic_to_shared(Ws2);
    int arow = lane & 15, ahalf = lane >> 4;
    int brow = (lane & 7) + ((lane >> 4) & 1) * 8;
    int bk   = ((lane >> 3) & 1) * 8;

    // ---- u-GEMM (K=16): Cu[o_u rows][col cols] = w1pe' * lp + b1pe ----
    float Cu[4][4][4];
#pragma unroll
    for (int mt = 0; mt < 4; mt++) {
        float b0 = s_b1pe[16 * mt + grp], b1 = s_b1pe[16 * mt + 8 + grp];
#pragma unroll
        for (int nt = 0; nt < 4; nt++) {
            Cu[mt][nt][0] = b0; Cu[mt][nt][1] = b0;
            Cu[mt][nt][2] = b1; Cu[mt][nt][3] = b1;
        }
    }
    {
        unsigned Af[4][4];
#pragma unroll
        for (int mt = 0; mt < 4; mt++)
            ldsm4(Af[mt], wlpb + 2 * ((16 * mt + arow) * WLSTR + 8 * ahalf));
#pragma unroll
        for (int ntp = 0; ntp < 2; ntp++) {
            unsigned Bf[4];
            ldsm4(Bf, xlpb + 2 * ((16 * ntp + brow) * XLSTR + bk));
#pragma unroll
            for (int mt = 0; mt < 4; mt++) {
                mma16816(Cu[mt][2 * ntp],     Af[mt], Bf);
                mma16816(Cu[mt][2 * ntp + 1], Af[mt], Bf + 2);
            }
        }
    }

    // ---- relu + movmatrix chain -> GEMM1 B-fragments ----
    unsigned Bu[4][4][2];
#pragma unroll
    for (int mt = 0; mt < 4; mt++)
#pragma unroll
        for (int nt = 0; nt < 4; nt++) {
            Bu[mt][nt][0] = movm(h2u(fmaxf(Cu[mt][nt][0], 0.f), fmaxf(Cu[mt][nt][1], 0.f)));
            Bu[mt][nt][1] = movm(h2u(fmaxf(Cu[mt][nt][2], 0.f), fmaxf(Cu[mt][nt][3], 0.f)));
        }

    // ---- GEMM1 (chained B): C1[o_pe rows][col cols] = w2pe * u + b2pe ----
    float C1[4][4][4];
#pragma unroll
    for (int mt = 0; mt < 4; mt++) {
        float b0 = s_b2pe[16 * mt + grp], b1 = s_b2pe[16 * mt + 8 + grp];
#pragma unroll
        for (int nt = 0; nt < 4; nt++) {
            C1[mt][nt][0] = b0; C1[mt][nt][1] = b0;
            C1[mt][nt][2] = b1; C1[mt][nt][3] = b1;
        }
    }
#pragma unroll
    for (int kt = 0; kt < 4; kt++) {
        unsigned Af[4][4];
#pragma unroll
        for (int mt = 0; mt < 4; mt++)
            ldsm4(Af[mt], ws1b + 2 * ((16 * mt + arow) * WSTR + 16 * kt + 8 * ahalf));
#pragma unroll
        for (int mt = 0; mt < 4; mt++)
#pragma unroll
            for (int nt = 0; nt < 4; nt++)
                mma16816(C1[mt][nt], Af[mt], Bu[kt][nt]);
    }

    // ---- pe store global [o][MKn] + movmatrix chain -> GEMM2 B-fragments ----
    unsigned Bc[4][4][2];
    {
        __half* gpe = g_pe_buf + (size_t)b * 64 * MKn + colbase;
#pragma unroll
        for (int mt = 0; mt < 4; mt++) {
            int r0 = 16 * mt + grp, r1 = r0 + 8;
#pragma unroll
            for (int nt = 0; nt < 4; nt++) {
                int colL = n0 + 8 * nt + 2 * tig;
                unsigned p01 = h2u(C1[mt][nt][0], C1[mt][nt][1]);
                unsigned p23 = h2u(C1[mt][nt][2], C1[mt][nt][3]);
                *reinterpret_cast<unsigned*>(gpe + (size_t)r0 * MKn + colL) = p01;
                *reinterpret_cast<unsigned*>(gpe + (size_t)r1 * MKn + colL) = p23;
                Bc[mt][nt][0] = movm(p01);
                Bc[mt][nt][1] = movm(p23);
            }
        }
    }

    // ---- GEMM2 (stats only): C2 = w1at * pe + b1at ----
    float C2[4][4][4];
#pragma unroll
    for (int mt = 0; mt < 4; mt++) {
        float b0 = s_b1at[16 * mt + grp], b1 = s_b1at[16 * mt + 8 + grp];
#pragma unroll
        for (int nt = 0; nt < 4; nt++) {
            C2[mt][nt][0] = b0; C2[mt][nt][1] = b0;
            C2[mt][nt][2] = b1; C2[mt][nt][3] = b1;
        }
    }
#pragma unroll
    for (int kt = 0; kt < 4; kt++) {
        unsigned Af[4][4];
#pragma unroll
        for (int mt = 0; mt < 4; mt++)
            ldsm4(Af[mt], ws2b + 2 * ((16 * mt + arow) * WSTR + 16 * kt + 8 * ahalf));
#pragma unroll
        for (int mt = 0; mt < 4; mt++)
#pragma unroll
            for (int nt = 0; nt < 4; nt++)
                mma16816(C2[mt][nt], Af[mt], Bc[kt][nt]);
    }

    // ---- GN2 stats from C2 fragments ----
    {
        float gs[8], gq[8];
#pragma unroll
        for (int g = 0; g < 8; g++) { gs[g] = 0.f; gq[g] = 0.f; }
#pragma unroll
        for (int mt = 0; mt < 4; mt++) {
#pragma unroll
            for (int nt = 0; nt < 4; nt++) {
                float v0 = C2[mt][nt][0], v1 = C2[mt][nt][1];
                float v2 = C2[mt][nt][2], v3 = C2[mt][nt][3];
                gs[2 * mt]     += v0 + v1;
                gq[2 * mt]     = fmaf(v0, v0, fmaf(v1, v1, gq[2 * mt]));
                gs[2 * mt + 1] += v2 + v3;
                gq[2 * mt + 1] = fmaf(v2, v2, fmaf(v3, v3, gq[2 * mt + 1]));
            }
        }
        float r[16];
#pragma unroll
        for (int g = 0; g < 8; g++) { r[g] = gs[g]; r[8 + g] = gq[g]; }
#pragma unroll
        for (int i = 0; i < 16; i++)
            for (int off = 16; off; off >>= 1)
                r[i] += __shfl_down_sync(0xffffffffu, r[i], off);
        if (lane == 0) {
#pragma unroll
            for (int i = 0; i < 16; i++) atomicAdd(&s_red[i], r[i]);
        }
    }
    __syncthreads();
    if (t < 16) atomicAdd(&g_s2[b][t & 7][t >> 3], (double)s_red[t]);
}

__global__ void k_fin2(const float* __restrict__ gam, const float* __restrict__ bet) {
    int o = threadIdx.x;  // 64 threads
    double n = (double)CPGn * (double)MKn;
    for (int b = 0; b < Bn; b++) {
        int g = o >> 3;
        double s = g_s2[b][g][0], sq = g_s2[b][g][1];
        double mean = s / n;
        double var  = sq / n - mean * mean;
        float rstd  = (float)(1.0 / sqrt(var + (double)GN_EPS));
        float a  = gam[o] * rstd;
        float cc = bet[o] - (float)mean * a;
        g_gn2d[b][o]      = a;
        g_gn2d[b][64 + o] = cc;
    }
}

// ---- pass3 smem (bytes) ----
#define P3_PE    0                       // fp16 [64][VSTR]   17408
#define P3_WS2   17408                   // fp16 [64][WSTR]   9216
#define P3_WS3   26624                   // fp16 [64][WSTR]   9216
#define P3_ACT   35840                   // fp16 [64][ASTRH]  17408
#define P3_GN    53248                   // fp32 128
#define P3_B1AT  53760                   // fp32 64
#define P3_BAT   54016                   // fp32 64
#define P3_TOTB  54272

__global__ __launch_bounds__(128, 4) void k_pass3(const int* __restrict__ mask,
                                                  const float* __restrict__ b1at,
                                                  const float* __restrict__ b2at,
                                                  float* __restrict__ out) {
    extern __shared__ __align__(16) char smc[];
    __half* Pe_s  = reinterpret_cast<__half*>(smc + P3_PE);
    __half* Ws2   = reinterpret_cast<__half*>(smc + P3_WS2);
    __half* Ws3   = reinterpret_cast<__half*>(smc + P3_WS3);
    __half* acth  = reinterpret_cast<__half*>(smc + P3_ACT);
    float* s_gn   = reinterpret_cast<float*>(smc + P3_GN);
    float* s_b1at = reinterpret_cast<float*>(smc + P3_B1AT);
    float* s_bat  = reinterpret_cast<float*>(smc + P3_BAT);

    int t = threadIdx.x, b = blockIdx.y;
    int colbase = blockIdx.x * 128;
    int lane = t & 31, warp = t >> 5;
    int grp = lane >> 2, tig = lane & 3;
    int n0 = warp * 32;

    stage_w(g_w1at_h, Ws2, t);
    stage_w(g_w2at_h, Ws3, t);
    s_gn[t] = g_gn2d[b][t];
    if (t < 64) { s_b1at[t] = b1at[t]; s_bat[t] = b2at[t]; }
    // stage pe -> Pe_s[o][col] (coalesced uint2)
    {
        const __half* gpe = g_pe_buf + (size_t)b * 64 * MKn;
#pragma unroll
        for (int s = 0; s < 16; s++) {
            int id = t + 128 * s;        // 64 o x 32 col-quads
            int o = id >> 5, cq = id & 31;
            uint2 hv = __ldg(reinterpret_cast<const uint2*>(
                gpe + (size_t)o * MKn + colbase + 4 * cq));
            *reinterpret_cast<uint2*>(Pe_s + o * VSTR + 4 * cq) = hv;
        }
    }
    __syncthreads();

    unsigned peb  = (unsigned)__cvta_generic_to_shared(Pe_s);
    unsigned ws2b = (unsigned)__cvta_generic_to_shared(Ws2);
    unsigned ws3b = (unsigned)__cvta_generic_to_shared(Ws3);
    int arow = lane & 15, ahalf = lane >> 4;
    int orow = (lane & 7) + ((lane >> 3) & 1) * 8;
    int ocol = ((lane >> 4) & 1) * 8;

    // ---- GEMM2: C2[o_h1][col] = w1at * pe + b1at ----
    float C2[4][4][4];
#pragma unroll
    for (int mt = 0; mt < 4; mt++) {
        float b0 = s_b1at[16 * mt + grp], b1 = s_b1at[16 * mt + 8 + grp];
#pragma unroll
        for (int nt = 0; nt < 4; nt++) {
            C2[mt][nt][0] = b0; C2[mt][nt][1] = b0;
            C2[mt][nt][2] = b1; C2[mt][nt][3] = b1;
        }
    }
#pragma unroll
    for (int kt = 0; kt < 4; kt++) {
        unsigned Af[4][4];
#pragma unroll
        for (int mt = 0; mt < 4; mt++)
            ldsm4(Af[mt], ws2b + 2 * ((16 * mt + arow) * WSTR + 16 * kt + 8 * ahalf));
#pragma unroll
        for (int ntp = 0; ntp < 2; ntp++) {
            unsigned Bf[4];
            ldsm4t(Bf, peb + 2 * ((16 * kt + orow) * VSTR + n0 + 16 * ntp + ocol));
#pragma unroll
            for (int mt = 0; mt < 4; mt++) {
                mma16816(C2[mt][2 * ntp],     Af[mt], Bf);
                mma16816(C2[mt][2 * ntp + 1], Af[mt], Bf + 2);
            }
        }
    }

    // ---- GN2 fold + relu on fragments -> movmatrix chain ----
    unsigned Bv[4][4][2];
#pragma unroll
    for (int mt = 0; mt < 4; mt++) {
        int r0 = 16 * mt + grp, r1 = r0 + 8;
        float a0 = s_gn[r0], c0 = s_gn[64 + r0];
        float a1 = s_gn[r1], c1 = s_gn[64 + r1];
#pragma unroll
        for (int nt = 0; nt < 4; nt++) {
            float v0 = fmaxf(fmaf(a0, C2[mt][nt][0], c0), 0.f);
            float v1 = fmaxf(fmaf(a0, C2[mt][nt][1], c0), 0.f);
            float v2 = fmaxf(fmaf(a1, C2[mt][nt][2], c1), 0.f);
            float v3 = fmaxf(fmaf(a1, C2[mt][nt][3], c1), 0.f);
            Bv[mt][nt][0] = movm(h2u(v0, v1));
            Bv[mt][nt][1] = movm(h2u(v2, v3));
        }
    }

    // ---- GEMM3: C3[o][col] = w2at * v + b2at (chained B) ----
    float C3[4][4][4];
#pragma unroll
    for (int mt = 0; mt < 4; mt++) {
        float b0 = s_bat[16 * mt + grp], b1 = s_bat[16 * mt + 8 + grp];
#pragma unroll
        for (int nt = 0; nt < 4; nt++) {
            C3[mt][nt][0] = b0; C3[mt][nt][1] = b0;
            C3[mt][nt][2] = b1; C3[mt][nt][3] = b1;
        }
    }
#pragma unroll
    for (int kt = 0; kt < 4; kt++) {
        unsigned Af[4][4];
#pragma unroll
        for (int mt = 0; mt < 4; mt++)
            ldsm4(Af[mt], ws3b + 2 * ((16 * mt + arow) * WSTR + 16 * kt + 8 * ahalf));
#pragma unroll
        for (int mt = 0; mt < 4; mt++)
#pragma unroll
            for (int nt = 0; nt < 4; nt++)
                mma16816(C3[mt][nt], Af[mt], Bv[kt][nt]);
    }

    // ---- masked store -> acth fp16 [o][col] ----
    {
        const int* mrow = mask + (size_t)b * MKn + colbase;
        int2 mv[4];
#pragma unroll
        for (int nt = 0; nt < 4; nt++)
            mv[nt] = *reinterpret_cast<const int2*>(mrow + n0 + 8 * nt + 2 * tig);
#pragma unroll
        for (int mt = 0; mt < 4; mt++) {
            int r0 = 16 * mt + grp, r1 = r0 + 8;
#pragma unroll
            for (int nt = 0; nt < 4; nt++) {
                int colL = n0 + 8 * nt + 2 * tig;
                bool m0 = mv[nt].x != 0, m1 = mv[nt].y != 0;
                float f0 = m0 ? C3[mt][nt][0] : -65504.f;
                float f1 = m1 ? C3[mt][nt][1] : -65504.f;
                float f2 = m0 ? C3[mt][nt][2] : -65504.f;
                float f3 = m1 ? C3[mt][nt][3] : -65504.f;
                *reinterpret_cast<unsigned*>(acth + r0 * ASTRH + colL) = h2u(f0, f1);
                *reinterpret_cast<unsigned*>(acth + r1 * ASTRH + colL) = h2u(f2, f3);
            }
        }
    }
    __syncthreads();

    // ---- per-(m,o) softmax units: 16 contiguous cols; pe from smem ----
    int mbase = colbase >> 4;      // 8 m per tile
#pragma unroll
    for (int r = 0; r < 4; r++) {
        int unit = r * 128 + t;    // 0..511
        int o = unit >> 3, ml = unit & 7;
        uint4 aw0 = *reinterpret_cast<const uint4*>(acth + o * ASTRH + 16 * ml);
        uint4 aw1 = *reinterpret_cast<const uint4*>(acth + o * ASTRH + 16 * ml + 8);
        float av[16];
        {
            float4 x;
            x = h4_to_f4(make_uint2(aw0.x, aw0.y));
            av[0] = x.x; av[1] = x.y; av[2] = x.z; av[3] = x.w;
            x = h4_to_f4(make_uint2(aw0.z, aw0.w));
            av[4] = x.x; av[5] = x.y; av[6] = x.z; av[7] = x.w;
            x = h4_to_f4(make_uint2(aw1.x, aw1.y));
            av[8] = x.x; av[9] = x.y; av[10] = x.z; av[11] = x.w;
            x = h4_to_f4(make_uint2(aw1.z, aw1.w));
            av[12] = x.x; av[13] = x.y; av[14] = x.z; av[15] = x.w;
        }
        float mx = av[0];
#pragma unroll
        for (int j = 1; j < 16; j++) mx = fmaxf(mx, av[j]);
        float s = 0.f;
#pragma unroll
        for (int j = 0; j < 16; j++) { av[j] = __expf(av[j] - mx); s += av[j]; }
        uint4 pw0 = *reinterpret_cast<const uint4*>(Pe_s + o * VSTR + 16 * ml);
        uint4 pw1 = *reinterpret_cast<const uint4*>(Pe_s + o * VSTR + 16 * ml + 8);
        float accum = 0.f;
        {
            float4 p;
            p = h4_to_f4(make_uint2(pw0.x, pw0.y));
            accum = fmaf(p.x, av[0], fmaf(p.y, av[1], fmaf(p.z, av[2], fmaf(p.w, av[3], accum))));
            p = h4_to_f4(make_uint2(pw0.z, pw0.w));
            accum = fmaf(p.x, av[4], fmaf(p.y, av[5], fmaf(p.z, av[6], fmaf(p.w, av[7], accum))));
            p = h4_to_f4(make_uint2(pw1.x, pw1.y));
            accum = fmaf(p.x, av[8], fmaf(p.y, av[9], fmaf(p.z, av[10], fmaf(p.w, av[11], accum))));
            p = h4_to_f4(make_uint2(pw1.z, pw1.w));
            accum = fmaf(p.x, av[12], fmaf(p.y, av[13], fmaf(p.z, av[14], fmaf(p.w, av[15], accum))));
        }
        out[((size_t)b * 64 + o) * Mn + mbase + ml] = accum * __fdividef(1.f, s);
    }
}

// ---------------- launch ----------------
extern "C" void kernel_launch(void* const* d_in, const int* in_sizes, int n_in,
                              void* d_out, int out_size) {
    const float* q_xyzs  = (const float*)d_in[0];
    const float* k_xyzs  = (const float*)d_in[1];
    const int*   knn_idx = (const int*)d_in[2];
    const int*   mask    = (const int*)d_in[3];
    const float* pe_w1   = (const float*)d_in[4];
    const float* pe_b1   = (const float*)d_in[5];
    const float* pe_g    = (const float*)d_in[6];
    const float* pe_be   = (const float*)d_in[7];
    const float* pe_w2   = (const float*)d_in[8];
    const float* pe_b2   = (const float*)d_in[9];
    const float* at_w1   = (const float*)d_in[10];
    const float* at_b1   = (const float*)d_in[11];
    const float* at_g    = (const float*)d_in[12];
    const float* at_be   = (const float*)d_in[13];
    const float* at_w2   = (const float*)d_in[14];
    const float* at_b2   = (const float*)d_in[15];
    float* out = (float*)d_out;

    static int smem_set = 0;
    if (!smem_set) {
        cudaFuncSetAttribute(k_pass2, cudaFuncAttributeMaxDynamicSharedMemorySize,
                             P2_TOTB);
        cudaFuncSetAttribute(k_pass3, cudaFuncAttributeMaxDynamicSharedMemorySize,
                             P3_TOTB);
        smem_set = 1;
    }

    k_prep<<<64, 64>>>(pe_w2, at_w1, at_w2);

    dim3 gcol(MKn / 128, Bn);
    k_pass1<<<gcol, 128>>>(q_xyzs, k_xyzs, knn_idx);
    k_fin1<<<1, 64>>>(pe_w1, pe_b1, pe_g, pe_be);

    k_pass2<<<gcol, 128, P2_TOTB>>>(q_xyzs, k_xyzs, knn_idx, pe_b2, at_b1);
    k_fin2<<<1, 64>>>(at_g, at_be);

    k_pass3<<<gcol, 128, P3_TOTB>>>(mask, at_b1, at_b2, out);
}

// round 15
// speedup vs baseline: 6.9557x; 1.0679x over previous
#include <cuda_runtime.h>
#include <cuda_fp16.h>
#include <math.h>
#include <float.h>

#define Bn   2
#define Mn   25000
#define Nn   100000
#define NGn  8
#define CPGn 8
#define GN_EPS 1e-5f
#define MKn  (Mn * 16)          // 400000 columns per batch

#define XLSTR 24                // fp16 lp-tile stride (halves)
#define WLSTR 24                // fp16 folded-w1 stride
#define WSTR 72                 // fp16 weight stride
#define VSTR 136                // fp16 pe stride in pass3 [o][col]
#define ASTRH 136               // fp16 attn stride in pass3 [o][col]

typedef unsigned long long u64;

// ---------------- device scratch ----------------
__device__ double g_m1[Bn][14];
__device__ double g_s2[Bn][NGn][2];
__device__ __align__(16) float g_b1pe_f[Bn][64];
__device__ __align__(16) __half g_w1pe_hf[Bn][1024]; // folded conv1_pe fp16 [o][16]
__device__ __align__(16) float g_gn2d[Bn][128];      // a2[64] | c2[64]
__device__ __align__(16) __half g_w2pe_h[4096];      // [o][k] fp16
__device__ __align__(16) __half g_w1at_h[4096];      // [o][k] fp16
__device__ __align__(16) __half g_w2at_h[4096];      // [o][k] fp16

// ---------------- scalar helpers ----------------
__device__ __forceinline__ float4 h4_to_f4(uint2 u) {
    __half2 a = *reinterpret_cast<__half2*>(&u.x);
    __half2 b = *reinterpret_cast<__half2*>(&u.y);
    float2 fa = __half22float2(a), fb = __half22float2(b);
    return make_float4(fa.x, fa.y, fb.x, fb.y);
}
__device__ __forceinline__ unsigned h2u(float a, float b) {
    __half2 h = __floats2half2_rn(a, b);
    return *reinterpret_cast<unsigned*>(&h);
}

// ---------------- tensor primitives ----------------
__device__ __forceinline__ void mma16816(float* c, const unsigned* a, const unsigned* b) {
    asm volatile(
        "mma.sync.aligned.m16n8k16.row.col.f32.f16.f16.f32 "
        "{%0,%1,%2,%3}, {%4,%5,%6,%7}, {%8,%9}, {%0,%1,%2,%3};\n"
        : "+f"(c[0]), "+f"(c[1]), "+f"(c[2]), "+f"(c[3])
        : "r"(a[0]), "r"(a[1]), "r"(a[2]), "r"(a[3]), "r"(b[0]), "r"(b[1]));
}
__device__ __forceinline__ void ldsm4(unsigned* r, unsigned addr) {
    asm volatile("ldmatrix.sync.aligned.m8n8.x4.shared.b16 {%0,%1,%2,%3}, [%4];"
        : "=r"(r[0]), "=r"(r[1]), "=r"(r[2]), "=r"(r[3]) : "r"(addr));
}
__device__ __forceinline__ unsigned movm(unsigned a) {
    unsigned d;
    asm volatile("movmatrix.sync.aligned.m8n8.trans.b16 %0, %1;" : "=r"(d) : "r"(a));
    return d;
}

// ---------------- misc helpers ----------------
__device__ __forceinline__ void compute_lp(const float* __restrict__ q,
                                           const float* __restrict__ kx,
                                           const int*   __restrict__ idx,
                                           int b, int c, float lp[4]) {
    int m  = c >> 4;
    int id = idx[b * MKn + c];
    float qx = q[(b * 3 + 0) * Mn + m];
    float qy = q[(b * 3 + 1) * Mn + m];
    float qz = q[(b * 3 + 2) * Mn + m];
    float px = kx[(b * 3 + 0) * Nn + id];
    float py = kx[(b * 3 + 1) * Nn + id];
    float pz = kx[(b * 3 + 2) * Nn + id];
    float ox = px - qx, oy = py - qy, oz = pz - qz;
    float d  = sqrtf(ox * ox + oy * oy + oz * oz);
    float r  = 1.0f / fmaxf(d, 1e-12f);
    lp[0] = ox * r; lp[1] = oy * r; lp[2] = oz * r; lp[3] = d;
}

__device__ __forceinline__ void stage_w(const __half* __restrict__ gsrc,
                                        __half* Ws, int t) {
#pragma unroll
    for (int id = t; id < 512; id += 128) {
        int row = id >> 3, c = id & 7;
        uint4 v = *reinterpret_cast<const uint4*>(gsrc + row * 64 + c * 8);
        *reinterpret_cast<uint4*>(Ws + row * WSTR + c * 8) = v;
    }
}

// ---------------- kernels ----------------
__global__ void k_prep(const float* __restrict__ w2pe,
                       const float* __restrict__ w1at,
                       const float* __restrict__ w2at) {
    int i = blockIdx.x;
    int j = threadIdx.x;
    g_w2pe_h[i * 64 + j] = __float2half(w2pe[i * 64 + j]);
    g_w1at_h[i * 64 + j] = __float2half(w1at[i * 64 + j]);
    g_w2at_h[i * 64 + j] = __float2half(w2at[i * 64 + j]);
    if (i == 0) {
        if (j < Bn * NGn * 2) ((double*)g_s2)[j] = 0.0;
        if (j < Bn * 14)      ((double*)g_m1)[j] = 0.0;
    }
}

__global__ __launch_bounds__(128) void k_pass1(const float* __restrict__ q,
                                               const float* __restrict__ kx,
                                               const int*   __restrict__ idx) {
    __shared__ float s_red[14];
    int t = threadIdx.x, b = blockIdx.y;
    if (t < 14) s_red[t] = 0.f;
    __syncthreads();
    int col = blockIdx.x * 128 + t;
    float lp[4];
    compute_lp(q, kx, idx, b, col, lp);

    float v[14];
    v[0] = lp[0]; v[1] = lp[1]; v[2] = lp[2]; v[3] = lp[3];
    {
        int n = 4;
#pragma unroll
        for (int c = 0; c < 4; c++)
#pragma unroll
            for (int d = c; d < 4; d++) v[n++] = lp[c] * lp[d];
    }
#pragma unroll
    for (int i = 0; i < 14; i++) {
        for (int off = 16; off; off >>= 1)
            v[i] += __shfl_down_sync(0xffffffffu, v[i], off);
        if ((t & 31) == 0) atomicAdd(&s_red[i], v[i]);
    }
    __syncthreads();
    if (t < 14) atomicAdd(&g_m1[b][t], (double)s_red[t]);
}

__global__ void k_fin1(const float* __restrict__ w1, const float* __restrict__ b1,
                       const float* __restrict__ gam, const float* __restrict__ bet) {
    __shared__ double gs[8], gq[8];
    int o = threadIdx.x;  // 64 threads
    double n = (double)CPGn * (double)MKn;
    for (int b = 0; b < Bn; b++) {
        if (o < 8) { gs[o] = 0.0; gq[o] = 0.0; }
        __syncthreads();
        double m[14];
#pragma unroll
        for (int i = 0; i < 14; i++) m[i] = g_m1[b][i];
        double M2[4][4];
        {
            int idx5 = 4;
            for (int c = 0; c < 4; c++)
                for (int d = c; d < 4; d++) {
                    M2[c][d] = m[idx5]; M2[d][c] = m[idx5]; idx5++;
                }
        }
        double w[4];
#pragma unroll
        for (int c = 0; c < 4; c++) w[c] = (double)w1[o * 4 + c];
        double bo = (double)b1[o];
        double dot = w[0] * m[0] + w[1] * m[1] + w[2] * m[2] + w[3] * m[3];
        double sum_o = dot + (double)MKn * bo;
        double sq_o = 0.0;
#pragma unroll
        for (int c = 0; c < 4; c++)
#pragma unroll
            for (int d = 0; d < 4; d++) sq_o += w[c] * w[d] * M2[c][d];
        sq_o += 2.0 * bo * dot + (double)MKn * bo * bo;
        atomicAdd(&gs[o >> 3], sum_o);
        atomicAdd(&gq[o >> 3], sq_o);
        __syncthreads();
        int g = o >> 3;
        double mean = gs[g] / n;
        double var  = gq[g] / n - mean * mean;
        float rstd  = (float)(1.0 / sqrt(var + (double)GN_EPS));
        float a  = gam[o] * rstd;
        float cc = bet[o] - (float)mean * a;
        g_b1pe_f[b][o] = fmaf(a, b1[o], cc);
        __half* wh = g_w1pe_hf[b] + o * 16;
        for (int c = 0; c < 4; c++) wh[c] = __float2half(a * w1[o * 4 + c]);
        for (int c = 4; c < 16; c++) wh[c] = __float2half(0.f);
        __syncthreads();
    }
}

// ---- pass2 smem (bytes) ----
#define P2_XLP   0                       // fp16 [128][XLSTR]  6144
#define P2_WLP   6144                    // 3072
#define P2_WS1   9216                    // 9216
#define P2_WS2   18432                   // 9216
#define P2_B1PE  27648
#define P2_B2PE  27904
#define P2_B1AT  28160
#define P2_RED   28416
#define P2_TOTB  28480

__global__ __launch_bounds__(128, 4) void k_pass2(const float* __restrict__ q,
                                                  const float* __restrict__ kx,
                                                  const int*   __restrict__ idx,
                                                  const float* __restrict__ b2pe,
                                                  const float* __restrict__ b1at) {
    extern __shared__ __align__(16) char smc[];
    __half* Xlp = reinterpret_cast<__half*>(smc + P2_XLP);
    __half* Wlp = reinterpret_cast<__half*>(smc + P2_WLP);
    __half* Ws1 = reinterpret_cast<__half*>(smc + P2_WS1);
    __half* Ws2 = reinterpret_cast<__half*>(smc + P2_WS2);
    float* s_b1pe = reinterpret_cast<float*>(smc + P2_B1PE);
    float* s_b2pe = reinterpret_cast<float*>(smc + P2_B2PE);
    float* s_b1at = reinterpret_cast<float*>(smc + P2_B1AT);
    float* s_red  = reinterpret_cast<float*>(smc + P2_RED);

    int t = threadIdx.x, b = blockIdx.y;
    int colbase = blockIdx.x * 128;
    int lane = t & 31, warp = t >> 5;
    int grp = lane >> 2;
    int n0 = warp * 32;

    stage_w(g_w2pe_h, Ws1, t);
    stage_w(g_w1at_h, Ws2, t);
    {
        int row = t >> 1, c = t & 1;
        uint4 v = *reinterpret_cast<const uint4*>(g_w1pe_hf[b] + row * 16 + c * 8);
        *reinterpret_cast<uint4*>(Wlp + row * WLSTR + c * 8) = v;
    }
    if (t < 64) {
        s_b1pe[t] = g_b1pe_f[b][t];
        s_b2pe[t] = b2pe[t];
        s_b1at[t] = b1at[t];
    }
    if (t < 16) s_red[t] = 0.f;

    {
        int col = colbase + t;
        float lp[4];
        compute_lp(q, kx, idx, b, col, lp);
        *reinterpret_cast<uint4*>(Xlp + t * XLSTR) =
            make_uint4(h2u(lp[0], lp[1]), h2u(lp[2], lp[3]), 0u, 0u);
        *reinterpret_cast<uint4*>(Xlp + t * XLSTR + 8) = make_uint4(0u, 0u, 0u, 0u);
    }
    __syncthreads();

    unsigned xlpb = (unsigned)__cvta_generic_to_shared(Xlp + (size_t)n0 * XLSTR);
    unsigned wlpb = (unsigned)__cvta_generic_to_shared(Wlp);
    unsigned ws1b = (unsigned)__cvta_generic_to_shared(Ws1);
    unsigned ws2b = (unsigned)__cvta_generic_to_shared(Ws2);
    int arow = lane & 15, ahalf = lane >> 4;
    int brow = (lane & 7) + ((lane >> 4) & 1) * 8;
    int bk   = ((lane >> 3) & 1) * 8;

    // ---- u-GEMM (K=16) ----
    float Cu[4][4][4];
#pragma unroll
    for (int mt = 0; mt < 4; mt++) {
        float b0 = s_b1pe[16 * mt + grp], b1 = s_b1pe[16 * mt + 8 + grp];
#pragma unroll
        for (int nt = 0; nt < 4; nt++) {
            Cu[mt][nt][0] = b0; Cu[mt][nt][1] = b0;
            Cu[mt][nt][2] = b1; Cu[mt][nt][3] = b1;
        }
    }
    {
        unsigned Af[4][4];
#pragma unroll
        for (int mt = 0; mt < 4; mt++)
            ldsm4(Af[mt], wlpb + 2 * ((16 * mt + arow) * WLSTR + 8 * ahalf));
#pragma unroll
        for (int ntp = 0; ntp < 2; ntp++) {
            unsigned Bf[4];
            ldsm4(Bf, xlpb + 2 * ((16 * ntp + brow) * XLSTR + bk));
#pragma unroll
            for (int mt = 0; mt < 4; mt++) {
                mma16816(Cu[mt][2 * ntp],     Af[mt], Bf);
                mma16816(Cu[mt][2 * ntp + 1], Af[mt], Bf + 2);
            }
        }
    }
    unsigned Bu[4][4][2];
#pragma unroll
    for (int mt = 0; mt < 4; mt++)
#pragma unroll
        for (int nt = 0; nt < 4; nt++) {
            Bu[mt][nt][0] = movm(h2u(fmaxf(Cu[mt][nt][0], 0.f), fmaxf(Cu[mt][nt][1], 0.f)));
            Bu[mt][nt][1] = movm(h2u(fmaxf(Cu[mt][nt][2], 0.f), fmaxf(Cu[mt][nt][3], 0.f)));
        }

    // ---- GEMM1 (chained B) ----
    float C1[4][4][4];
#pragma unroll
    for (int mt = 0; mt < 4; mt++) {
        float b0 = s_b2pe[16 * mt + grp], b1 = s_b2pe[16 * mt + 8 + grp];
#pragma unroll
        for (int nt = 0; nt < 4; nt++) {
            C1[mt][nt][0] = b0; C1[mt][nt][1] = b0;
            C1[mt][nt][2] = b1; C1[mt][nt][3] = b1;
        }
    }
#pragma unroll
    for (int kt = 0; kt < 4; kt++) {
        unsigned Af[4][4];
#pragma unroll
        for (int mt = 0; mt < 4; mt++)
            ldsm4(Af[mt], ws1b + 2 * ((16 * mt + arow) * WSTR + 16 * kt + 8 * ahalf));
#pragma unroll
        for (int mt = 0; mt < 4; mt++)
#pragma unroll
            for (int nt = 0; nt < 4; nt++)
                mma16816(C1[mt][nt], Af[mt], Bu[kt][nt]);
    }

    // ---- movm chain (no global store) ----
    unsigned Bc[4][4][2];
#pragma unroll
    for (int mt = 0; mt < 4; mt++)
#pragma unroll
        for (int nt = 0; nt < 4; nt++) {
            Bc[mt][nt][0] = movm(h2u(C1[mt][nt][0], C1[mt][nt][1]));
            Bc[mt][nt][1] = movm(h2u(C1[mt][nt][2], C1[mt][nt][3]));
        }

    // ---- GEMM2 (stats only) ----
    float C2[4][4][4];
#pragma unroll
    for (int mt = 0; mt < 4; mt++) {
        float b0 = s_b1at[16 * mt + grp], b1 = s_b1at[16 * mt + 8 + grp];
#pragma unroll
        for (int nt = 0; nt < 4; nt++) {
            C2[mt][nt][0] = b0; C2[mt][nt][1] = b0;
            C2[mt][nt][2] = b1; C2[mt][nt][3] = b1;
        }
    }
#pragma unroll
    for (int kt = 0; kt < 4; kt++) {
        unsigned Af[4][4];
#pragma unroll
        for (int mt = 0; mt < 4; mt++)
            ldsm4(Af[mt], ws2b + 2 * ((16 * mt + arow) * WSTR + 16 * kt + 8 * ahalf));
#pragma unroll
        for (int mt = 0; mt < 4; mt++)
#pragma unroll
            for (int nt = 0; nt < 4; nt++)
                mma16816(C2[mt][nt], Af[mt], Bc[kt][nt]);
    }

    // ---- GN2 stats from C2 fragments ----
    {
        float gs[8], gq[8];
#pragma unroll
        for (int g = 0; g < 8; g++) { gs[g] = 0.f; gq[g] = 0.f; }
#pragma unroll
        for (int mt = 0; mt < 4; mt++) {
#pragma unroll
            for (int nt = 0; nt < 4; nt++) {
                float v0 = C2[mt][nt][0], v1 = C2[mt][nt][1];
                float v2 = C2[mt][nt][2], v3 = C2[mt][nt][3];
                gs[2 * mt]     += v0 + v1;
                gq[2 * mt]     = fmaf(v0, v0, fmaf(v1, v1, gq[2 * mt]));
                gs[2 * mt + 1] += v2 + v3;
                gq[2 * mt + 1] = fmaf(v2, v2, fmaf(v3, v3, gq[2 * mt + 1]));
            }
        }
        float r[16];
#pragma unroll
        for (int g = 0; g < 8; g++) { r[g] = gs[g]; r[8 + g] = gq[g]; }
#pragma unroll
        for (int i = 0; i < 16; i++)
            for (int off = 16; off; off >>= 1)
                r[i] += __shfl_down_sync(0xffffffffu, r[i], off);
        if (lane == 0) {
#pragma unroll
            for (int i = 0; i < 16; i++) atomicAdd(&s_red[i], r[i]);
        }
    }
    __syncthreads();
    if (t < 16) atomicAdd(&g_s2[b][t & 7][t >> 3], (double)s_red[t]);
}

__global__ void k_fin2(const float* __restrict__ gam, const float* __restrict__ bet) {
    int o = threadIdx.x;  // 64 threads
    double n = (double)CPGn * (double)MKn;
    for (int b = 0; b < Bn; b++) {
        int g = o >> 3;
        double s = g_s2[b][g][0], sq = g_s2[b][g][1];
        double mean = s / n;
        double var  = sq / n - mean * mean;
        float rstd  = (float)(1.0 / sqrt(var + (double)GN_EPS));
        float a  = gam[o] * rstd;
        float cc = bet[o] - (float)mean * a;
        g_gn2d[b][o]      = a;
        g_gn2d[b][64 + o] = cc;
    }
}

// ---- pass3 smem (bytes): acth overlays Xlp/Wlp/Ws1 (dead after GEMM1) ----
#define P3_XLP   0                       // 6144
#define P3_WLP   6144                    // 3072
#define P3_WS1   9216                    // 9216 -> ends 18432
#define P3_ACT   0                       // fp16 [64][ASTRH] 17408 (overlay)
#define P3_WS2   18432                   // 9216
#define P3_WS3   27648                   // 9216
#define P3_PE    36864                   // fp16 [64][VSTR] 17408
#define P3_GN    54272                   // fp32 128
#define P3_B1PE  54784
#define P3_B2PE  55040
#define P3_B1AT  55296
#define P3_BAT   55552
#define P3_TOTB  55808

__global__ __launch_bounds__(128, 4) void k_pass3(const float* __restrict__ q,
                                                  const float* __restrict__ kx,
                                                  const int*   __restrict__ idx,
                                                  const int*   __restrict__ mask,
                                                  const float* __restrict__ b2pe,
                                                  const float* __restrict__ b1at,
                                                  const float* __restrict__ b2at,
                                                  float* __restrict__ out) {
    extern __shared__ __align__(16) char smc[];
    __half* Xlp   = reinterpret_cast<__half*>(smc + P3_XLP);
    __half* Wlp   = reinterpret_cast<__half*>(smc + P3_WLP);
    __half* Ws1   = reinterpret_cast<__half*>(smc + P3_WS1);
    __half* acth  = reinterpret_cast<__half*>(smc + P3_ACT);
    __half* Ws2   = reinterpret_cast<__half*>(smc + P3_WS2);
    __half* Ws3   = reinterpret_cast<__half*>(smc + P3_WS3);
    __half* Pe_s  = reinterpret_cast<__half*>(smc + P3_PE);
    float* s_gn   = reinterpret_cast<float*>(smc + P3_GN);
    float* s_b1pe = reinterpret_cast<float*>(smc + P3_B1PE);
    float* s_b2pe = reinterpret_cast<float*>(smc + P3_B2PE);
    float* s_b1at = reinterpret_cast<float*>(smc + P3_B1AT);
    float* s_bat  = reinterpret_cast<float*>(smc + P3_BAT);

    int t = threadIdx.x, b = blockIdx.y;
    int colbase = blockIdx.x * 128;
    int lane = t & 31, warp = t >> 5;
    int grp = lane >> 2, tig = lane & 3;
    int n0 = warp * 32;

    stage_w(g_w2pe_h, Ws1, t);
    stage_w(g_w1at_h, Ws2, t);
    stage_w(g_w2at_h, Ws3, t);
    {
        int row = t >> 1, c = t & 1;
        uint4 v = *reinterpret_cast<const uint4*>(g_w1pe_hf[b] + row * 16 + c * 8);
        *reinterpret_cast<uint4*>(Wlp + row * WLSTR + c * 8) = v;
    }
    s_gn[t] = g_gn2d[b][t];
    if (t < 64) {
        s_b1pe[t] = g_b1pe_f[b][t];
        s_b2pe[t] = b2pe[t];
        s_b1at[t] = b1at[t];
        s_bat[t]  = b2at[t];
    }
    {
        int col = colbase + t;
        float lp[4];
        compute_lp(q, kx, idx, b, col, lp);
        *reinterpret_cast<uint4*>(Xlp + t * XLSTR) =
            make_uint4(h2u(lp[0], lp[1]), h2u(lp[2], lp[3]), 0u, 0u);
        *reinterpret_cast<uint4*>(Xlp + t * XLSTR + 8) = make_uint4(0u, 0u, 0u, 0u);
    }
    __syncthreads();

    unsigned xlpb = (unsigned)__cvta_generic_to_shared(Xlp + (size_t)n0 * XLSTR);
    unsigned wlpb = (unsigned)__cvta_generic_to_shared(Wlp);
    unsigned ws1b = (unsigned)__cvta_generic_to_shared(Ws1);
    unsigned ws2b = (unsigned)__cvta_generic_to_shared(Ws2);
    unsigned ws3b = (unsigned)__cvta_generic_to_shared(Ws3);
    int arow = lane & 15, ahalf = lane >> 4;
    int brow = (lane & 7) + ((lane >> 4) & 1) * 8;
    int bk   = ((lane >> 3) & 1) * 8;

    // ---- u-GEMM (K=16) ----
    float Cu[4][4][4];
#pragma unroll
    for (int mt = 0; mt < 4; mt++) {
        float b0 = s_b1pe[16 * mt + grp], b1 = s_b1pe[16 * mt + 8 + grp];
#pragma unroll
        for (int nt = 0; nt < 4; nt++) {
            Cu[mt][nt][0] = b0; Cu[mt][nt][1] = b0;
            Cu[mt][nt][2] = b1; Cu[mt][nt][3] = b1;
        }
    }
    {
        unsigned Af[4][4];
#pragma unroll
        for (int mt = 0; mt < 4; mt++)
            ldsm4(Af[mt], wlpb + 2 * ((16 * mt + arow) * WLSTR + 8 * ahalf));
#pragma unroll
        for (int ntp = 0; ntp < 2; ntp++) {
            unsigned Bf[4];
            ldsm4(Bf, xlpb + 2 * ((16 * ntp + brow) * XLSTR + bk));
#pragma unroll
            for (int mt = 0; mt < 4; mt++) {
                mma16816(Cu[mt][2 * ntp],     Af[mt], Bf);
                mma16816(Cu[mt][2 * ntp + 1], Af[mt], Bf + 2);
            }
        }
    }
    unsigned Bu[4][4][2];
#pragma unroll
    for (int mt = 0; mt < 4; mt++)
#pragma unroll
        for (int nt = 0; nt < 4; nt++) {
            Bu[mt][nt][0] = movm(h2u(fmaxf(Cu[mt][nt][0], 0.f), fmaxf(Cu[mt][nt][1], 0.f)));
            Bu[mt][nt][1] = movm(h2u(fmaxf(Cu[mt][nt][2], 0.f), fmaxf(Cu[mt][nt][3], 0.f)));
        }

    // ---- GEMM1 (chained B) -> pe ----
    float C1[4][4][4];
#pragma unroll
    for (int mt = 0; mt < 4; mt++) {
        float b0 = s_b2pe[16 * mt + grp], b1 = s_b2pe[16 * mt + 8 + grp];
#pragma unroll
        for (int nt = 0; nt < 4; nt++) {
            C1[mt][nt][0] = b0; C1[mt][nt][1] = b0;
            C1[mt][nt][2] = b1; C1[mt][nt][3] = b1;
        }
    }
#pragma unroll
    for (int kt = 0; kt < 4; kt++) {
        unsigned Af[4][4];
#pragma unroll
        for (int mt = 0; mt < 4; mt++)
            ldsm4(Af[mt], ws1b + 2 * ((16 * mt + arow) * WSTR + 16 * kt + 8 * ahalf));
#pragma unroll
        for (int mt = 0; mt < 4; mt++)
#pragma unroll
            for (int nt = 0; nt < 4; nt++)
                mma16816(C1[mt][nt], Af[mt], Bu[kt][nt]);
    }

    // ---- pe -> Pe_s smem + movm chain ----
    unsigned Bc[4][4][2];
#pragma unroll
    for (int mt = 0; mt < 4; mt++) {
        int r0 = 16 * mt + grp, r1 = r0 + 8;
#pragma unroll
        for (int nt = 0; nt < 4; nt++) {
            int colL = n0 + 8 * nt + 2 * tig;
            unsigned p01 = h2u(C1[mt][nt][0], C1[mt][nt][1]);
            unsigned p23 = h2u(C1[mt][nt][2], C1[mt][nt][3]);
            *reinterpret_cast<unsigned*>(Pe_s + r0 * VSTR + colL) = p01;
            *reinterpret_cast<unsigned*>(Pe_s + r1 * VSTR + colL) = p23;
            Bc[mt][nt][0] = movm(p01);
            Bc[mt][nt][1] = movm(p23);
        }
    }
    __syncthreads();   // all Xlp/Wlp/Ws1 reads done before acth overlay writes

    // ---- GEMM2 (chained B) ----
    float C2[4][4][4];
#pragma unroll
    for (int mt = 0; mt < 4; mt++) {
        float b0 = s_b1at[16 * mt + grp], b1 = s_b1at[16 * mt + 8 + grp];
#pragma unroll
        for (int nt = 0; nt < 4; nt++) {
            C2[mt][nt][0] = b0; C2[mt][nt][1] = b0;
            C2[mt][nt][2] = b1; C2[mt][nt][3] = b1;
        }
    }
#pragma unroll
    for (int kt = 0; kt < 4; kt++) {
        unsigned Af[4][4];
#pragma unroll
        for (int mt = 0; mt < 4; mt++)
            ldsm4(Af[mt], ws2b + 2 * ((16 * mt + arow) * WSTR + 16 * kt + 8 * ahalf));
#pragma unroll
        for (int mt = 0; mt < 4; mt++)
#pragma unroll
            for (int nt = 0; nt < 4; nt++)
                mma16816(C2[mt][nt], Af[mt], Bc[kt][nt]);
    }

    // ---- GN2 fold + relu -> movm chain ----
    unsigned Bv[4][4][2];
#pragma unroll
    for (int mt = 0; mt < 4; mt++) {
        int r0 = 16 * mt + grp, r1 = r0 + 8;
        float a0 = s_gn[r0], c0 = s_gn[64 + r0];
        float a1 = s_gn[r1], c1 = s_gn[64 + r1];
#pragma unroll
        for (int nt = 0; nt < 4; nt++) {
            float v0 = fmaxf(fmaf(a0, C2[mt][nt][0], c0), 0.f);
            float v1 = fmaxf(fmaf(a0, C2[mt][nt][1], c0), 0.f);
            float v2 = fmaxf(fmaf(a1, C2[mt][nt][2], c1), 0.f);
            float v3 = fmaxf(fmaf(a1, C2[mt][nt][3], c1), 0.f);
            Bv[mt][nt][0] = movm(h2u(v0, v1));
            Bv[mt][nt][1] = movm(h2u(v2, v3));
        }
    }

    // ---- GEMM3 (chained B) ----
    float C3[4][4][4];
#pragma unroll
    for (int mt = 0; mt < 4; mt++) {
        float b0 = s_bat[16 * mt + grp], b1 = s_bat[16 * mt + 8 + grp];
#pragma unroll
        for (int nt = 0; nt < 4; nt++) {
            C3[mt][nt][0] = b0; C3[mt][nt][1] = b0;
            C3[mt][nt][2] = b1; C3[mt][nt][3] = b1;
        }
    }
#pragma unroll
    for (int kt = 0; kt < 4; kt++) {
        unsigned Af[4][4];
#pragma unroll
        for (int mt = 0; mt < 4; mt++)
            ldsm4(Af[mt], ws3b + 2 * ((16 * mt + arow) * WSTR + 16 * kt + 8 * ahalf));
#pragma unroll
        for (int mt = 0; mt < 4; mt++)
#pragma unroll
            for (int nt = 0; nt < 4; nt++)
                mma16816(C3[mt][nt], Af[mt], Bv[kt][nt]);
    }

    // ---- masked store -> acth fp16 [o][col] ----
    {
        const int* mrow = mask + (size_t)b * MKn + colbase;
        int2 mv[4];
#pragma unroll
        for (int nt = 0; nt < 4; nt++)
            mv[nt] = *reinterpret_cast<const int2*>(mrow + n0 + 8 * nt + 2 * tig);
#pragma unroll
        for (int mt = 0; mt < 4; mt++) {
            int r0 = 16 * mt + grp, r1 = r0 + 8;
#pragma unroll
            for (int nt = 0; nt < 4; nt++) {
                int colL = n0 + 8 * nt + 2 * tig;
                bool m0 = mv[nt].x != 0, m1 = mv[nt].y != 0;
                float f0 = m0 ? C3[mt][nt][0] : -65504.f;
                float f1 = m1 ? C3[mt][nt][1] : -65504.f;
                float f2 = m0 ? C3[mt][nt][2] : -65504.f;
                float f3 = m1 ? C3[mt][nt][3] : -65504.f;
                *reinterpret_cast<unsigned*>(acth + r0 * ASTRH + colL) = h2u(f0, f1);
                *reinterpret_cast<unsigned*>(acth + r1 * ASTRH + colL) = h2u(f2, f3);
            }
        }
    }
    __syncthreads();

    // ---- per-(m,o) softmax units; pe from Pe_s smem ----
    int mbase = colbase >> 4;      // 8 m per tile
#pragma unroll
    for (int r = 0; r < 4; r++) {
        int unit = r * 128 + t;    // 0..511
        int o = unit >> 3, ml = unit & 7;
        uint4 aw0 = *reinterpret_cast<const uint4*>(acth + o * ASTRH + 16 * ml);
        uint4 aw1 = *reinterpret_cast<const uint4*>(acth + o * ASTRH + 16 * ml + 8);
        float av[16];
        {
            float4 x;
            x = h4_to_f4(make_uint2(aw0.x, aw0.y));
            av[0] = x.x; av[1] = x.y; av[2] = x.z; av[3] = x.w;
            x = h4_to_f4(make_uint2(aw0.z, aw0.w));
            av[4] = x.x; av[5] = x.y; av[6] = x.z; av[7] = x.w;
            x = h4_to_f4(make_uint2(aw1.x, aw1.y));
            av[8] = x.x; av[9] = x.y; av[10] = x.z; av[11] = x.w;
            x = h4_to_f4(make_uint2(aw1.z, aw1.w));
            av[12] = x.x; av[13] = x.y; av[14] = x.z; av[15] = x.w;
        }
        float mx = av[0];
#pragma unroll
        for (int j = 1; j < 16; j++) mx = fmaxf(mx, av[j]);
        float s = 0.f;
#pragma unroll
        for (int j = 0; j < 16; j++) { av[j] = __expf(av[j] - mx); s += av[j]; }
        uint4 pw0 = *reinterpret_cast<const uint4*>(Pe_s + o * VSTR + 16 * ml);
        uint4 pw1 = *reinterpret_cast<const uint4*>(Pe_s + o * VSTR + 16 * ml + 8);
        float accum = 0.f;
        {
            float4 p;
            p = h4_to_f4(make_uint2(pw0.x, pw0.y));
            accum = fmaf(p.x, av[0], fmaf(p.y, av[1], fmaf(p.z, av[2], fmaf(p.w, av[3], accum))));
            p = h4_to_f4(make_uint2(pw0.z, pw0.w));
            accum = fmaf(p.x, av[4], fmaf(p.y, av[5], fmaf(p.z, av[6], fmaf(p.w, av[7], accum))));
            p = h4_to_f4(make_uint2(pw1.x, pw1.y));
            accum = fmaf(p.x, av[8], fmaf(p.y, av[9], fmaf(p.z, av[10], fmaf(p.w, av[11], accum))));
            p = h4_to_f4(make_uint2(pw1.z, pw1.w));
            accum = fmaf(p.x, av[12], fmaf(p.y, av[13], fmaf(p.z, av[14], fmaf(p.w, av[15], accum))));
        }
        out[((size_t)b * 64 + o) * Mn + mbase + ml] = accum * __fdividef(1.f, s);
    }
}

// ---------------- launch ----------------
extern "C" void kernel_launch(void* const* d_in, const int* in_sizes, int n_in,
                              void* d_out, int out_size) {
    const float* q_xyzs  = (const float*)d_in[0];
    const float* k_xyzs  = (const float*)d_in[1];
    const int*   knn_idx = (const int*)d_in[2];
    const int*   mask    = (const int*)d_in[3];
    const float* pe_w1   = (const float*)d_in[4];
    const float* pe_b1   = (const float*)d_in[5];
    const float* pe_g    = (const float*)d_in[6];
    const float* pe_be   = (const float*)d_in[7];
    const float* pe_w2   = (const float*)d_in[8];
    const float* pe_b2   = (const float*)d_in[9];
    const float* at_w1   = (const float*)d_in[10];
    const float* at_b1   = (const float*)d_in[11];
    const float* at_g    = (const float*)d_in[12];
    const float* at_be   = (const float*)d_in[13];
    const float* at_w2   = (const float*)d_in[14];
    const float* at_b2   = (const float*)d_in[15];
    float* out = (float*)d_out;

    static int smem_set = 0;
    if (!smem_set) {
        cudaFuncSetAttribute(k_pass2, cudaFuncAttributeMaxDynamicSharedMemorySize,
                             P2_TOTB);
        cudaFuncSetAttribute(k_pass3, cudaFuncAttributeMaxDynamicSharedMemorySize,
                             P3_TOTB);
        smem_set = 1;
    }

    k_prep<<<64, 64>>>(pe_w2, at_w1, at_w2);

    dim3 gcol(MKn / 128, Bn);
    k_pass1<<<gcol, 128>>>(q_xyzs, k_xyzs, knn_idx);
    k_fin1<<<1, 64>>>(pe_w1, pe_b1, pe_g, pe_be);

    k_pass2<<<gcol, 128, P2_TOTB>>>(q_xyzs, k_xyzs, knn_idx, pe_b2, at_b1);
    k_fin2<<<1, 64>>>(at_g, at_be);

    k_pass3<<<gcol, 128, P3_TOTB>>>(q_xyzs, k_xyzs, knn_idx, mask,
                                    pe_b2, at_b1, at_b2, out);
}

// round 16
// speedup vs baseline: 7.7749x; 1.1178x over previous
#include <cuda_runtime.h>
#include <cuda_fp16.h>
#include <math.h>
#include <float.h>

#define Bn   2
#define Mn   25000
#define Nn   100000
#define NGn  8
#define CPGn 8
#define GN_EPS 1e-5f
#define MKn  (Mn * 16)          // 400000 columns per batch

#define XLSTR 24                // fp16 lp-tile stride (halves)
#define WLSTR 24                // fp16 folded-w1 stride
#define WSTR 72                 // fp16 weight stride
#define VSTR 136                // fp16 pe stride in pass3 [o][col]
#define ASTRH 136               // fp16 attn stride in pass3 [o][col]

typedef unsigned long long u64;

// ---------------- device scratch ----------------
__device__ double g_m1[Bn][14];
__device__ double g_s2[Bn][NGn][2];
__device__ __align__(16) float g_b1pe_f[Bn][64];
__device__ __align__(16) __half g_w1pe_hf[Bn][1024]; // folded conv1_pe fp16 [o][16]
__device__ __align__(16) float g_gn2d[Bn][128];      // a2[64] | c2[64]
__device__ __align__(16) __half g_w2pe_h[4096];      // [o][k] fp16
__device__ __align__(16) __half g_w1at_h[4096];      // [o][k] fp16
__device__ __align__(16) __half g_w2at_h[4096];      // [o][k] fp16

// ---------------- scalar helpers ----------------
__device__ __forceinline__ float4 h4_to_f4(uint2 u) {
    __half2 a = *reinterpret_cast<__half2*>(&u.x);
    __half2 b = *reinterpret_cast<__half2*>(&u.y);
    float2 fa = __half22float2(a), fb = __half22float2(b);
    return make_float4(fa.x, fa.y, fb.x, fb.y);
}
__device__ __forceinline__ unsigned h2u(float a, float b) {
    __half2 h = __floats2half2_rn(a, b);
    return *reinterpret_cast<unsigned*>(&h);
}

// ---------------- tensor primitives ----------------
__device__ __forceinline__ void mma16816(float* c, const unsigned* a, const unsigned* b) {
    asm volatile(
        "mma.sync.aligned.m16n8k16.row.col.f32.f16.f16.f32 "
        "{%0,%1,%2,%3}, {%4,%5,%6,%7}, {%8,%9}, {%0,%1,%2,%3};\n"
        : "+f"(c[0]), "+f"(c[1]), "+f"(c[2]), "+f"(c[3])
        : "r"(a[0]), "r"(a[1]), "r"(a[2]), "r"(a[3]), "r"(b[0]), "r"(b[1]));
}
__device__ __forceinline__ void ldsm4(unsigned* r, unsigned addr) {
    asm volatile("ldmatrix.sync.aligned.m8n8.x4.shared.b16 {%0,%1,%2,%3}, [%4];"
        : "=r"(r[0]), "=r"(r[1]), "=r"(r[2]), "=r"(r[3]) : "r"(addr));
}
__device__ __forceinline__ unsigned movm(unsigned a) {
    unsigned d;
    asm volatile("movmatrix.sync.aligned.m8n8.trans.b16 %0, %1;" : "=r"(d) : "r"(a));
    return d;
}

// ---------------- misc helpers ----------------
__device__ __forceinline__ void compute_lp(const float* __restrict__ q,
                                           const float* __restrict__ kx,
                                           const int*   __restrict__ idx,
                                           int b, int c, float lp[4]) {
    int m  = c >> 4;
    int id = idx[b * MKn + c];
    float qx = q[(b * 3 + 0) * Mn + m];
    float qy = q[(b * 3 + 1) * Mn + m];
    float qz = q[(b * 3 + 2) * Mn + m];
    float px = kx[(b * 3 + 0) * Nn + id];
    float py = kx[(b * 3 + 1) * Nn + id];
    float pz = kx[(b * 3 + 2) * Nn + id];
    float ox = px - qx, oy = py - qy, oz = pz - qz;
    float d  = sqrtf(ox * ox + oy * oy + oz * oz);
    float r  = 1.0f / fmaxf(d, 1e-12f);
    lp[0] = ox * r; lp[1] = oy * r; lp[2] = oz * r; lp[3] = d;
}

__device__ __forceinline__ void stage_w(const __half* __restrict__ gsrc,
                                        __half* Ws, int t) {
#pragma unroll
    for (int id = t; id < 512; id += 128) {
        int row = id >> 3, c = id & 7;
        uint4 v = *reinterpret_cast<const uint4*>(gsrc + row * 64 + c * 8);
        *reinterpret_cast<uint4*>(Ws + row * WSTR + c * 8) = v;
    }
}

// ---------------- kernels ----------------
__global__ void k_prep(const float* __restrict__ w2pe,
                       const float* __restrict__ w1at,
                       const float* __restrict__ w2at) {
    int i = blockIdx.x;
    int j = threadIdx.x;
    g_w2pe_h[i * 64 + j] = __float2half(w2pe[i * 64 + j]);
    g_w1at_h[i * 64 + j] = __float2half(w1at[i * 64 + j]);
    g_w2at_h[i * 64 + j] = __float2half(w2at[i * 64 + j]);
    if (i == 0) {
        if (j < Bn * NGn * 2) ((double*)g_s2)[j] = 0.0;
        if (j < Bn * 14)      ((double*)g_m1)[j] = 0.0;
    }
}

// pass1: lp moments, 5 columns per thread (block covers 640 cols)
__global__ __launch_bounds__(128) void k_pass1(const float* __restrict__ q,
                                               const float* __restrict__ kx,
                                               const int*   __restrict__ idx) {
    __shared__ float s_red[14];
    int t = threadIdx.x, b = blockIdx.y;
    if (t < 14) s_red[t] = 0.f;
    __syncthreads();

    float v[14];
#pragma unroll
    for (int i = 0; i < 14; i++) v[i] = 0.f;

    int base = blockIdx.x * 640 + t;
#pragma unroll
    for (int i = 0; i < 5; i++) {
        int col = base + i * 128;
        float lp[4];
        compute_lp(q, kx, idx, b, col, lp);
        v[0] += lp[0]; v[1] += lp[1]; v[2] += lp[2]; v[3] += lp[3];
        int n = 4;
#pragma unroll
        for (int c = 0; c < 4; c++)
#pragma unroll
            for (int d = c; d < 4; d++) v[n++] += lp[c] * lp[d];
    }
#pragma unroll
    for (int i = 0; i < 14; i++) {
        for (int off = 16; off; off >>= 1)
            v[i] += __shfl_down_sync(0xffffffffu, v[i], off);
        if ((t & 31) == 0) atomicAdd(&s_red[i], v[i]);
    }
    __syncthreads();
    if (t < 14) atomicAdd(&g_m1[b][t], (double)s_red[t]);
}

__global__ void k_fin1(const float* __restrict__ w1, const float* __restrict__ b1,
                       const float* __restrict__ gam, const float* __restrict__ bet) {
    __shared__ double gs[8], gq[8];
    int o = threadIdx.x;  // 64 threads
    double n = (double)CPGn * (double)MKn;
    for (int b = 0; b < Bn; b++) {
        if (o < 8) { gs[o] = 0.0; gq[o] = 0.0; }
        __syncthreads();
        double m[14];
#pragma unroll
        for (int i = 0; i < 14; i++) m[i] = g_m1[b][i];
        double M2[4][4];
        {
            int idx5 = 4;
            for (int c = 0; c < 4; c++)
                for (int d = c; d < 4; d++) {
                    M2[c][d] = m[idx5]; M2[d][c] = m[idx5]; idx5++;
                }
        }
        double w[4];
#pragma unroll
        for (int c = 0; c < 4; c++) w[c] = (double)w1[o * 4 + c];
        double bo = (double)b1[o];
        double dot = w[0] * m[0] + w[1] * m[1] + w[2] * m[2] + w[3] * m[3];
        double sum_o = dot + (double)MKn * bo;
        double sq_o = 0.0;
#pragma unroll
        for (int c = 0; c < 4; c++)
#pragma unroll
            for (int d = 0; d < 4; d++) sq_o += w[c] * w[d] * M2[c][d];
        sq_o += 2.0 * bo * dot + (double)MKn * bo * bo;
        atomicAdd(&gs[o >> 3], sum_o);
        atomicAdd(&gq[o >> 3], sq_o);
        __syncthreads();
        int g = o >> 3;
        double mean = gs[g] / n;
        double var  = gq[g] / n - mean * mean;
        float rstd  = (float)(1.0 / sqrt(var + (double)GN_EPS));
        float a  = gam[o] * rstd;
        float cc = bet[o] - (float)mean * a;
        g_b1pe_f[b][o] = fmaf(a, b1[o], cc);
        __half* wh = g_w1pe_hf[b] + o * 16;
        for (int c = 0; c < 4; c++) wh[c] = __float2half(a * w1[o * 4 + c]);
        for (int c = 4; c < 16; c++) wh[c] = __float2half(0.f);
        __syncthreads();
    }
}

// ---- pass2 smem (bytes) ----
#define P2_XLP   0                       // fp16 [128][XLSTR]  6144
#define P2_WLP   6144                    // 3072
#define P2_WS1   9216                    // 9216
#define P2_WS2   18432                   // 9216
#define P2_B1PE  27648
#define P2_B2PE  27904
#define P2_B1AT  28160
#define P2_RED   28416
#define P2_TOTB  28480

__global__ __launch_bounds__(128, 4) void k_pass2(const float* __restrict__ q,
                                                  const float* __restrict__ kx,
                                                  const int*   __restrict__ idx,
                                                  const float* __restrict__ b2pe,
                                                  const float* __restrict__ b1at) {
    extern __shared__ __align__(16) char smc[];
    __half* Xlp = reinterpret_cast<__half*>(smc + P2_XLP);
    __half* Wlp = reinterpret_cast<__half*>(smc + P2_WLP);
    __half* Ws1 = reinterpret_cast<__half*>(smc + P2_WS1);
    __half* Ws2 = reinterpret_cast<__half*>(smc + P2_WS2);
    float* s_b1pe = reinterpret_cast<float*>(smc + P2_B1PE);
    float* s_b2pe = reinterpret_cast<float*>(smc + P2_B2PE);
    float* s_b1at = reinterpret_cast<float*>(smc + P2_B1AT);
    float* s_red  = reinterpret_cast<float*>(smc + P2_RED);

    int t = threadIdx.x, b = blockIdx.y;
    int colbase = blockIdx.x * 128;
    int lane = t & 31, warp = t >> 5;
    int grp = lane >> 2;
    int n0 = warp * 32;

    stage_w(g_w2pe_h, Ws1, t);
    stage_w(g_w1at_h, Ws2, t);
    {
        int row = t >> 1, c = t & 1;
        uint4 v = *reinterpret_cast<const uint4*>(g_w1pe_hf[b] + row * 16 + c * 8);
        *reinterpret_cast<uint4*>(Wlp + row * WLSTR + c * 8) = v;
    }
    if (t < 64) {
        s_b1pe[t] = g_b1pe_f[b][t];
        s_b2pe[t] = b2pe[t];
        s_b1at[t] = b1at[t];
    }
    if (t < 16) s_red[t] = 0.f;

    {
        int col = colbase + t;
        float lp[4];
        compute_lp(q, kx, idx, b, col, lp);
        *reinterpret_cast<uint4*>(Xlp + t * XLSTR) =
            make_uint4(h2u(lp[0], lp[1]), h2u(lp[2], lp[3]), 0u, 0u);
        *reinterpret_cast<uint4*>(Xlp + t * XLSTR + 8) = make_uint4(0u, 0u, 0u, 0u);
    }
    __syncthreads();

    unsigned xlpb = (unsigned)__cvta_generic_to_shared(Xlp + (size_t)n0 * XLSTR);
    unsigned wlpb = (unsigned)__cvta_generic_to_shared(Wlp);
    unsigned ws1b = (unsigned)__cvta_generic_to_shared(Ws1);
    unsigned ws2b = (unsigned)__cvta_generic_to_shared(Ws2);
    int arow = lane & 15, ahalf = lane >> 4;
    int brow = (lane & 7) + ((lane >> 4) & 1) * 8;
    int bk   = ((lane >> 3) & 1) * 8;

    // ---- u-GEMM (K=16) ----
    float Cu[4][4][4];
#pragma unroll
    for (int mt = 0; mt < 4; mt++) {
        float b0 = s_b1pe[16 * mt + grp], b1 = s_b1pe[16 * mt + 8 + grp];
#pragma unroll
        for (int nt = 0; nt < 4; nt++) {
            Cu[mt][nt][0] = b0; Cu[mt][nt][1] = b0;
            Cu[mt][nt][2] = b1; Cu[mt][nt][3] = b1;
        }
    }
    {
        unsigned Af[4][4];
#pragma unroll
        for (int mt = 0; mt < 4; mt++)
            ldsm4(Af[mt], wlpb + 2 * ((16 * mt + arow) * WLSTR + 8 * ahalf));
#pragma unroll
        for (int ntp = 0; ntp < 2; ntp++) {
            unsigned Bf[4];
            ldsm4(Bf, xlpb + 2 * ((16 * ntp + brow) * XLSTR + bk));
#pragma unroll
            for (int mt = 0; mt < 4; mt++) {
                mma16816(Cu[mt][2 * ntp],     Af[mt], Bf);
                mma16816(Cu[mt][2 * ntp + 1], Af[mt], Bf + 2);
            }
        }
    }
    unsigned Bu[4][4][2];
#pragma unroll
    for (int mt = 0; mt < 4; mt++)
#pragma unroll
        for (int nt = 0; nt < 4; nt++) {
            Bu[mt][nt][0] = movm(h2u(fmaxf(Cu[mt][nt][0], 0.f), fmaxf(Cu[mt][nt][1], 0.f)));
            Bu[mt][nt][1] = movm(h2u(fmaxf(Cu[mt][nt][2], 0.f), fmaxf(Cu[mt][nt][3], 0.f)));
        }

    // ---- GEMM1 (chained B) ----
    float C1[4][4][4];
#pragma unroll
    for (int mt = 0; mt < 4; mt++) {
        float b0 = s_b2pe[16 * mt + grp], b1 = s_b2pe[16 * mt + 8 + grp];
#pragma unroll
        for (int nt = 0; nt < 4; nt++) {
            C1[mt][nt][0] = b0; C1[mt][nt][1] = b0;
            C1[mt][nt][2] = b1; C1[mt][nt][3] = b1;
        }
    }
#pragma unroll
    for (int kt = 0; kt < 4; kt++) {
        unsigned Af[4][4];
#pragma unroll
        for (int mt = 0; mt < 4; mt++)
            ldsm4(Af[mt], ws1b + 2 * ((16 * mt + arow) * WSTR + 16 * kt + 8 * ahalf));
#pragma unroll
        for (int mt = 0; mt < 4; mt++)
#pragma unroll
            for (int nt = 0; nt < 4; nt++)
                mma16816(C1[mt][nt], Af[mt], Bu[kt][nt]);
    }

    // ---- movm chain (no global store) ----
    unsigned Bc[4][4][2];
#pragma unroll
    for (int mt = 0; mt < 4; mt++)
#pragma unroll
        for (int nt = 0; nt < 4; nt++) {
            Bc[mt][nt][0] = movm(h2u(C1[mt][nt][0], C1[mt][nt][1]));
            Bc[mt][nt][1] = movm(h2u(C1[mt][nt][2], C1[mt][nt][3]));
        }

    // ---- GEMM2 (stats only) ----
    float C2[4][4][4];
#pragma unroll
    for (int mt = 0; mt < 4; mt++) {
        float b0 = s_b1at[16 * mt + grp], b1 = s_b1at[16 * mt + 8 + grp];
#pragma unroll
        for (int nt = 0; nt < 4; nt++) {
            C2[mt][nt][0] = b0; C2[mt][nt][1] = b0;
            C2[mt][nt][2] = b1; C2[mt][nt][3] = b1;
        }
    }
#pragma unroll
    for (int kt = 0; kt < 4; kt++) {
        unsigned Af[4][4];
#pragma unroll
        for (int mt = 0; mt < 4; mt++)
            ldsm4(Af[mt], ws2b + 2 * ((16 * mt + arow) * WSTR + 16 * kt + 8 * ahalf));
#pragma unroll
        for (int mt = 0; mt < 4; mt++)
#pragma unroll
            for (int nt = 0; nt < 4; nt++)
                mma16816(C2[mt][nt], Af[mt], Bc[kt][nt]);
    }

    // ---- GN2 stats from C2 fragments ----
    {
        float gs[8], gq[8];
#pragma unroll
        for (int g = 0; g < 8; g++) { gs[g] = 0.f; gq[g] = 0.f; }
#pragma unroll
        for (int mt = 0; mt < 4; mt++) {
#pragma unroll
            for (int nt = 0; nt < 4; nt++) {
                float v0 = C2[mt][nt][0], v1 = C2[mt][nt][1];
                float v2 = C2[mt][nt][2], v3 = C2[mt][nt][3];
                gs[2 * mt]     += v0 + v1;
                gq[2 * mt]     = fmaf(v0, v0, fmaf(v1, v1, gq[2 * mt]));
                gs[2 * mt + 1] += v2 + v3;
                gq[2 * mt + 1] = fmaf(v2, v2, fmaf(v3, v3, gq[2 * mt + 1]));
            }
        }
        float r[16];
#pragma unroll
        for (int g = 0; g < 8; g++) { r[g] = gs[g]; r[8 + g] = gq[g]; }
#pragma unroll
        for (int i = 0; i < 16; i++)
            for (int off = 16; off; off >>= 1)
                r[i] += __shfl_down_sync(0xffffffffu, r[i], off);
        if (lane == 0) {
#pragma unroll
            for (int i = 0; i < 16; i++) atomicAdd(&s_red[i], r[i]);
        }
    }
    __syncthreads();
    if (t < 16) atomicAdd(&g_s2[b][t & 7][t >> 3], (double)s_red[t]);
}

__global__ void k_fin2(const float* __restrict__ gam, const float* __restrict__ bet) {
    int o = threadIdx.x;  // 64 threads
    double n = (double)CPGn * (double)MKn;
    for (int b = 0; b < Bn; b++) {
        int g = o >> 3;
        double s = g_s2[b][g][0], sq = g_s2[b][g][1];
        double mean = s / n;
        double var  = sq / n - mean * mean;
        float rstd  = (float)(1.0 / sqrt(var + (double)GN_EPS));
        float a  = gam[o] * rstd;
        float cc = bet[o] - (float)mean * a;
        g_gn2d[b][o]      = a;
        g_gn2d[b][64 + o] = cc;
    }
}

// ---- pass3 smem (bytes): acth overlays Xlp/Wlp/Ws1 (dead after GEMM1) ----
#define P3_XLP   0                       // 6144
#define P3_WLP   6144                    // 3072
#define P3_WS1   9216                    // 9216 -> ends 18432
#define P3_ACT   0                       // fp16 [64][ASTRH] 17408 (overlay)
#define P3_WS2   18432                   // 9216
#define P3_WS3   27648                   // 9216
#define P3_PE    36864                   // fp16 [64][VSTR] 17408
#define P3_GN    54272                   // fp32 128
#define P3_B1PE  54784
#define P3_B2PE  55040
#define P3_B1AT  55296
#define P3_BAT   55552
#define P3_TOTB  55808

__global__ __launch_bounds__(128, 4) void k_pass3(const float* __restrict__ q,
                                                  const float* __restrict__ kx,
                                                  const int*   __restrict__ idx,
                                                  const int*   __restrict__ mask,
                                                  const float* __restrict__ b2pe,
                                                  const float* __restrict__ b1at,
                                                  const float* __restrict__ b2at,
                                                  float* __restrict__ out) {
    extern __shared__ __align__(16) char smc[];
    __half* Xlp   = reinterpret_cast<__half*>(smc + P3_XLP);
    __half* Wlp   = reinterpret_cast<__half*>(smc + P3_WLP);
    __half* Ws1   = reinterpret_cast<__half*>(smc + P3_WS1);
    __half* acth  = reinterpret_cast<__half*>(smc + P3_ACT);
    __half* Ws2   = reinterpret_cast<__half*>(smc + P3_WS2);
    __half* Ws3   = reinterpret_cast<__half*>(smc + P3_WS3);
    __half* Pe_s  = reinterpret_cast<__half*>(smc + P3_PE);
    float* s_gn   = reinterpret_cast<float*>(smc + P3_GN);
    float* s_b1pe = reinterpret_cast<float*>(smc + P3_B1PE);
    float* s_b2pe = reinterpret_cast<float*>(smc + P3_B2PE);
    float* s_b1at = reinterpret_cast<float*>(smc + P3_B1AT);
    float* s_bat  = reinterpret_cast<float*>(smc + P3_BAT);

    int t = threadIdx.x, b = blockIdx.y;
    int colbase = blockIdx.x * 128;
    int lane = t & 31, warp = t >> 5;
    int grp = lane >> 2, tig = lane & 3;
    int n0 = warp * 32;

    stage_w(g_w2pe_h, Ws1, t);
    stage_w(g_w1at_h, Ws2, t);
    stage_w(g_w2at_h, Ws3, t);
    {
        int row = t >> 1, c = t & 1;
        uint4 v = *reinterpret_cast<const uint4*>(g_w1pe_hf[b] + row * 16 + c * 8);
        *reinterpret_cast<uint4*>(Wlp + row * WLSTR + c * 8) = v;
    }
    s_gn[t] = g_gn2d[b][t];
    if (t < 64) {
        s_b1pe[t] = g_b1pe_f[b][t];
        s_b2pe[t] = b2pe[t];
        s_b1at[t] = b1at[t];
        s_bat[t]  = b2at[t];
    }
    {
        int col = colbase + t;
        float lp[4];
        compute_lp(q, kx, idx, b, col, lp);
        *reinterpret_cast<uint4*>(Xlp + t * XLSTR) =
            make_uint4(h2u(lp[0], lp[1]), h2u(lp[2], lp[3]), 0u, 0u);
        *reinterpret_cast<uint4*>(Xlp + t * XLSTR + 8) = make_uint4(0u, 0u, 0u, 0u);
    }
    __syncthreads();

    unsigned xlpb = (unsigned)__cvta_generic_to_shared(Xlp + (size_t)n0 * XLSTR);
    unsigned wlpb = (unsigned)__cvta_generic_to_shared(Wlp);
    unsigned ws1b = (unsigned)__cvta_generic_to_shared(Ws1);
    unsigned ws2b = (unsigned)__cvta_generic_to_shared(Ws2);
    unsigned ws3b = (unsigned)__cvta_generic_to_shared(Ws3);
    int arow = lane & 15, ahalf = lane >> 4;
    int brow = (lane & 7) + ((lane >> 4) & 1) * 8;
    int bk   = ((lane >> 3) & 1) * 8;

    // ---- u-GEMM (K=16) ----
    float Cu[4][4][4];
#pragma unroll
    for (int mt = 0; mt < 4; mt++) {
        float b0 = s_b1pe[16 * mt + grp], b1 = s_b1pe[16 * mt + 8 + grp];
#pragma unroll
        for (int nt = 0; nt < 4; nt++) {
            Cu[mt][nt][0] = b0; Cu[mt][nt][1] = b0;
            Cu[mt][nt][2] = b1; Cu[mt][nt][3] = b1;
        }
    }
    {
        unsigned Af[4][4];
#pragma unroll
        for (int mt = 0; mt < 4; mt++)
            ldsm4(Af[mt], wlpb + 2 * ((16 * mt + arow) * WLSTR + 8 * ahalf));
#pragma unroll
        for (int ntp = 0; ntp < 2; ntp++) {
            unsigned Bf[4];
            ldsm4(Bf, xlpb + 2 * ((16 * ntp + brow) * XLSTR + bk));
#pragma unroll
            for (int mt = 0; mt < 4; mt++) {
                mma16816(Cu[mt][2 * ntp],     Af[mt], Bf);
                mma16816(Cu[mt][2 * ntp + 1], Af[mt], Bf + 2);
            }
        }
    }
    unsigned Bu[4][4][2];
#pragma unroll
    for (int mt = 0; mt < 4; mt++)
#pragma unroll
        for (int nt = 0; nt < 4; nt++) {
            Bu[mt][nt][0] = movm(h2u(fmaxf(Cu[mt][nt][0], 0.f), fmaxf(Cu[mt][nt][1], 0.f)));
            Bu[mt][nt][1] = movm(h2u(fmaxf(Cu[mt][nt][2], 0.f), fmaxf(Cu[mt][nt][3], 0.f)));
        }

    // ---- GEMM1 (chained B) -> pe ----
    float C1[4][4][4];
#pragma unroll
    for (int mt = 0; mt < 4; mt++) {
        float b0 = s_b2pe[16 * mt + grp], b1 = s_b2pe[16 * mt + 8 + grp];
#pragma unroll
        for (int nt = 0; nt < 4; nt++) {
            C1[mt][nt][0] = b0; C1[mt][nt][1] = b0;
            C1[mt][nt][2] = b1; C1[mt][nt][3] = b1;
        }
    }
#pragma unroll
    for (int kt = 0; kt < 4; kt++) {
        unsigned Af[4][4];
#pragma unroll
        for (int mt = 0; mt < 4; mt++)
            ldsm4(Af[mt], ws1b + 2 * ((16 * mt + arow) * WSTR + 16 * kt + 8 * ahalf));
#pragma unroll
        for (int mt = 0; mt < 4; mt++)
#pragma unroll
            for (int nt = 0; nt < 4; nt++)
                mma16816(C1[mt][nt], Af[mt], Bu[kt][nt]);
    }

    // ---- pe -> Pe_s smem + movm chain ----
    unsigned Bc[4][4][2];
#pragma unroll
    for (int mt = 0; mt < 4; mt++) {
        int r0 = 16 * mt + grp, r1 = r0 + 8;
#pragma unroll
        for (int nt = 0; nt < 4; nt++) {
            int colL = n0 + 8 * nt + 2 * tig;
            unsigned p01 = h2u(C1[mt][nt][0], C1[mt][nt][1]);
            unsigned p23 = h2u(C1[mt][nt][2], C1[mt][nt][3]);
            *reinterpret_cast<unsigned*>(Pe_s + r0 * VSTR + colL) = p01;
            *reinterpret_cast<unsigned*>(Pe_s + r1 * VSTR + colL) = p23;
            Bc[mt][nt][0] = movm(p01);
            Bc[mt][nt][1] = movm(p23);
        }
    }
    __syncthreads();   // all Xlp/Wlp/Ws1 reads done before acth overlay writes

    // ---- GEMM2 (chained B) ----
    float C2[4][4][4];
#pragma unroll
    for (int mt = 0; mt < 4; mt++) {
        float b0 = s_b1at[16 * mt + grp], b1 = s_b1at[16 * mt + 8 + grp];
#pragma unroll
        for (int nt = 0; nt < 4; nt++) {
            C2[mt][nt][0] = b0; C2[mt][nt][1] = b0;
            C2[mt][nt][2] = b1; C2[mt][nt][3] = b1;
        }
    }
#pragma unroll
    for (int kt = 0; kt < 4; kt++) {
        unsigned Af[4][4];
#pragma unroll
        for (int mt = 0; mt < 4; mt++)
            ldsm4(Af[mt], ws2b + 2 * ((16 * mt + arow) * WSTR + 16 * kt + 8 * ahalf));
#pragma unroll
        for (int mt = 0; mt < 4; mt++)
#pragma unroll
            for (int nt = 0; nt < 4; nt++)
                mma16816(C2[mt][nt], Af[mt], Bc[kt][nt]);
    }

    // ---- GN2 fold + relu -> movm chain ----
    unsigned Bv[4][4][2];
#pragma unroll
    for (int mt = 0; mt < 4; mt++) {
        int r0 = 16 * mt + grp, r1 = r0 + 8;
        float a0 = s_gn[r0], c0 = s_gn[64 + r0];
        float a1 = s_gn[r1], c1 = s_gn[64 + r1];
#pragma unroll
        for (int nt = 0; nt < 4; nt++) {
            float v0 = fmaxf(fmaf(a0, C2[mt][nt][0], c0), 0.f);
            float v1 = fmaxf(fmaf(a0, C2[mt][nt][1], c0), 0.f);
            float v2 = fmaxf(fmaf(a1, C2[mt][nt][2], c1), 0.f);
            float v3 = fmaxf(fmaf(a1, C2[mt][nt][3], c1), 0.f);
            Bv[mt][nt][0] = movm(h2u(v0, v1));
            Bv[mt][nt][1] = movm(h2u(v2, v3));
        }
    }

    // ---- GEMM3 (chained B) ----
    float C3[4][4][4];
#pragma unroll
    for (int mt = 0; mt < 4; mt++) {
        float b0 = s_bat[16 * mt + grp], b1 = s_bat[16 * mt + 8 + grp];
#pragma unroll
        for (int nt = 0; nt < 4; nt++) {
            C3[mt][nt][0] = b0; C3[mt][nt][1] = b0;
            C3[mt][nt][2] = b1; C3[mt][nt][3] = b1;
        }
    }
#pragma unroll
    for (int kt = 0; kt < 4; kt++) {
        unsigned Af[4][4];
#pragma unroll
        for (int mt = 0; mt < 4; mt++)
            ldsm4(Af[mt], ws3b + 2 * ((16 * mt + arow) * WSTR + 16 * kt + 8 * ahalf));
#pragma unroll
        for (int mt = 0; mt < 4; mt++)
#pragma unroll
            for (int nt = 0; nt < 4; nt++)
                mma16816(C3[mt][nt], Af[mt], Bv[kt][nt]);
    }

    // ---- masked store -> acth fp16 [o][col] ----
    {
        const int* mrow = mask + (size_t)b * MKn + colbase;
        int2 mv[4];
#pragma unroll
        for (int nt = 0; nt < 4; nt++)
            mv[nt] = *reinterpret_cast<const int2*>(mrow + n0 + 8 * nt + 2 * tig);
#pragma unroll
        for (int mt = 0; mt < 4; mt++) {
            int r0 = 16 * mt + grp, r1 = r0 + 8;
#pragma unroll
            for (int nt = 0; nt < 4; nt++) {
                int colL = n0 + 8 * nt + 2 * tig;
                bool m0 = mv[nt].x != 0, m1 = mv[nt].y != 0;
                float f0 = m0 ? C3[mt][nt][0] : -65504.f;
                float f1 = m1 ? C3[mt][nt][1] : -65504.f;
                float f2 = m0 ? C3[mt][nt][2] : -65504.f;
                float f3 = m1 ? C3[mt][nt][3] : -65504.f;
                *reinterpret_cast<unsigned*>(acth + r0 * ASTRH + colL) = h2u(f0, f1);
                *reinterpret_cast<unsigned*>(acth + r1 * ASTRH + colL) = h2u(f2, f3);
            }
        }
    }
    __syncthreads();

    // ---- per-(m,o) softmax units; pe from Pe_s smem ----
    int mbase = colbase >> 4;      // 8 m per tile
#pragma unroll
    for (int r = 0; r < 4; r++) {
        int unit = r * 128 + t;    // 0..511
        int o = unit >> 3, ml = unit & 7;
        uint4 aw0 = *reinterpret_cast<const uint4*>(acth + o * ASTRH + 16 * ml);
        uint4 aw1 = *reinterpret_cast<const uint4*>(acth + o * ASTRH + 16 * ml + 8);
        float av[16];
        {
            float4 x;
            x = h4_to_f4(make_uint2(aw0.x, aw0.y));
            av[0] = x.x; av[1] = x.y; av[2] = x.z; av[3] = x.w;
            x = h4_to_f4(make_uint2(aw0.z, aw0.w));
            av[4] = x.x; av[5] = x.y; av[6] = x.z; av[7] = x.w;
            x = h4_to_f4(make_uint2(aw1.x, aw1.y));
            av[8] = x.x; av[9] = x.y; av[10] = x.z; av[11] = x.w;
            x = h4_to_f4(make_uint2(aw1.z, aw1.w));
            av[12] = x.x; av[13] = x.y; av[14] = x.z; av[15] = x.w;
        }
        float mx = av[0];
#pragma unroll
        for (int j = 1; j < 16; j++) mx = fmaxf(mx, av[j]);
        float s = 0.f;
#pragma unroll
        for (int j = 0; j < 16; j++) { av[j] = __expf(av[j] - mx); s += av[j]; }
        uint4 pw0 = *reinterpret_cast<const uint4*>(Pe_s + o * VSTR + 16 * ml);
        uint4 pw1 = *reinterpret_cast<const uint4*>(Pe_s + o * VSTR + 16 * ml + 8);
        float accum = 0.f;
        {
            float4 p;
            p = h4_to_f4(make_uint2(pw0.x, pw0.y));
            accum = fmaf(p.x, av[0], fmaf(p.y, av[1], fmaf(p.z, av[2], fmaf(p.w, av[3], accum))));
            p = h4_to_f4(make_uint2(pw0.z, pw0.w));
            accum = fmaf(p.x, av[4], fmaf(p.y, av[5], fmaf(p.z, av[6], fmaf(p.w, av[7], accum))));
            p = h4_to_f4(make_uint2(pw1.x, pw1.y));
            accum = fmaf(p.x, av[8], fmaf(p.y, av[9], fmaf(p.z, av[10], fmaf(p.w, av[11], accum))));
            p = h4_to_f4(make_uint2(pw1.z, pw1.w));
            accum = fmaf(p.x, av[12], fmaf(p.y, av[13], fmaf(p.z, av[14], fmaf(p.w, av[15], accum))));
        }
        out[((size_t)b * 64 + o) * Mn + mbase + ml] = accum * __fdividef(1.f, s);
    }
}

// ---------------- launch ----------------
extern "C" void kernel_launch(void* const* d_in, const int* in_sizes, int n_in,
                              void* d_out, int out_size) {
    const float* q_xyzs  = (const float*)d_in[0];
    const float* k_xyzs  = (const float*)d_in[1];
    const int*   knn_idx = (const int*)d_in[2];
    const int*   mask    = (const int*)d_in[3];
    const float* pe_w1   = (const float*)d_in[4];
    const float* pe_b1   = (const float*)d_in[5];
    const float* pe_g    = (const float*)d_in[6];
    const float* pe_be   = (const float*)d_in[7];
    const float* pe_w2   = (const float*)d_in[8];
    const float* pe_b2   = (const float*)d_in[9];
    const float* at_w1   = (const float*)d_in[10];
    const float* at_b1   = (const float*)d_in[11];
    const float* at_g    = (const float*)d_in[12];
    const float* at_be   = (const float*)d_in[13];
    const float* at_w2   = (const float*)d_in[14];
    const float* at_b2   = (const float*)d_in[15];
    float* out = (float*)d_out;

    static int smem_set = 0;
    if (!smem_set) {
        cudaFuncSetAttribute(k_pass2, cudaFuncAttributeMaxDynamicSharedMemorySize,
                             P2_TOTB);
        cudaFuncSetAttribute(k_pass3, cudaFuncAttributeMaxDynamicSharedMemorySize,
                             P3_TOTB);
        smem_set = 1;
    }

    k_prep<<<64, 64>>>(pe_w2, at_w1, at_w2);

    dim3 g1(MKn / 640, Bn);
    k_pass1<<<g1, 128>>>(q_xyzs, k_xyzs, knn_idx);
    k_fin1<<<1, 64>>>(pe_w1, pe_b1, pe_g, pe_be);

    dim3 gcol(MKn / 128, Bn);
    k_pass2<<<gcol, 128, P2_TOTB>>>(q_xyzs, k_xyzs, knn_idx, pe_b2, at_b1);
    k_fin2<<<1, 64>>>(at_g, at_be);

    k_pass3<<<gcol, 128, P3_TOTB>>>(q_xyzs, k_xyzs, knn_idx, mask,
                                    pe_b2, at_b1, at_b2, out);
}

// round 17
// speedup vs baseline: 7.9821x; 1.0267x over previous
#include <cuda_runtime.h>
#include <cuda_fp16.h>
#include <math.h>
#include <float.h>

#define Bn   2
#define Mn   25000
#define Nn   100000
#define NGn  8
#define CPGn 8
#define GN_EPS 1e-5f
#define MKn  (Mn * 16)          // 400000 columns per batch

#define XLSTR 24                // fp16 lp-tile stride (halves)
#define WLSTR 24                // fp16 folded-w1 stride
#define WSTR 72                 // fp16 weight stride
#define VSTR 136                // fp16 pe stride in pass3 [o][col]
#define ASTRH 136               // fp16 attn stride in pass3 [o][col]

typedef unsigned long long u64;

// ---------------- device scratch ----------------
__device__ double g_m1[Bn][14];
__device__ double g_s2[Bn][NGn][2];
__device__ __align__(16) float g_b1pe_f[Bn][64];
__device__ __align__(16) __half g_w1pe_hf[Bn][1024]; // folded conv1_pe fp16 [o][16]
__device__ __align__(16) float g_gn2d[Bn][128];      // a2[64] | c2[64]
__device__ __align__(16) __half g_w2pe_h[4096];      // [o][k] fp16
__device__ __align__(16) __half g_w1at_h[4096];      // [o][k] fp16
__device__ __align__(16) __half g_w2at_h[4096];      // [o][k] fp16

// ---------------- scalar helpers ----------------
__device__ __forceinline__ float4 h4_to_f4(uint2 u) {
    __half2 a = *reinterpret_cast<__half2*>(&u.x);
    __half2 b = *reinterpret_cast<__half2*>(&u.y);
    float2 fa = __half22float2(a), fb = __half22float2(b);
    return make_float4(fa.x, fa.y, fb.x, fb.y);
}
__device__ __forceinline__ unsigned h2u(float a, float b) {
    __half2 h = __floats2half2_rn(a, b);
    return *reinterpret_cast<unsigned*>(&h);
}

// ---------------- tensor primitives ----------------
__device__ __forceinline__ void mma16816(float* c, const unsigned* a, const unsigned* b) {
    asm volatile(
        "mma.sync.aligned.m16n8k16.row.col.f32.f16.f16.f32 "
        "{%0,%1,%2,%3}, {%4,%5,%6,%7}, {%8,%9}, {%0,%1,%2,%3};\n"
        : "+f"(c[0]), "+f"(c[1]), "+f"(c[2]), "+f"(c[3])
        : "r"(a[0]), "r"(a[1]), "r"(a[2]), "r"(a[3]), "r"(b[0]), "r"(b[1]));
}
__device__ __forceinline__ void ldsm4(unsigned* r, unsigned addr) {
    asm volatile("ldmatrix.sync.aligned.m8n8.x4.shared.b16 {%0,%1,%2,%3}, [%4];"
        : "=r"(r[0]), "=r"(r[1]), "=r"(r[2]), "=r"(r[3]) : "r"(addr));
}
__device__ __forceinline__ unsigned movm(unsigned a) {
    unsigned d;
    asm volatile("movmatrix.sync.aligned.m8n8.trans.b16 %0, %1;" : "=r"(d) : "r"(a));
    return d;
}

// ---------------- misc helpers ----------------
__device__ __forceinline__ void compute_lp(const float* __restrict__ q,
                                           const float* __restrict__ kx,
                                           const int*   __restrict__ idx,
                                           int b, int c, float lp[4]) {
    int m  = c >> 4;
    int id = idx[b * MKn + c];
    float qx = q[(b * 3 + 0) * Mn + m];
    float qy = q[(b * 3 + 1) * Mn + m];
    float qz = q[(b * 3 + 2) * Mn + m];
    float px = kx[(b * 3 + 0) * Nn + id];
    float py = kx[(b * 3 + 1) * Nn + id];
    float pz = kx[(b * 3 + 2) * Nn + id];
    float ox = px - qx, oy = py - qy, oz = pz - qz;
    float d  = sqrtf(ox * ox + oy * oy + oz * oz);
    float r  = 1.0f / fmaxf(d, 1e-12f);
    lp[0] = ox * r; lp[1] = oy * r; lp[2] = oz * r; lp[3] = d;
}

__device__ __forceinline__ void stage_w(const __half* __restrict__ gsrc,
                                        __half* Ws, int t) {
#pragma unroll
    for (int id = t; id < 512; id += 128) {
        int row = id >> 3, c = id & 7;
        uint4 v = *reinterpret_cast<const uint4*>(gsrc + row * 64 + c * 8);
        *reinterpret_cast<uint4*>(Ws + row * WSTR + c * 8) = v;
    }
}

// ---------------- kernels ----------------
__global__ void k_prep(const float* __restrict__ w2pe,
                       const float* __restrict__ w1at,
                       const float* __restrict__ w2at) {
    int i = blockIdx.x;
    int j = threadIdx.x;
    g_w2pe_h[i * 64 + j] = __float2half(w2pe[i * 64 + j]);
    g_w1at_h[i * 64 + j] = __float2half(w1at[i * 64 + j]);
    g_w2at_h[i * 64 + j] = __float2half(w2at[i * 64 + j]);
    if (i == 0) {
        if (j < Bn * NGn * 2) ((double*)g_s2)[j] = 0.0;
        if (j < Bn * 14)      ((double*)g_m1)[j] = 0.0;
    }
}

// pass1: lp moments, 5 columns per thread (block covers 640 cols)
__global__ __launch_bounds__(128) void k_pass1(const float* __restrict__ q,
                                               const float* __restrict__ kx,
                                               const int*   __restrict__ idx) {
    __shared__ float s_red[14];
    int t = threadIdx.x, b = blockIdx.y;
    if (t < 14) s_red[t] = 0.f;
    __syncthreads();

    float v[14];
#pragma unroll
    for (int i = 0; i < 14; i++) v[i] = 0.f;

    int base = blockIdx.x * 640 + t;
#pragma unroll
    for (int i = 0; i < 5; i++) {
        int col = base + i * 128;
        float lp[4];
        compute_lp(q, kx, idx, b, col, lp);
        v[0] += lp[0]; v[1] += lp[1]; v[2] += lp[2]; v[3] += lp[3];
        int n = 4;
#pragma unroll
        for (int c = 0; c < 4; c++)
#pragma unroll
            for (int d = c; d < 4; d++) v[n++] += lp[c] * lp[d];
    }
#pragma unroll
    for (int i = 0; i < 14; i++) {
        for (int off = 16; off; off >>= 1)
            v[i] += __shfl_down_sync(0xffffffffu, v[i], off);
        if ((t & 31) == 0) atomicAdd(&s_red[i], v[i]);
    }
    __syncthreads();
    if (t < 14) atomicAdd(&g_m1[b][t], (double)s_red[t]);
}

__global__ void k_fin1(const float* __restrict__ w1, const float* __restrict__ b1,
                       const float* __restrict__ gam, const float* __restrict__ bet) {
    __shared__ double gs[8], gq[8];
    int o = threadIdx.x;  // 64 threads
    double n = (double)CPGn * (double)MKn;
    for (int b = 0; b < Bn; b++) {
        if (o < 8) { gs[o] = 0.0; gq[o] = 0.0; }
        __syncthreads();
        double m[14];
#pragma unroll
        for (int i = 0; i < 14; i++) m[i] = g_m1[b][i];
        double M2[4][4];
        {
            int idx5 = 4;
            for (int c = 0; c < 4; c++)
                for (int d = c; d < 4; d++) {
                    M2[c][d] = m[idx5]; M2[d][c] = m[idx5]; idx5++;
                }
        }
        double w[4];
#pragma unroll
        for (int c = 0; c < 4; c++) w[c] = (double)w1[o * 4 + c];
        double bo = (double)b1[o];
        double dot = w[0] * m[0] + w[1] * m[1] + w[2] * m[2] + w[3] * m[3];
        double sum_o = dot + (double)MKn * bo;
        double sq_o = 0.0;
#pragma unroll
        for (int c = 0; c < 4; c++)
#pragma unroll
            for (int d = 0; d < 4; d++) sq_o += w[c] * w[d] * M2[c][d];
        sq_o += 2.0 * bo * dot + (double)MKn * bo * bo;
        atomicAdd(&gs[o >> 3], sum_o);
        atomicAdd(&gq[o >> 3], sq_o);
        __syncthreads();
        int g = o >> 3;
        double mean = gs[g] / n;
        double var  = gq[g] / n - mean * mean;
        float rstd  = (float)(1.0 / sqrt(var + (double)GN_EPS));
        float a  = gam[o] * rstd;
        float cc = bet[o] - (float)mean * a;
        g_b1pe_f[b][o] = fmaf(a, b1[o], cc);
        __half* wh = g_w1pe_hf[b] + o * 16;
        for (int c = 0; c < 4; c++) wh[c] = __float2half(a * w1[o * 4 + c]);
        for (int c = 4; c < 16; c++) wh[c] = __float2half(0.f);
        __syncthreads();
    }
}

// ---- pass2 smem (bytes) ----
#define P2_XLP   0                       // fp16 [128][XLSTR]  6144
#define P2_WLP   6144                    // 3072
#define P2_WS1   9216                    // 9216
#define P2_WS2   18432                   // 9216
#define P2_B1PE  27648
#define P2_B2PE  27904
#define P2_B1AT  28160
#define P2_RED   28416
#define P2_TOTB  28480

__global__ __launch_bounds__(128, 4) void k_pass2(const float* __restrict__ q,
                                                  const float* __restrict__ kx,
                                                  const int*   __restrict__ idx,
                                                  const float* __restrict__ b2pe,
                                                  const float* __restrict__ b1at) {
    extern __shared__ __align__(16) char smc[];
    __half* Xlp = reinterpret_cast<__half*>(smc + P2_XLP);
    __half* Wlp = reinterpret_cast<__half*>(smc + P2_WLP);
    __half* Ws1 = reinterpret_cast<__half*>(smc + P2_WS1);
    __half* Ws2 = reinterpret_cast<__half*>(smc + P2_WS2);
    float* s_b1pe = reinterpret_cast<float*>(smc + P2_B1PE);
    float* s_b2pe = reinterpret_cast<float*>(smc + P2_B2PE);
    float* s_b1at = reinterpret_cast<float*>(smc + P2_B1AT);
    float* s_red  = reinterpret_cast<float*>(smc + P2_RED);

    int t = threadIdx.x, b = blockIdx.y;
    int colbase = blockIdx.x * 256;
    int lane = t & 31, warp = t >> 5;
    int grp = lane >> 2;
    int n0 = warp * 32;

    stage_w(g_w2pe_h, Ws1, t);
    stage_w(g_w1at_h, Ws2, t);
    {
        int row = t >> 1, c = t & 1;
        uint4 v = *reinterpret_cast<const uint4*>(g_w1pe_hf[b] + row * 16 + c * 8);
        *reinterpret_cast<uint4*>(Wlp + row * WLSTR + c * 8) = v;
    }
    if (t < 64) {
        s_b1pe[t] = g_b1pe_f[b][t];
        s_b2pe[t] = b2pe[t];
        s_b1at[t] = b1at[t];
    }
    if (t < 16) s_red[t] = 0.f;
    __syncthreads();

    unsigned xlpb = (unsigned)__cvta_generic_to_shared(Xlp + (size_t)n0 * XLSTR);
    unsigned wlpb = (unsigned)__cvta_generic_to_shared(Wlp);
    unsigned ws1b = (unsigned)__cvta_generic_to_shared(Ws1);
    unsigned ws2b = (unsigned)__cvta_generic_to_shared(Ws2);
    int arow = lane & 15, ahalf = lane >> 4;
    int brow = (lane & 7) + ((lane >> 4) & 1) * 8;
    int bk   = ((lane >> 3) & 1) * 8;

#pragma unroll
    for (int tile = 0; tile < 2; tile++) {
        int colT = colbase + 128 * tile;
        if (tile && colT >= MKn) break;

        // ---- stage lp for this tile (warp-local rows; syncwarp suffices) ----
        if (tile) __syncwarp();
        {
            int col = colT + t;
            float lp[4];
            compute_lp(q, kx, idx, b, col, lp);
            *reinterpret_cast<uint4*>(Xlp + t * XLSTR) =
                make_uint4(h2u(lp[0], lp[1]), h2u(lp[2], lp[3]), 0u, 0u);
            *reinterpret_cast<uint4*>(Xlp + t * XLSTR + 8) = make_uint4(0u, 0u, 0u, 0u);
        }
        __syncwarp();

        // ---- u-GEMM (K=16) ----
        float Cu[4][4][4];
#pragma unroll
        for (int mt = 0; mt < 4; mt++) {
            float b0 = s_b1pe[16 * mt + grp], b1 = s_b1pe[16 * mt + 8 + grp];
#pragma unroll
            for (int nt = 0; nt < 4; nt++) {
                Cu[mt][nt][0] = b0; Cu[mt][nt][1] = b0;
                Cu[mt][nt][2] = b1; Cu[mt][nt][3] = b1;
            }
        }
        {
            unsigned Af[4][4];
#pragma unroll
            for (int mt = 0; mt < 4; mt++)
                ldsm4(Af[mt], wlpb + 2 * ((16 * mt + arow) * WLSTR + 8 * ahalf));
#pragma unroll
            for (int ntp = 0; ntp < 2; ntp++) {
                unsigned Bf[4];
                ldsm4(Bf, xlpb + 2 * ((16 * ntp + brow) * XLSTR + bk));
#pragma unroll
                for (int mt = 0; mt < 4; mt++) {
                    mma16816(Cu[mt][2 * ntp],     Af[mt], Bf);
                    mma16816(Cu[mt][2 * ntp + 1], Af[mt], Bf + 2);
                }
            }
        }
        unsigned Bu[4][4][2];
#pragma unroll
        for (int mt = 0; mt < 4; mt++)
#pragma unroll
            for (int nt = 0; nt < 4; nt++) {
                Bu[mt][nt][0] = movm(h2u(fmaxf(Cu[mt][nt][0], 0.f), fmaxf(Cu[mt][nt][1], 0.f)));
                Bu[mt][nt][1] = movm(h2u(fmaxf(Cu[mt][nt][2], 0.f), fmaxf(Cu[mt][nt][3], 0.f)));
            }

        // ---- GEMM1 (chained B) ----
        float C1[4][4][4];
#pragma unroll
        for (int mt = 0; mt < 4; mt++) {
            float b0 = s_b2pe[16 * mt + grp], b1 = s_b2pe[16 * mt + 8 + grp];
#pragma unroll
            for (int nt = 0; nt < 4; nt++) {
                C1[mt][nt][0] = b0; C1[mt][nt][1] = b0;
                C1[mt][nt][2] = b1; C1[mt][nt][3] = b1;
            }
        }
#pragma unroll
        for (int kt = 0; kt < 4; kt++) {
            unsigned Af[4][4];
#pragma unroll
            for (int mt = 0; mt < 4; mt++)
                ldsm4(Af[mt], ws1b + 2 * ((16 * mt + arow) * WSTR + 16 * kt + 8 * ahalf));
#pragma unroll
            for (int mt = 0; mt < 4; mt++)
#pragma unroll
                for (int nt = 0; nt < 4; nt++)
                    mma16816(C1[mt][nt], Af[mt], Bu[kt][nt]);
        }

        // ---- movm chain (no global store) ----
        unsigned Bc[4][4][2];
#pragma unroll
        for (int mt = 0; mt < 4; mt++)
#pragma unroll
            for (int nt = 0; nt < 4; nt++) {
                Bc[mt][nt][0] = movm(h2u(C1[mt][nt][0], C1[mt][nt][1]));
                Bc[mt][nt][1] = movm(h2u(C1[mt][nt][2], C1[mt][nt][3]));
            }

        // ---- GEMM2 (stats only) ----
        float C2[4][4][4];
#pragma unroll
        for (int mt = 0; mt < 4; mt++) {
            float b0 = s_b1at[16 * mt + grp], b1 = s_b1at[16 * mt + 8 + grp];
#pragma unroll
            for (int nt = 0; nt < 4; nt++) {
                C2[mt][nt][0] = b0; C2[mt][nt][1] = b0;
                C2[mt][nt][2] = b1; C2[mt][nt][3] = b1;
            }
        }
#pragma unroll
        for (int kt = 0; kt < 4; kt++) {
            unsigned Af[4][4];
#pragma unroll
            for (int mt = 0; mt < 4; mt++)
                ldsm4(Af[mt], ws2b + 2 * ((16 * mt + arow) * WSTR + 16 * kt + 8 * ahalf));
#pragma unroll
            for (int mt = 0; mt < 4; mt++)
#pragma unroll
                for (int nt = 0; nt < 4; nt++)
                    mma16816(C2[mt][nt], Af[mt], Bc[kt][nt]);
        }

        // ---- GN2 stats from C2 fragments (per tile, atomic into s_red) ----
        {
            float gs[8], gq[8];
#pragma unroll
            for (int g = 0; g < 8; g++) { gs[g] = 0.f; gq[g] = 0.f; }
#pragma unroll
            for (int mt = 0; mt < 4; mt++) {
#pragma unroll
                for (int nt = 0; nt < 4; nt++) {
                    float v0 = C2[mt][nt][0], v1 = C2[mt][nt][1];
                    float v2 = C2[mt][nt][2], v3 = C2[mt][nt][3];
                    gs[2 * mt]     += v0 + v1;
                    gq[2 * mt]     = fmaf(v0, v0, fmaf(v1, v1, gq[2 * mt]));
                    gs[2 * mt + 1] += v2 + v3;
                    gq[2 * mt + 1] = fmaf(v2, v2, fmaf(v3, v3, gq[2 * mt + 1]));
                }
            }
            float r[16];
#pragma unroll
            for (int g = 0; g < 8; g++) { r[g] = gs[g]; r[8 + g] = gq[g]; }
#pragma unroll
            for (int i = 0; i < 16; i++)
                for (int off = 16; off; off >>= 1)
                    r[i] += __shfl_down_sync(0xffffffffu, r[i], off);
            if (lane == 0) {
#pragma unroll
                for (int i = 0; i < 16; i++) atomicAdd(&s_red[i], r[i]);
            }
        }
    }
    __syncthreads();
    if (t < 16) atomicAdd(&g_s2[b][t & 7][t >> 3], (double)s_red[t]);
}

__global__ void k_fin2(const float* __restrict__ gam, const float* __restrict__ bet) {
    int o = threadIdx.x;  // 64 threads
    double n = (double)CPGn * (double)MKn;
    for (int b = 0; b < Bn; b++) {
        int g = o >> 3;
        double s = g_s2[b][g][0], sq = g_s2[b][g][1];
        double mean = s / n;
        double var  = sq / n - mean * mean;
        float rstd  = (float)(1.0 / sqrt(var + (double)GN_EPS));
        float a  = gam[o] * rstd;
        float cc = bet[o] - (float)mean * a;
        g_gn2d[b][o]      = a;
        g_gn2d[b][64 + o] = cc;
    }
}

// ---- pass3 smem (bytes): acth overlays Xlp/Wlp/Ws1 (dead after GEMM1) ----
#define P3_XLP   0                       // 6144
#define P3_WLP   6144                    // 3072
#define P3_WS1   9216                    // 9216 -> ends 18432
#define P3_ACT   0                       // fp16 [64][ASTRH] 17408 (overlay)
#define P3_WS2   18432                   // 9216
#define P3_WS3   27648                   // 9216
#define P3_PE    36864                   // fp16 [64][VSTR] 17408
#define P3_GN    54272                   // fp32 128
#define P3_B1PE  54784
#define P3_B2PE  55040
#define P3_B1AT  55296
#define P3_BAT   55552
#define P3_TOTB  55808

__global__ __launch_bounds__(128, 4) void k_pass3(const float* __restrict__ q,
                                                  const float* __restrict__ kx,
                                                  const int*   __restrict__ idx,
                                                  const int*   __restrict__ mask,
                                                  const float* __restrict__ b2pe,
                                                  const float* __restrict__ b1at,
                                                  const float* __restrict__ b2at,
                                                  float* __restrict__ out) {
    extern __shared__ __align__(16) char smc[];
    __half* Xlp   = reinterpret_cast<__half*>(smc + P3_XLP);
    __half* Wlp   = reinterpret_cast<__half*>(smc + P3_WLP);
    __half* Ws1   = reinterpret_cast<__half*>(smc + P3_WS1);
    __half* acth  = reinterpret_cast<__half*>(smc + P3_ACT);
    __half* Ws2   = reinterpret_cast<__half*>(smc + P3_WS2);
    __half* Ws3   = reinterpret_cast<__half*>(smc + P3_WS3);
    __half* Pe_s  = reinterpret_cast<__half*>(smc + P3_PE);
    float* s_gn   = reinterpret_cast<float*>(smc + P3_GN);
    float* s_b1pe = reinterpret_cast<float*>(smc + P3_B1PE);
    float* s_b2pe = reinterpret_cast<float*>(smc + P3_B2PE);
    float* s_b1at = reinterpret_cast<float*>(smc + P3_B1AT);
    float* s_bat  = reinterpret_cast<float*>(smc + P3_BAT);

    int t = threadIdx.x, b = blockIdx.y;
    int colbase = blockIdx.x * 128;
    int lane = t & 31, warp = t >> 5;
    int grp = lane >> 2, tig = lane & 3;
    int n0 = warp * 32;

    stage_w(g_w2pe_h, Ws1, t);
    stage_w(g_w1at_h, Ws2, t);
    stage_w(g_w2at_h, Ws3, t);
    {
        int row = t >> 1, c = t & 1;
        uint4 v = *reinterpret_cast<const uint4*>(g_w1pe_hf[b] + row * 16 + c * 8);
        *reinterpret_cast<uint4*>(Wlp + row * WLSTR + c * 8) = v;
    }
    s_gn[t] = g_gn2d[b][t];
    if (t < 64) {
        s_b1pe[t] = g_b1pe_f[b][t];
        s_b2pe[t] = b2pe[t];
        s_b1at[t] = b1at[t];
        s_bat[t]  = b2at[t];
    }
    {
        int col = colbase + t;
        float lp[4];
        compute_lp(q, kx, idx, b, col, lp);
        *reinterpret_cast<uint4*>(Xlp + t * XLSTR) =
            make_uint4(h2u(lp[0], lp[1]), h2u(lp[2], lp[3]), 0u, 0u);
        *reinterpret_cast<uint4*>(Xlp + t * XLSTR + 8) = make_uint4(0u, 0u, 0u, 0u);
    }
    __syncthreads();

    unsigned xlpb = (unsigned)__cvta_generic_to_shared(Xlp + (size_t)n0 * XLSTR);
    unsigned wlpb = (unsigned)__cvta_generic_to_shared(Wlp);
    unsigned ws1b = (unsigned)__cvta_generic_to_shared(Ws1);
    unsigned ws2b = (unsigned)__cvta_generic_to_shared(Ws2);
    unsigned ws3b = (unsigned)__cvta_generic_to_shared(Ws3);
    int arow = lane & 15, ahalf = lane >> 4;
    int brow = (lane & 7) + ((lane >> 4) & 1) * 8;
    int bk   = ((lane >> 3) & 1) * 8;

    // ---- u-GEMM (K=16) ----
    float Cu[4][4][4];
#pragma unroll
    for (int mt = 0; mt < 4; mt++) {
        float b0 = s_b1pe[16 * mt + grp], b1 = s_b1pe[16 * mt + 8 + grp];
#pragma unroll
        for (int nt = 0; nt < 4; nt++) {
            Cu[mt][nt][0] = b0; Cu[mt][nt][1] = b0;
            Cu[mt][nt][2] = b1; Cu[mt][nt][3] = b1;
        }
    }
    {
        unsigned Af[4][4];
#pragma unroll
        for (int mt = 0; mt < 4; mt++)
            ldsm4(Af[mt], wlpb + 2 * ((16 * mt + arow) * WLSTR + 8 * ahalf));
#pragma unroll
        for (int ntp = 0; ntp < 2; ntp++) {
            unsigned Bf[4];
            ldsm4(Bf, xlpb + 2 * ((16 * ntp + brow) * XLSTR + bk));
#pragma unroll
            for (int mt = 0; mt < 4; mt++) {
                mma16816(Cu[mt][2 * ntp],     Af[mt], Bf);
                mma16816(Cu[mt][2 * ntp + 1], Af[mt], Bf + 2);
            }
        }
    }
    unsigned Bu[4][4][2];
#pragma unroll
    for (int mt = 0; mt < 4; mt++)
#pragma unroll
        for (int nt = 0; nt < 4; nt++) {
            Bu[mt][nt][0] = movm(h2u(fmaxf(Cu[mt][nt][0], 0.f), fmaxf(Cu[mt][nt][1], 0.f)));
            Bu[mt][nt][1] = movm(h2u(fmaxf(Cu[mt][nt][2], 0.f), fmaxf(Cu[mt][nt][3], 0.f)));
        }

    // ---- GEMM1 (chained B) -> pe ----
    float C1[4][4][4];
#pragma unroll
    for (int mt = 0; mt < 4; mt++) {
        float b0 = s_b2pe[16 * mt + grp], b1 = s_b2pe[16 * mt + 8 + grp];
#pragma unroll
        for (int nt = 0; nt < 4; nt++) {
            C1[mt][nt][0] = b0; C1[mt][nt][1] = b0;
            C1[mt][nt][2] = b1; C1[mt][nt][3] = b1;
        }
    }
#pragma unroll
    for (int kt = 0; kt < 4; kt++) {
        unsigned Af[4][4];
#pragma unroll
        for (int mt = 0; mt < 4; mt++)
            ldsm4(Af[mt], ws1b + 2 * ((16 * mt + arow) * WSTR + 16 * kt + 8 * ahalf));
#pragma unroll
        for (int mt = 0; mt < 4; mt++)
#pragma unroll
            for (int nt = 0; nt < 4; nt++)
                mma16816(C1[mt][nt], Af[mt], Bu[kt][nt]);
    }

    // ---- pe -> Pe_s smem + movm chain ----
    unsigned Bc[4][4][2];
#pragma unroll
    for (int mt = 0; mt < 4; mt++) {
        int r0 = 16 * mt + grp, r1 = r0 + 8;
#pragma unroll
        for (int nt = 0; nt < 4; nt++) {
            int colL = n0 + 8 * nt + 2 * tig;
            unsigned p01 = h2u(C1[mt][nt][0], C1[mt][nt][1]);
            unsigned p23 = h2u(C1[mt][nt][2], C1[mt][nt][3]);
            *reinterpret_cast<unsigned*>(Pe_s + r0 * VSTR + colL) = p01;
            *reinterpret_cast<unsigned*>(Pe_s + r1 * VSTR + colL) = p23;
            Bc[mt][nt][0] = movm(p01);
            Bc[mt][nt][1] = movm(p23);
        }
    }
    __syncthreads();   // all Xlp/Wlp/Ws1 reads done before acth overlay writes

    // ---- GEMM2 (chained B) ----
    float C2[4][4][4];
#pragma unroll
    for (int mt = 0; mt < 4; mt++) {
        float b0 = s_b1at[16 * mt + grp], b1 = s_b1at[16 * mt + 8 + grp];
#pragma unroll
        for (int nt = 0; nt < 4; nt++) {
            C2[mt][nt][0] = b0; C2[mt][nt][1] = b0;
            C2[mt][nt][2] = b1; C2[mt][nt][3] = b1;
        }
    }
#pragma unroll
    for (int kt = 0; kt < 4; kt++) {
        unsigned Af[4][4];
#pragma unroll
        for (int mt = 0; mt < 4; mt++)
            ldsm4(Af[mt], ws2b + 2 * ((16 * mt + arow) * WSTR + 16 * kt + 8 * ahalf));
#pragma unroll
        for (int mt = 0; mt < 4; mt++)
#pragma unroll
            for (int nt = 0; nt < 4; nt++)
                mma16816(C2[mt][nt], Af[mt], Bc[kt][nt]);
    }

    // ---- GN2 fold + relu -> movm chain ----
    unsigned Bv[4][4][2];
#pragma unroll
    for (int mt = 0; mt < 4; mt++) {
        int r0 = 16 * mt + grp, r1 = r0 + 8;
        float a0 = s_gn[r0], c0 = s_gn[64 + r0];
        float a1 = s_gn[r1], c1 = s_gn[64 + r1];
#pragma unroll
        for (int nt = 0; nt < 4; nt++) {
            float v0 = fmaxf(fmaf(a0, C2[mt][nt][0], c0), 0.f);
            float v1 = fmaxf(fmaf(a0, C2[mt][nt][1], c0), 0.f);
            float v2 = fmaxf(fmaf(a1, C2[mt][nt][2], c1), 0.f);
            float v3 = fmaxf(fmaf(a1, C2[mt][nt][3], c1), 0.f);
            Bv[mt][nt][0] = movm(h2u(v0, v1));
            Bv[mt][nt][1] = movm(h2u(v2, v3));
        }
    }

    // ---- GEMM3 (chained B) ----
    float C3[4][4][4];
#pragma unroll
    for (int mt = 0; mt < 4; mt++) {
        float b0 = s_bat[16 * mt + grp], b1 = s_bat[16 * mt + 8 + grp];
#pragma unroll
        for (int nt = 0; nt < 4; nt++) {
            C3[mt][nt][0] = b0; C3[mt][nt][1] = b0;
            C3[mt][nt][2] = b1; C3[mt][nt][3] = b1;
        }
    }
#pragma unroll
    for (int kt = 0; kt < 4; kt++) {
        unsigned Af[4][4];
#pragma unroll
        for (int mt = 0; mt < 4; mt++)
            ldsm4(Af[mt], ws3b + 2 * ((16 * mt + arow) * WSTR + 16 * kt + 8 * ahalf));
#pragma unroll
        for (int mt = 0; mt < 4; mt++)
#pragma unroll
            for (int nt = 0; nt < 4; nt++)
                mma16816(C3[mt][nt], Af[mt], Bv[kt][nt]);
    }

    // ---- masked store -> acth fp16 [o][col] ----
    {
        const int* mrow = mask + (size_t)b * MKn + colbase;
        int2 mv[4];
#pragma unroll
        for (int nt = 0; nt < 4; nt++)
            mv[nt] = *reinterpret_cast<const int2*>(mrow + n0 + 8 * nt + 2 * tig);
#pragma unroll
        for (int mt = 0; mt < 4; mt++) {
            int r0 = 16 * mt + grp, r1 = r0 + 8;
#pragma unroll
            for (int nt = 0; nt < 4; nt++) {
                int colL = n0 + 8 * nt + 2 * tig;
                bool m0 = mv[nt].x != 0, m1 = mv[nt].y != 0;
                float f0 = m0 ? C3[mt][nt][0] : -65504.f;
                float f1 = m1 ? C3[mt][nt][1] : -65504.f;
                float f2 = m0 ? C3[mt][nt][2] : -65504.f;
                float f3 = m1 ? C3[mt][nt][3] : -65504.f;
                *reinterpret_cast<unsigned*>(acth + r0 * ASTRH + colL) = h2u(f0, f1);
                *reinterpret_cast<unsigned*>(acth + r1 * ASTRH + colL) = h2u(f2, f3);
            }
        }
    }
    __syncthreads();

    // ---- per-(m,o) softmax units; pe from Pe_s smem ----
    int mbase = colbase >> 4;      // 8 m per tile
#pragma unroll
    for (int r = 0; r < 4; r++) {
        int unit = r * 128 + t;    // 0..511
        int o = unit >> 3, ml = unit & 7;
        uint4 aw0 = *reinterpret_cast<const uint4*>(acth + o * ASTRH + 16 * ml);
        uint4 aw1 = *reinterpret_cast<const uint4*>(acth + o * ASTRH + 16 * ml + 8);
        float av[16];
        {
            float4 x;
            x = h4_to_f4(make_uint2(aw0.x, aw0.y));
            av[0] = x.x; av[1] = x.y; av[2] = x.z; av[3] = x.w;
            x = h4_to_f4(make_uint2(aw0.z, aw0.w));
            av[4] = x.x; av[5] = x.y; av[6] = x.z; av[7] = x.w;
            x = h4_to_f4(make_uint2(aw1.x, aw1.y));
            av[8] = x.x; av[9] = x.y; av[10] = x.z; av[11] = x.w;
            x = h4_to_f4(make_uint2(aw1.z, aw1.w));
            av[12] = x.x; av[13] = x.y; av[14] = x.z; av[15] = x.w;
        }
        float mx = av[0];
#pragma unroll
        for (int j = 1; j < 16; j++) mx = fmaxf(mx, av[j]);
        float s = 0.f;
#pragma unroll
        for (int j = 0; j < 16; j++) { av[j] = __expf(av[j] - mx); s += av[j]; }
        uint4 pw0 = *reinterpret_cast<const uint4*>(Pe_s + o * VSTR + 16 * ml);
        uint4 pw1 = *reinterpret_cast<const uint4*>(Pe_s + o * VSTR + 16 * ml + 8);
        float accum = 0.f;
        {
            float4 p;
            p = h4_to_f4(make_uint2(pw0.x, pw0.y));
            accum = fmaf(p.x, av[0], fmaf(p.y, av[1], fmaf(p.z, av[2], fmaf(p.w, av[3], accum))));
            p = h4_to_f4(make_uint2(pw0.z, pw0.w));
            accum = fmaf(p.x, av[4], fmaf(p.y, av[5], fmaf(p.z, av[6], fmaf(p.w, av[7], accum))));
            p = h4_to_f4(make_uint2(pw1.x, pw1.y));
            accum = fmaf(p.x, av[8], fmaf(p.y, av[9], fmaf(p.z, av[10], fmaf(p.w, av[11], accum))));
            p = h4_to_f4(make_uint2(pw1.z, pw1.w));
            accum = fmaf(p.x, av[12], fmaf(p.y, av[13], fmaf(p.z, av[14], fmaf(p.w, av[15], accum))));
        }
        out[((size_t)b * 64 + o) * Mn + mbase + ml] = accum * __fdividef(1.f, s);
    }
}

// ---------------- launch ----------------
extern "C" void kernel_launch(void* const* d_in, const int* in_sizes, int n_in,
                              void* d_out, int out_size) {
    const float* q_xyzs  = (const float*)d_in[0];
    const float* k_xyzs  = (const float*)d_in[1];
    const int*   knn_idx = (const int*)d_in[2];
    const int*   mask    = (const int*)d_in[3];
    const float* pe_w1   = (const float*)d_in[4];
    const float* pe_b1   = (const float*)d_in[5];
    const float* pe_g    = (const float*)d_in[6];
    const float* pe_be   = (const float*)d_in[7];
    const float* pe_w2   = (const float*)d_in[8];
    const float* pe_b2   = (const float*)d_in[9];
    const float* at_w1   = (const float*)d_in[10];
    const float* at_b1   = (const float*)d_in[11];
    const float* at_g    = (const float*)d_in[12];
    const float* at_be   = (const float*)d_in[13];
    const float* at_w2   = (const float*)d_in[14];
    const float* at_b2   = (const float*)d_in[15];
    float* out = (float*)d_out;

    static int smem_set = 0;
    if (!smem_set) {
        cudaFuncSetAttribute(k_pass2, cudaFuncAttributeMaxDynamicSharedMemorySize,
                             P2_TOTB);
        cudaFuncSetAttribute(k_pass3, cudaFuncAttributeMaxDynamicSharedMemorySize,
                             P3_TOTB);
        smem_set = 1;
    }

    k_prep<<<64, 64>>>(pe_w2, at_w1, at_w2);

    dim3 g1(MKn / 640, Bn);
    k_pass1<<<g1, 128>>>(q_xyzs, k_xyzs, knn_idx);
    k_fin1<<<1, 64>>>(pe_w1, pe_b1, pe_g, pe_be);

    dim3 gcol2((MKn + 255) / 256, Bn);
    k_pass2<<<gcol2, 128, P2_TOTB>>>(q_xyzs, k_xyzs, knn_idx, pe_b2, at_b1);
    k_fin2<<<1, 64>>>(at_g, at_be);

    dim3 gcol(MKn / 128, Bn);
    k_pass3<<<gcol, 128, P3_TOTB>>>(q_xyzs, k_xyzs, knn_idx, mask,
                                    pe_b2, at_b1, at_b2, out);
}